// round 10
// baseline (speedup 1.0000x reference)
#include <cuda_runtime.h>
#include <cuda_bf16.h>
#include <math.h>
#include <cstdint>

// Shapes (fixed)
#define BB 8
#define LL 1024
#define DD 256
#define HH 8
#define HD 32
#define MROWS (BB*LL)   // 8192

// ---------------- scratch (device globals) -----------------------------------
__device__ float g_obsp[MROWS * DD];
__device__ float g_obs2[MROWS * DD];
__device__ float g_y   [MROWS * DD];
__device__ float g_h   [MROWS * DD];
__device__ float2 g_stats[MROWS];
__device__ unsigned g_mbits[BB * LL * (LL/32)];

__device__ __nv_bfloat16 g_qh[MROWS * DD], g_ql[MROWS * DD];
__device__ __nv_bfloat16 g_kh[MROWS * DD], g_kl[MROWS * DD];
__device__ __nv_bfloat16 g_vh[MROWS * DD], g_vl[MROWS * DD];

// ---------------- helpers -----------------------------------------------------
__device__ __forceinline__ void split1(float x, __nv_bfloat16& h, __nv_bfloat16& l) {
    h = __float2bfloat16(x);
    l = __float2bfloat16(x - __bfloat162float(h));
}
__device__ __forceinline__ uint32_t pack_bf2(float a, float b) {
    __nv_bfloat162 p = __halves2bfloat162(__float2bfloat16(a), __float2bfloat16(b));
    return *reinterpret_cast<uint32_t*>(&p);
}
// truncation split: hi = top16 bits (exact), lo = rn_bf16(x - hi)
__device__ __forceinline__ uint32_t hi_pack(float a, float b) {
    uint32_t r;
    asm("prmt.b32 %0, %1, %2, 0x7632;" : "=r"(r)
        : "r"(__float_as_int(a)), "r"(__float_as_int(b)));
    return r;
}
__device__ __forceinline__ uint32_t lo_pack(float a, float b) {
    float la = a - __int_as_float(__float_as_int(a) & 0xFFFF0000u);
    float lb = b - __int_as_float(__float_as_int(b) & 0xFFFF0000u);
    uint32_t r;
    asm("cvt.rn.bf16x2.f32 %0, %1, %2;" : "=r"(r) : "f"(lb), "f"(la));
    return r;
}
// fast exp on FMA pipe, degree-4 (rel err ~4e-5, plenty under 1e-3 gate)
__device__ __forceinline__ float fexp(float s) {
    const float L2E = 1.4426950408889634f;
    float t  = fmaf(s, L2E, 12582912.0f);
    int   ei = __float_as_int(t) << 23;
    float n  = t - 12582912.0f;
    float f  = fmaf(s, L2E, -n);
    float r  = 9.6181291e-3f;
    r = fmaf(r, f, 5.5504109e-2f);
    r = fmaf(r, f, 2.4022651e-1f);
    r = fmaf(r, f, 6.9314718e-1f);
    r = fmaf(r, f, 1.0f);
    return __int_as_float(__float_as_int(r) + ei);
}

// pack mask (diagonal cleared) into bitwords
__global__ __launch_bounds__(128)
void pack_mask_kernel(const int* __restrict__ mask, unsigned* __restrict__ bits) {
    int b = blockIdx.y, row = blockIdx.x;
    int lane = threadIdx.x & 31, warp = threadIdx.x >> 5;
    const int* mrow = mask + ((size_t)b * LL + row) * LL;
    for (int w = warp; w < 32; w += 4) {
        int col = w * 32 + lane;
        unsigned bit = (unsigned)((mrow[col] != 0) && (col != row));
        unsigned word = __ballot_sync(0xFFFFFFFFu, bit);
        if (lane == 0) bits[((size_t)b * LL + row) * 32 + w] = word;
    }
}

// ---------------- block reduction (parallel final stage) -----------------------
__device__ __forceinline__ void blockReduce2(float& a, float& b, float* sh) {
    int lane = threadIdx.x & 31, warp = threadIdx.x >> 5;
#pragma unroll
    for (int o = 16; o > 0; o >>= 1) {
        a += __shfl_xor_sync(0xFFFFFFFFu, a, o);
        b += __shfl_xor_sync(0xFFFFFFFFu, b, o);
    }
    if (lane == 0) { sh[warp * 2] = a; sh[warp * 2 + 1] = b; }
    __syncthreads();
    int nw = blockDim.x >> 5;
    if (warp == 0) {
        float sa = (lane < nw) ? sh[lane * 2]     : 0.f;
        float sb = (lane < nw) ? sh[lane * 2 + 1] : 0.f;
#pragma unroll
        for (int o = 8; o > 0; o >>= 1) {
            sa += __shfl_xor_sync(0xFFFFFFFFu, sa, o);
            sb += __shfl_xor_sync(0xFFFFFFFFu, sb, o);
        }
        if (lane == 0) { sh[0] = sa; sh[1] = sb; }
    }
    __syncthreads();
    a = sh[0]; b = sh[1];
}

// ---------------- dual-output fused-split GEMM via mma.sync --------------------
// Optional fused LayerNorm on A: x -> (x - mean)*rstd*g + b (per-row stats).
#define APAD 8

__device__ __forceinline__ void mma_bf16(float* c, const uint32_t* a, const uint32_t* b) {
    asm volatile(
        "mma.sync.aligned.m16n8k16.row.col.f32.bf16.bf16.f32 "
        "{%0,%1,%2,%3},{%4,%5,%6,%7},{%8,%9},{%0,%1,%2,%3};"
        : "+f"(c[0]), "+f"(c[1]), "+f"(c[2]), "+f"(c[3])
        : "r"(a[0]), "r"(a[1]), "r"(a[2]), "r"(a[3]), "r"(b[0]), "r"(b[1]));
}

__device__ __forceinline__ void split8s(float4 f0, float4 f1,
                                        __nv_bfloat16* hiDst, __nv_bfloat16* loDst) {
    uint4 hi, lo;
    hi.x = hi_pack(f0.x, f0.y); lo.x = lo_pack(f0.x, f0.y);
    hi.y = hi_pack(f0.z, f0.w); lo.y = lo_pack(f0.z, f0.w);
    hi.z = hi_pack(f1.x, f1.y); lo.z = lo_pack(f1.x, f1.y);
    hi.w = hi_pack(f1.z, f1.w); lo.w = lo_pack(f1.z, f1.w);
    *(uint4*)hiDst = hi;
    *(uint4*)loDst = lo;
}

__global__ __launch_bounds__(256)
void gemm2_kernel(const float* __restrict__ A0, const float* __restrict__ A1, int K0,
                  const float* __restrict__ W0, const float* __restrict__ W1,
                  const float* __restrict__ bias0, const float* __restrict__ bias1,
                  float* __restrict__ C0, __nv_bfloat16* __restrict__ C0h,
                  __nv_bfloat16* __restrict__ C0l,
                  float* __restrict__ C1, __nv_bfloat16* __restrict__ C1h,
                  __nv_bfloat16* __restrict__ C1l,
                  const float2* __restrict__ lnStats,
                  const float* __restrict__ lnG, const float* __restrict__ lnB, int K) {
    __shared__ __nv_bfloat16 Ash[64][32 + APAD];
    __shared__ __nv_bfloat16 Asl[64][32 + APAD];
    __shared__ __nv_bfloat16 Wsh[64][32 + APAD];
    __shared__ __nv_bfloat16 Wsl[64][32 + APAD];

    const int tid = threadIdx.x;
    const int bn = blockIdx.x * 64;
    const int bm = blockIdx.y * 64;
    const int wid = tid >> 5, lane = tid & 31;
    const int wm = (wid >> 2) * 32;
    const int wn = (wid & 3) * 16;
    const int g  = lane >> 2;
    const int tg = lane & 3;

    const bool half0 = (bn < 256);
    const float* W    = half0 ? W0 : W1;
    const float* bias = half0 ? bias0 : bias1;
    float* C          = half0 ? C0 : C1;
    __nv_bfloat16* Ch = half0 ? C0h : C1h;
    __nv_bfloat16* Cl = half0 ? C0l : C1l;
    const int cb = bn & 255;

    const int ar = tid >> 2;
    const int ac = tid & 3;

    float2 st = make_float2(0.f, 1.f);
    if (lnStats) st = lnStats[bm + ar];

    float acc[2][2][4];
#pragma unroll
    for (int mt = 0; mt < 2; mt++)
#pragma unroll
        for (int nt = 0; nt < 2; nt++)
#pragma unroll
            for (int j = 0; j < 4; j++) acc[mt][nt][j] = 0.f;

    float4 fa0, fa1, fw0, fw1;
    {
        const float* Ab; int As;
        if (0 < K0) { Ab = A0; As = K0; } else { Ab = A1; As = K - K0; }
        const float* pa = Ab + (size_t)(bm + ar) * As + ac * 8;
        fa0 = ((const float4*)pa)[0]; fa1 = ((const float4*)pa)[1];
        const float* pw = W + (size_t)(cb + ar) * K + ac * 8;
        fw0 = ((const float4*)pw)[0]; fw1 = ((const float4*)pw)[1];
    }

    const int nkb = K / 32;
    for (int kb = 0; kb < nkb; kb++) {
        if (lnStats) {
            const int kcur = kb * 32 + ac * 8;
            float4 gg0 = *(const float4*)&lnG[kcur];
            float4 gg1 = *(const float4*)&lnG[kcur + 4];
            float4 bb0 = *(const float4*)&lnB[kcur];
            float4 bb1 = *(const float4*)&lnB[kcur + 4];
            fa0.x = fmaf((fa0.x - st.x) * st.y, gg0.x, bb0.x);
            fa0.y = fmaf((fa0.y - st.x) * st.y, gg0.y, bb0.y);
            fa0.z = fmaf((fa0.z - st.x) * st.y, gg0.z, bb0.z);
            fa0.w = fmaf((fa0.w - st.x) * st.y, gg0.w, bb0.w);
            fa1.x = fmaf((fa1.x - st.x) * st.y, gg1.x, bb1.x);
            fa1.y = fmaf((fa1.y - st.x) * st.y, gg1.y, bb1.y);
            fa1.z = fmaf((fa1.z - st.x) * st.y, gg1.z, bb1.z);
            fa1.w = fmaf((fa1.w - st.x) * st.y, gg1.w, bb1.w);
        }
        split8s(fa0, fa1, &Ash[ar][ac * 8], &Asl[ar][ac * 8]);
        split8s(fw0, fw1, &Wsh[ar][ac * 8], &Wsl[ar][ac * 8]);
        __syncthreads();

        if (kb + 1 < nkb) {
            const int k0 = (kb + 1) * 32;
            const float* Ab; int As;
            if (k0 < K0) { Ab = A0 + k0; As = K0; } else { Ab = A1 + (k0 - K0); As = K - K0; }
            const float* pa = Ab + (size_t)(bm + ar) * As + ac * 8;
            fa0 = ((const float4*)pa)[0]; fa1 = ((const float4*)pa)[1];
            const float* pw = W + (size_t)(cb + ar) * K + k0 + ac * 8;
            fw0 = ((const float4*)pw)[0]; fw1 = ((const float4*)pw)[1];
        }

#pragma unroll
        for (int ks = 0; ks < 2; ks++) {
            const int kk = ks * 16;
            uint32_t ah[2][4], al[2][4], bh[2][2], bl[2][2];
#pragma unroll
            for (int mt = 0; mt < 2; mt++) {
                const int rb = wm + mt * 16;
                ah[mt][0] = *(const uint32_t*)&Ash[rb + g    ][kk + 2*tg];
                ah[mt][1] = *(const uint32_t*)&Ash[rb + g + 8][kk + 2*tg];
                ah[mt][2] = *(const uint32_t*)&Ash[rb + g    ][kk + 2*tg + 8];
                ah[mt][3] = *(const uint32_t*)&Ash[rb + g + 8][kk + 2*tg + 8];
                al[mt][0] = *(const uint32_t*)&Asl[rb + g    ][kk + 2*tg];
                al[mt][1] = *(const uint32_t*)&Asl[rb + g + 8][kk + 2*tg];
                al[mt][2] = *(const uint32_t*)&Asl[rb + g    ][kk + 2*tg + 8];
                al[mt][3] = *(const uint32_t*)&Asl[rb + g + 8][kk + 2*tg + 8];
            }
#pragma unroll
            for (int nt = 0; nt < 2; nt++) {
                const int nb = wn + nt * 8;
                bh[nt][0] = *(const uint32_t*)&Wsh[nb + g][kk + 2*tg];
                bh[nt][1] = *(const uint32_t*)&Wsh[nb + g][kk + 2*tg + 8];
                bl[nt][0] = *(const uint32_t*)&Wsl[nb + g][kk + 2*tg];
                bl[nt][1] = *(const uint32_t*)&Wsl[nb + g][kk + 2*tg + 8];
            }
#pragma unroll
            for (int mt = 0; mt < 2; mt++)
#pragma unroll
                for (int nt = 0; nt < 2; nt++) {
                    mma_bf16(acc[mt][nt], ah[mt], bh[nt]);
                    mma_bf16(acc[mt][nt], al[mt], bh[nt]);
                    mma_bf16(acc[mt][nt], ah[mt], bl[nt]);
                }
        }
        __syncthreads();
    }

#pragma unroll
    for (int mt = 0; mt < 2; mt++) {
#pragma unroll
        for (int nt = 0; nt < 2; nt++) {
            const int col = cb + wn + nt * 8 + 2 * tg;
            const float bx = bias[col], by = bias[col + 1];
            const int r0 = bm + wm + mt * 16 + g;
            float v0 = acc[mt][nt][0] + bx, v1 = acc[mt][nt][1] + by;
            float v2 = acc[mt][nt][2] + bx, v3 = acc[mt][nt][3] + by;
            if (C) {
                *(float2*)&C[(size_t)r0 * DD + col]       = make_float2(v0, v1);
                *(float2*)&C[(size_t)(r0 + 8) * DD + col] = make_float2(v2, v3);
            } else {
                __nv_bfloat16 h0,l0,h1,l1,h2,l2,h3,l3;
                split1(v0,h0,l0); split1(v1,h1,l1); split1(v2,h2,l2); split1(v3,h3,l3);
                *(__nv_bfloat162*)&Ch[(size_t)r0 * DD + col]       = __halves2bfloat162(h0,h1);
                *(__nv_bfloat162*)&Cl[(size_t)r0 * DD + col]       = __halves2bfloat162(l0,l1);
                *(__nv_bfloat162*)&Ch[(size_t)(r0 + 8) * DD + col] = __halves2bfloat162(h2,h3);
                *(__nv_bfloat162*)&Cl[(size_t)(r0 + 8) * DD + col] = __halves2bfloat162(l2,l3);
            }
        }
    }
}

// ---------------- gelu (exact) + LayerNorm (D=256) ----------------------------
__global__ __launch_bounds__(256)
void gelu_ln_kernel(const float* __restrict__ in, const float* __restrict__ g,
                    const float* __restrict__ b, float* __restrict__ out) {
    __shared__ float sh[64];
    int row = blockIdx.x, tid = threadIdx.x;
    float x  = in[(size_t)row * 256 + tid];
    float ge = 0.5f * x * (1.f + erff(x * 0.70710678118654752f));
    float s = ge, s2 = ge * ge;
    blockReduce2(s, s2, sh);
    float mean = s * (1.f / 256.f);
    float var  = s2 * (1.f / 256.f) - mean * mean;
    out[(size_t)row * 256 + tid] = (ge - mean) * rsqrtf(var + 1e-5f) * g[tid] + b[tid];
}

// row stats of virtual z=[y|obs2] (D=512): mean + rstd
__global__ __launch_bounds__(512)
void ln_stats_kernel(const float* __restrict__ y, const float* __restrict__ o2,
                     float2* __restrict__ stats) {
    __shared__ float sh[64];
    int row = blockIdx.x, tid = threadIdx.x;
    float x = (tid < 256) ? y[(size_t)row * 256 + tid]
                          : o2[(size_t)row * 256 + tid - 256];
    float s = x, s2 = x * x;
    blockReduce2(s, s2, sh);
    if (tid == 0) {
        float mean = s * (1.f / 512.f);
        float var  = s2 * (1.f / 512.f) - mean * mean;
        stats[row] = make_float2(mean, rsqrtf(var + 1e-5f));
    }
}

// ---------------- tensor-core attention (64-key tiles) -------------------------
#define AT_PAD 8
__global__ __launch_bounds__(128)
void attn_tc_kernel(const __nv_bfloat16* __restrict__ qh, const __nv_bfloat16* __restrict__ ql,
                    const __nv_bfloat16* __restrict__ kh, const __nv_bfloat16* __restrict__ kl,
                    const __nv_bfloat16* __restrict__ vh, const __nv_bfloat16* __restrict__ vl,
                    const unsigned* __restrict__ mbits, float* __restrict__ y) {
    __shared__ __nv_bfloat16 Ksh[64][32 + AT_PAD];
    __shared__ __nv_bfloat16 Ksl[64][32 + AT_PAD];
    __shared__ __nv_bfloat16 Vth[32][64 + AT_PAD];
    __shared__ __nv_bfloat16 Vtl[32][64 + AT_PAD];
    __shared__ unsigned Msk[128][2];

    const int b = blockIdx.z, h = blockIdx.y;
    const int qb = blockIdx.x * 128;
    const int tid = threadIdx.x;
    const int warp = tid >> 5, lane = tid & 31;
    const int g = lane >> 2, tg = lane & 3;

    uint32_t aqh[2][2][4], aql[2][2][4];
#pragma unroll
    for (int mt = 0; mt < 2; mt++) {
        const int r0 = qb + warp * 32 + mt * 16 + g;
#pragma unroll
        for (int ks = 0; ks < 2; ks++) {
            const size_t base0 = ((size_t)(b * LL + r0)) * DD + h * HD + ks * 16 + 2 * tg;
            const size_t base8 = base0 + 8ull * DD;
            aqh[mt][ks][0] = *(const uint32_t*)&qh[base0];
            aqh[mt][ks][1] = *(const uint32_t*)&qh[base8];
            aqh[mt][ks][2] = *(const uint32_t*)&qh[base0 + 8];
            aqh[mt][ks][3] = *(const uint32_t*)&qh[base8 + 8];
            aql[mt][ks][0] = *(const uint32_t*)&ql[base0];
            aql[mt][ks][1] = *(const uint32_t*)&ql[base8];
            aql[mt][ks][2] = *(const uint32_t*)&ql[base0 + 8];
            aql[mt][ks][3] = *(const uint32_t*)&ql[base8 + 8];
        }
    }

    float co[2][4][4];
#pragma unroll
    for (int mt = 0; mt < 2; mt++)
#pragma unroll
        for (int n = 0; n < 4; n++)
#pragma unroll
            for (int j = 0; j < 4; j++) co[mt][n][j] = 0.f;
    float dn[2][2] = {{0.f,0.f},{0.f,0.f}};

    for (int t = 0; t < LL / 64; t++) {
        const int kb = t * 64;
        {
            const int j  = tid & 63;            // key within tile
            const int d0 = (tid >> 6) * 16;     // dim half
            const size_t src = ((size_t)(b * LL + kb + j)) * DD + h * HD + d0;
            uint4 a0 = *(const uint4*)&kh[src];
            uint4 a1 = *(const uint4*)&kh[src + 8];
            *(uint4*)&Ksh[j][d0]     = a0;
            *(uint4*)&Ksh[j][d0 + 8] = a1;
            uint4 b0 = *(const uint4*)&kl[src];
            uint4 b1 = *(const uint4*)&kl[src + 8];
            *(uint4*)&Ksl[j][d0]     = b0;
            *(uint4*)&Ksl[j][d0 + 8] = b1;
            uint4 v0 = *(const uint4*)&vh[src];
            uint4 v1 = *(const uint4*)&vh[src + 8];
            uint4 w0 = *(const uint4*)&vl[src];
            uint4 w1 = *(const uint4*)&vl[src + 8];
            const __nv_bfloat16* p0 = (const __nv_bfloat16*)&v0;
            const __nv_bfloat16* p1 = (const __nv_bfloat16*)&v1;
            const __nv_bfloat16* q0 = (const __nv_bfloat16*)&w0;
            const __nv_bfloat16* q1 = (const __nv_bfloat16*)&w1;
#pragma unroll
            for (int i = 0; i < 8; i++) {
                Vth[d0 + i][j]     = p0[i];
                Vth[d0 + 8 + i][j] = p1[i];
                Vtl[d0 + i][j]     = q0[i];
                Vtl[d0 + 8 + i][j] = q1[i];
            }
            uint2 mw = *(const uint2*)&mbits[((size_t)(b * LL + qb + tid)) * 32 + 2 * t];
            Msk[tid][0] = mw.x;
            Msk[tid][1] = mw.y;
        }
        __syncthreads();

#pragma unroll
        for (int s = 0; s < 2; s++) {
            const int so = s * 32;
            uint32_t bKh[2][4][2], bKl[2][4][2];
#pragma unroll
            for (int ks = 0; ks < 2; ks++)
#pragma unroll
                for (int n = 0; n < 4; n++) {
                    bKh[ks][n][0] = *(const uint32_t*)&Ksh[so + n * 8 + g][ks * 16 + 2 * tg];
                    bKh[ks][n][1] = *(const uint32_t*)&Ksh[so + n * 8 + g][ks * 16 + 2 * tg + 8];
                    bKl[ks][n][0] = *(const uint32_t*)&Ksl[so + n * 8 + g][ks * 16 + 2 * tg];
                    bKl[ks][n][1] = *(const uint32_t*)&Ksl[so + n * 8 + g][ks * 16 + 2 * tg + 8];
                }
            float cs[2][4][4];
#pragma unroll
            for (int mt = 0; mt < 2; mt++)
#pragma unroll
                for (int n = 0; n < 4; n++)
#pragma unroll
                    for (int j = 0; j < 4; j++) cs[mt][n][j] = 0.f;
#pragma unroll
            for (int ks = 0; ks < 2; ks++)
#pragma unroll
                for (int mt = 0; mt < 2; mt++)
#pragma unroll
                    for (int n = 0; n < 4; n++) {
                        mma_bf16(cs[mt][n], aqh[mt][ks], bKh[ks][n]);
                        mma_bf16(cs[mt][n], aql[mt][ks], bKh[ks][n]);
                        mma_bf16(cs[mt][n], aqh[mt][ks], bKl[ks][n]);
                    }

            uint32_t bVh[2][4][2], bVl[2][4][2];
#pragma unroll
            for (int kp = 0; kp < 2; kp++)
#pragma unroll
                for (int n = 0; n < 4; n++) {
                    bVh[kp][n][0] = *(const uint32_t*)&Vth[n * 8 + g][so + kp * 16 + 2 * tg];
                    bVh[kp][n][1] = *(const uint32_t*)&Vth[n * 8 + g][so + kp * 16 + 2 * tg + 8];
                    bVl[kp][n][0] = *(const uint32_t*)&Vtl[n * 8 + g][so + kp * 16 + 2 * tg];
                    bVl[kp][n][1] = *(const uint32_t*)&Vtl[n * 8 + g][so + kp * 16 + 2 * tg + 8];
                }

#pragma unroll
            for (int mt = 0; mt < 2; mt++) {
                const int rbase = warp * 32 + mt * 16;
                const unsigned w0 = Msk[rbase + g][s];
                const unsigned w8 = Msk[rbase + g + 8][s];
                float pr[4][4];
#pragma unroll
                for (int n = 0; n < 4; n++) {
                    const int c0 = n * 8 + 2 * tg;
                    const float m00 = (float)((w0 >> c0) & 1u);
                    const float m01 = (float)((w0 >> (c0 + 1)) & 1u);
                    const float m10 = (float)((w8 >> c0) & 1u);
                    const float m11 = (float)((w8 >> (c0 + 1)) & 1u);
                    pr[n][0] = fexp(cs[mt][n][0]) * m00;
                    pr[n][1] = fexp(cs[mt][n][1]) * m01;
                    pr[n][2] = fexp(cs[mt][n][2]) * m10;
                    pr[n][3] = fexp(cs[mt][n][3]) * m11;
                    dn[mt][0] += pr[n][0] + pr[n][1];
                    dn[mt][1] += pr[n][2] + pr[n][3];
                }
#pragma unroll
                for (int kp = 0; kp < 2; kp++) {
                    float e00 = pr[kp*2][0], e01 = pr[kp*2][1], e02 = pr[kp*2][2], e03 = pr[kp*2][3];
                    float e10 = pr[kp*2+1][0], e11 = pr[kp*2+1][1], e12 = pr[kp*2+1][2], e13 = pr[kp*2+1][3];
                    uint32_t pah[4], pal[4];
                    pah[0] = pack_bf2(e00, e01);
                    pah[1] = pack_bf2(e02, e03);
                    pah[2] = pack_bf2(e10, e11);
                    pah[3] = pack_bf2(e12, e13);
                    __nv_bfloat162 t0 = *(__nv_bfloat162*)&pah[0];
                    __nv_bfloat162 t1 = *(__nv_bfloat162*)&pah[1];
                    __nv_bfloat162 t2 = *(__nv_bfloat162*)&pah[2];
                    __nv_bfloat162 t3 = *(__nv_bfloat162*)&pah[3];
                    pal[0] = pack_bf2(e00 - __bfloat162float(t0.x), e01 - __bfloat162float(t0.y));
                    pal[1] = pack_bf2(e02 - __bfloat162float(t1.x), e03 - __bfloat162float(t1.y));
                    pal[2] = pack_bf2(e10 - __bfloat162float(t2.x), e11 - __bfloat162float(t2.y));
                    pal[3] = pack_bf2(e12 - __bfloat162float(t3.x), e13 - __bfloat162float(t3.y));
#pragma unroll
                    for (int n = 0; n < 4; n++) {
                        mma_bf16(co[mt][n], pah, bVh[kp][n]);
                        mma_bf16(co[mt][n], pal, bVh[kp][n]);
                        mma_bf16(co[mt][n], pah, bVl[kp][n]);
                    }
                }
            }
        }
        __syncthreads();
    }

#pragma unroll
    for (int mt = 0; mt < 2; mt++)
#pragma unroll
        for (int rh = 0; rh < 2; rh++) {
            float d = dn[mt][rh];
            d += __shfl_xor_sync(0xFFFFFFFFu, d, 1);
            d += __shfl_xor_sync(0xFFFFFFFFu, d, 2);
            dn[mt][rh] = (d > 0.f) ? 1.0f / d : 0.f;
        }

#pragma unroll
    for (int mt = 0; mt < 2; mt++) {
        const int r0 = qb + warp * 32 + mt * 16 + g;
#pragma unroll
        for (int n = 0; n < 4; n++) {
            const int col = h * HD + n * 8 + 2 * tg;
            *(float2*)&y[((size_t)(b * LL + r0)) * DD + col] =
                make_float2(co[mt][n][0] * dn[mt][0], co[mt][n][1] * dn[mt][0]);
            *(float2*)&y[((size_t)(b * LL + r0 + 8)) * DD + col] =
                make_float2(co[mt][n][2] * dn[mt][1], co[mt][n][3] * dn[mt][1]);
        }
    }
}

// ---------------- launch ------------------------------------------------------
extern "C" void kernel_launch(void* const* d_in, const int* in_sizes, int n_in,
                              void* d_out, int out_size) {
    const float* obs  = (const float*)d_in[0];
    const float* act  = (const float*)d_in[1];
    const int*   msk  = (const int*)  d_in[2];
    const float* Wq   = (const float*)d_in[3];
    const float* bq   = (const float*)d_in[4];
    const float* Wk   = (const float*)d_in[5];
    const float* bk   = (const float*)d_in[6];
    const float* Wv   = (const float*)d_in[7];
    const float* bv   = (const float*)d_in[8];
    const float* Wobs = (const float*)d_in[9];
    const float* bobs = (const float*)d_in[10];
    const float* gob  = (const float*)d_in[11];
    const float* bob  = (const float*)d_in[12];
    const float* g1   = (const float*)d_in[13];
    const float* b1   = (const float*)d_in[14];
    const float* Wp   = (const float*)d_in[15];
    const float* bp   = (const float*)d_in[16];
    const float* g2   = (const float*)d_in[17];
    const float* b2   = (const float*)d_in[18];

    float *obsp, *obs2, *yb, *hb;
    float2* stats;
    unsigned* mb;
    cudaGetSymbolAddress((void**)&obsp,  g_obsp);
    cudaGetSymbolAddress((void**)&obs2,  g_obs2);
    cudaGetSymbolAddress((void**)&yb,    g_y);
    cudaGetSymbolAddress((void**)&hb,    g_h);
    cudaGetSymbolAddress((void**)&stats, g_stats);
    cudaGetSymbolAddress((void**)&mb,    g_mbits);

    __nv_bfloat16 *qh,*ql,*kh,*kl,*vh,*vl;
    cudaGetSymbolAddress((void**)&qh, g_qh); cudaGetSymbolAddress((void**)&ql, g_ql);
    cudaGetSymbolAddress((void**)&kh, g_kh); cudaGetSymbolAddress((void**)&kl, g_kl);
    cudaGetSymbolAddress((void**)&vh, g_vh); cudaGetSymbolAddress((void**)&vl, g_vl);

    pack_mask_kernel<<<dim3(LL, BB), 128>>>(msk, mb);

    // q + obsp merged (A=obs, K=256)
    gemm2_kernel<<<dim3(8, 128), 256>>>(obs, obs, 256, Wq, Wobs, bq, bobs,
                                        nullptr, qh, ql, obsp, nullptr, nullptr,
                                        nullptr, nullptr, nullptr, 256);
    // k + v merged (A=[obs|act], K=512)
    gemm2_kernel<<<dim3(8, 128), 256>>>(obs, act, 256, Wk, Wv, bk, bv,
                                        nullptr, kh, kl, nullptr, vh, vl,
                                        nullptr, nullptr, nullptr, 512);

    gelu_ln_kernel<<<MROWS, 256>>>(obsp, gob, bob, obs2);

    attn_tc_kernel<<<dim3(LL / 128, HH, BB), 128>>>(qh, ql, kh, kl, vh, vl, mb, yb);

    // row stats of z=[y|obs2], then Wp GEMM with fused LayerNorm on A
    ln_stats_kernel<<<MROWS, 512>>>(yb, obs2, stats);
    gemm2_kernel<<<dim3(4, 128), 256>>>(yb, obs2, 256, Wp, Wp, bp, bp,
                                        hb, nullptr, nullptr, hb, nullptr, nullptr,
                                        stats, g1, b1, 512);

    gelu_ln_kernel<<<MROWS, 256>>>(hb, g2, b2, (float*)d_out);
}

// round 11
// speedup vs baseline: 1.0346x; 1.0346x over previous
#include <cuda_runtime.h>
#include <cuda_bf16.h>
#include <math.h>
#include <cstdint>

// Shapes (fixed)
#define BB 8
#define LL 1024
#define DD 256
#define HH 8
#define HD 32
#define MROWS (BB*LL)   // 8192

// ---------------- scratch (device globals) -----------------------------------
__device__ float g_obsp[MROWS * DD];
__device__ float g_obs2[MROWS * DD];
__device__ float g_y   [MROWS * DD];
__device__ float g_h   [MROWS * DD];
__device__ float2 g_stats[MROWS];
__device__ unsigned g_mbits[BB * LL * (LL/32)];

__device__ __nv_bfloat16 g_qh[MROWS * DD], g_ql[MROWS * DD];
__device__ __nv_bfloat16 g_kh[MROWS * DD], g_kl[MROWS * DD];
__device__ __nv_bfloat16 g_vh[MROWS * DD], g_vl[MROWS * DD];

// ---------------- helpers -----------------------------------------------------
__device__ __forceinline__ void split1(float x, __nv_bfloat16& h, __nv_bfloat16& l) {
    h = __float2bfloat16(x);
    l = __float2bfloat16(x - __bfloat162float(h));
}
__device__ __forceinline__ uint32_t pack_bf2(float a, float b) {
    __nv_bfloat162 p = __halves2bfloat162(__float2bfloat16(a), __float2bfloat16(b));
    return *reinterpret_cast<uint32_t*>(&p);
}
// truncation split: hi = top16 bits (exact), lo = rn_bf16(x - hi)
__device__ __forceinline__ uint32_t hi_pack(float a, float b) {
    uint32_t r;
    asm("prmt.b32 %0, %1, %2, 0x7632;" : "=r"(r)
        : "r"(__float_as_int(a)), "r"(__float_as_int(b)));
    return r;
}
__device__ __forceinline__ uint32_t lo_pack(float a, float b) {
    float la = a - __int_as_float(__float_as_int(a) & 0xFFFF0000u);
    float lb = b - __int_as_float(__float_as_int(b) & 0xFFFF0000u);
    uint32_t r;
    asm("cvt.rn.bf16x2.f32 %0, %1, %2;" : "=r"(r) : "f"(lb), "f"(la));
    return r;
}
// fast exp on FMA pipe, degree-4 (rel err ~4e-5, plenty under 1e-3 gate)
__device__ __forceinline__ float fexp(float s) {
    const float L2E = 1.4426950408889634f;
    float t  = fmaf(s, L2E, 12582912.0f);
    int   ei = __float_as_int(t) << 23;
    float n  = t - 12582912.0f;
    float f  = fmaf(s, L2E, -n);
    float r  = 9.6181291e-3f;
    r = fmaf(r, f, 5.5504109e-2f);
    r = fmaf(r, f, 2.4022651e-1f);
    r = fmaf(r, f, 6.9314718e-1f);
    r = fmaf(r, f, 1.0f);
    return __int_as_float(__float_as_int(r) + ei);
}

// pack mask (diagonal cleared) into bitwords
__global__ __launch_bounds__(128)
void pack_mask_kernel(const int* __restrict__ mask, unsigned* __restrict__ bits) {
    int b = blockIdx.y, row = blockIdx.x;
    int lane = threadIdx.x & 31, warp = threadIdx.x >> 5;
    const int* mrow = mask + ((size_t)b * LL + row) * LL;
    for (int w = warp; w < 32; w += 4) {
        int col = w * 32 + lane;
        unsigned bit = (unsigned)((mrow[col] != 0) && (col != row));
        unsigned word = __ballot_sync(0xFFFFFFFFu, bit);
        if (lane == 0) bits[((size_t)b * LL + row) * 32 + w] = word;
    }
}

// ---------------- block reduction (parallel final stage) -----------------------
__device__ __forceinline__ void blockReduce2(float& a, float& b, float* sh) {
    int lane = threadIdx.x & 31, warp = threadIdx.x >> 5;
#pragma unroll
    for (int o = 16; o > 0; o >>= 1) {
        a += __shfl_xor_sync(0xFFFFFFFFu, a, o);
        b += __shfl_xor_sync(0xFFFFFFFFu, b, o);
    }
    if (lane == 0) { sh[warp * 2] = a; sh[warp * 2 + 1] = b; }
    __syncthreads();
    int nw = blockDim.x >> 5;
    if (warp == 0) {
        float sa = (lane < nw) ? sh[lane * 2]     : 0.f;
        float sb = (lane < nw) ? sh[lane * 2 + 1] : 0.f;
#pragma unroll
        for (int o = 8; o > 0; o >>= 1) {
            sa += __shfl_xor_sync(0xFFFFFFFFu, sa, o);
            sb += __shfl_xor_sync(0xFFFFFFFFu, sb, o);
        }
        if (lane == 0) { sh[0] = sa; sh[1] = sb; }
    }
    __syncthreads();
    a = sh[0]; b = sh[1];
}

// ---------------- dual-output fused-split GEMM via mma.sync --------------------
// Optional fused LayerNorm on A: x -> (x - mean)*rstd*g + b (per-row stats).
#define APAD 8

__device__ __forceinline__ void mma_bf16(float* c, const uint32_t* a, const uint32_t* b) {
    asm volatile(
        "mma.sync.aligned.m16n8k16.row.col.f32.bf16.bf16.f32 "
        "{%0,%1,%2,%3},{%4,%5,%6,%7},{%8,%9},{%0,%1,%2,%3};"
        : "+f"(c[0]), "+f"(c[1]), "+f"(c[2]), "+f"(c[3])
        : "r"(a[0]), "r"(a[1]), "r"(a[2]), "r"(a[3]), "r"(b[0]), "r"(b[1]));
}

__device__ __forceinline__ void split8s(float4 f0, float4 f1,
                                        __nv_bfloat16* hiDst, __nv_bfloat16* loDst) {
    uint4 hi, lo;
    hi.x = hi_pack(f0.x, f0.y); lo.x = lo_pack(f0.x, f0.y);
    hi.y = hi_pack(f0.z, f0.w); lo.y = lo_pack(f0.z, f0.w);
    hi.z = hi_pack(f1.x, f1.y); lo.z = lo_pack(f1.x, f1.y);
    hi.w = hi_pack(f1.z, f1.w); lo.w = lo_pack(f1.z, f1.w);
    *(uint4*)hiDst = hi;
    *(uint4*)loDst = lo;
}

__global__ __launch_bounds__(256)
void gemm2_kernel(const float* __restrict__ A0, const float* __restrict__ A1, int K0,
                  const float* __restrict__ W0, const float* __restrict__ W1,
                  const float* __restrict__ bias0, const float* __restrict__ bias1,
                  float* __restrict__ C0, __nv_bfloat16* __restrict__ C0h,
                  __nv_bfloat16* __restrict__ C0l,
                  float* __restrict__ C1, __nv_bfloat16* __restrict__ C1h,
                  __nv_bfloat16* __restrict__ C1l,
                  const float2* __restrict__ lnStats,
                  const float* __restrict__ lnG, const float* __restrict__ lnB, int K) {
    __shared__ __nv_bfloat16 Ash[64][32 + APAD];
    __shared__ __nv_bfloat16 Asl[64][32 + APAD];
    __shared__ __nv_bfloat16 Wsh[64][32 + APAD];
    __shared__ __nv_bfloat16 Wsl[64][32 + APAD];

    const int tid = threadIdx.x;
    const int bn = blockIdx.x * 64;
    const int bm = blockIdx.y * 64;
    const int wid = tid >> 5, lane = tid & 31;
    const int wm = (wid >> 2) * 32;
    const int wn = (wid & 3) * 16;
    const int g  = lane >> 2;
    const int tg = lane & 3;

    const bool half0 = (bn < 256);
    const float* W    = half0 ? W0 : W1;
    const float* bias = half0 ? bias0 : bias1;
    float* C          = half0 ? C0 : C1;
    __nv_bfloat16* Ch = half0 ? C0h : C1h;
    __nv_bfloat16* Cl = half0 ? C0l : C1l;
    const int cb = bn & 255;

    const int ar = tid >> 2;
    const int ac = tid & 3;

    float2 st = make_float2(0.f, 1.f);
    if (lnStats) st = lnStats[bm + ar];

    float acc[2][2][4];
#pragma unroll
    for (int mt = 0; mt < 2; mt++)
#pragma unroll
        for (int nt = 0; nt < 2; nt++)
#pragma unroll
            for (int j = 0; j < 4; j++) acc[mt][nt][j] = 0.f;

    float4 fa0, fa1, fw0, fw1;
    {
        const float* Ab; int As;
        if (0 < K0) { Ab = A0; As = K0; } else { Ab = A1; As = K - K0; }
        const float* pa = Ab + (size_t)(bm + ar) * As + ac * 8;
        fa0 = ((const float4*)pa)[0]; fa1 = ((const float4*)pa)[1];
        const float* pw = W + (size_t)(cb + ar) * K + ac * 8;
        fw0 = ((const float4*)pw)[0]; fw1 = ((const float4*)pw)[1];
    }

    const int nkb = K / 32;
    for (int kb = 0; kb < nkb; kb++) {
        if (lnStats) {
            const int kcur = kb * 32 + ac * 8;
            float4 gg0 = *(const float4*)&lnG[kcur];
            float4 gg1 = *(const float4*)&lnG[kcur + 4];
            float4 bb0 = *(const float4*)&lnB[kcur];
            float4 bb1 = *(const float4*)&lnB[kcur + 4];
            fa0.x = fmaf((fa0.x - st.x) * st.y, gg0.x, bb0.x);
            fa0.y = fmaf((fa0.y - st.x) * st.y, gg0.y, bb0.y);
            fa0.z = fmaf((fa0.z - st.x) * st.y, gg0.z, bb0.z);
            fa0.w = fmaf((fa0.w - st.x) * st.y, gg0.w, bb0.w);
            fa1.x = fmaf((fa1.x - st.x) * st.y, gg1.x, bb1.x);
            fa1.y = fmaf((fa1.y - st.x) * st.y, gg1.y, bb1.y);
            fa1.z = fmaf((fa1.z - st.x) * st.y, gg1.z, bb1.z);
            fa1.w = fmaf((fa1.w - st.x) * st.y, gg1.w, bb1.w);
        }
        split8s(fa0, fa1, &Ash[ar][ac * 8], &Asl[ar][ac * 8]);
        split8s(fw0, fw1, &Wsh[ar][ac * 8], &Wsl[ar][ac * 8]);
        __syncthreads();

        if (kb + 1 < nkb) {
            const int k0 = (kb + 1) * 32;
            const float* Ab; int As;
            if (k0 < K0) { Ab = A0 + k0; As = K0; } else { Ab = A1 + (k0 - K0); As = K - K0; }
            const float* pa = Ab + (size_t)(bm + ar) * As + ac * 8;
            fa0 = ((const float4*)pa)[0]; fa1 = ((const float4*)pa)[1];
            const float* pw = W + (size_t)(cb + ar) * K + k0 + ac * 8;
            fw0 = ((const float4*)pw)[0]; fw1 = ((const float4*)pw)[1];
        }

#pragma unroll
        for (int ks = 0; ks < 2; ks++) {
            const int kk = ks * 16;
            uint32_t ah[2][4], al[2][4], bh[2][2], bl[2][2];
#pragma unroll
            for (int mt = 0; mt < 2; mt++) {
                const int rb = wm + mt * 16;
                ah[mt][0] = *(const uint32_t*)&Ash[rb + g    ][kk + 2*tg];
                ah[mt][1] = *(const uint32_t*)&Ash[rb + g + 8][kk + 2*tg];
                ah[mt][2] = *(const uint32_t*)&Ash[rb + g    ][kk + 2*tg + 8];
                ah[mt][3] = *(const uint32_t*)&Ash[rb + g + 8][kk + 2*tg + 8];
                al[mt][0] = *(const uint32_t*)&Asl[rb + g    ][kk + 2*tg];
                al[mt][1] = *(const uint32_t*)&Asl[rb + g + 8][kk + 2*tg];
                al[mt][2] = *(const uint32_t*)&Asl[rb + g    ][kk + 2*tg + 8];
                al[mt][3] = *(const uint32_t*)&Asl[rb + g + 8][kk + 2*tg + 8];
            }
#pragma unroll
            for (int nt = 0; nt < 2; nt++) {
                const int nb = wn + nt * 8;
                bh[nt][0] = *(const uint32_t*)&Wsh[nb + g][kk + 2*tg];
                bh[nt][1] = *(const uint32_t*)&Wsh[nb + g][kk + 2*tg + 8];
                bl[nt][0] = *(const uint32_t*)&Wsl[nb + g][kk + 2*tg];
                bl[nt][1] = *(const uint32_t*)&Wsl[nb + g][kk + 2*tg + 8];
            }
#pragma unroll
            for (int mt = 0; mt < 2; mt++)
#pragma unroll
                for (int nt = 0; nt < 2; nt++) {
                    mma_bf16(acc[mt][nt], ah[mt], bh[nt]);
                    mma_bf16(acc[mt][nt], al[mt], bh[nt]);
                    mma_bf16(acc[mt][nt], ah[mt], bl[nt]);
                }
        }
        __syncthreads();
    }

#pragma unroll
    for (int mt = 0; mt < 2; mt++) {
#pragma unroll
        for (int nt = 0; nt < 2; nt++) {
            const int col = cb + wn + nt * 8 + 2 * tg;
            const float bx = bias[col], by = bias[col + 1];
            const int r0 = bm + wm + mt * 16 + g;
            float v0 = acc[mt][nt][0] + bx, v1 = acc[mt][nt][1] + by;
            float v2 = acc[mt][nt][2] + bx, v3 = acc[mt][nt][3] + by;
            if (C) {
                *(float2*)&C[(size_t)r0 * DD + col]       = make_float2(v0, v1);
                *(float2*)&C[(size_t)(r0 + 8) * DD + col] = make_float2(v2, v3);
            } else {
                __nv_bfloat16 h0,l0,h1,l1,h2,l2,h3,l3;
                split1(v0,h0,l0); split1(v1,h1,l1); split1(v2,h2,l2); split1(v3,h3,l3);
                *(__nv_bfloat162*)&Ch[(size_t)r0 * DD + col]       = __halves2bfloat162(h0,h1);
                *(__nv_bfloat162*)&Cl[(size_t)r0 * DD + col]       = __halves2bfloat162(l0,l1);
                *(__nv_bfloat162*)&Ch[(size_t)(r0 + 8) * DD + col] = __halves2bfloat162(h2,h3);
                *(__nv_bfloat162*)&Cl[(size_t)(r0 + 8) * DD + col] = __halves2bfloat162(l2,l3);
            }
        }
    }
}

// ---------------- gelu (exact) + LayerNorm (D=256) ----------------------------
__global__ __launch_bounds__(256)
void gelu_ln_kernel(const float* __restrict__ in, const float* __restrict__ g,
                    const float* __restrict__ b, float* __restrict__ out) {
    __shared__ float sh[64];
    int row = blockIdx.x, tid = threadIdx.x;
    float x  = in[(size_t)row * 256 + tid];
    float ge = 0.5f * x * (1.f + erff(x * 0.70710678118654752f));
    float s = ge, s2 = ge * ge;
    blockReduce2(s, s2, sh);
    float mean = s * (1.f / 256.f);
    float var  = s2 * (1.f / 256.f) - mean * mean;
    out[(size_t)row * 256 + tid] = (ge - mean) * rsqrtf(var + 1e-5f) * g[tid] + b[tid];
}

// row stats of virtual z=[y|obs2] (D=512): mean + rstd
__global__ __launch_bounds__(512)
void ln_stats_kernel(const float* __restrict__ y, const float* __restrict__ o2,
                     float2* __restrict__ stats) {
    __shared__ float sh[64];
    int row = blockIdx.x, tid = threadIdx.x;
    float x = (tid < 256) ? y[(size_t)row * 256 + tid]
                          : o2[(size_t)row * 256 + tid - 256];
    float s = x, s2 = x * x;
    blockReduce2(s, s2, sh);
    if (tid == 0) {
        float mean = s * (1.f / 512.f);
        float var  = s2 * (1.f / 512.f) - mean * mean;
        stats[row] = make_float2(mean, rsqrtf(var + 1e-5f));
    }
}

// ---------------- tensor-core attention (32-key tiles; R9 version) -------------
#define AT_PAD 8
__global__ __launch_bounds__(128)
void attn_tc_kernel(const __nv_bfloat16* __restrict__ qh, const __nv_bfloat16* __restrict__ ql,
                    const __nv_bfloat16* __restrict__ kh, const __nv_bfloat16* __restrict__ kl,
                    const __nv_bfloat16* __restrict__ vh, const __nv_bfloat16* __restrict__ vl,
                    const unsigned* __restrict__ mbits, float* __restrict__ y) {
    __shared__ __nv_bfloat16 Ksh[32][32 + AT_PAD];
    __shared__ __nv_bfloat16 Ksl[32][32 + AT_PAD];
    __shared__ __nv_bfloat16 Vth[32][32 + AT_PAD];
    __shared__ __nv_bfloat16 Vtl[32][32 + AT_PAD];
    __shared__ unsigned Msk[128];

    const int b = blockIdx.z, h = blockIdx.y;
    const int qb = blockIdx.x * 128;
    const int tid = threadIdx.x;
    const int warp = tid >> 5, lane = tid & 31;
    const int g = lane >> 2, tg = lane & 3;

    uint32_t aqh[2][2][4], aql[2][2][4];
#pragma unroll
    for (int mt = 0; mt < 2; mt++) {
        const int r0 = qb + warp * 32 + mt * 16 + g;
#pragma unroll
        for (int ks = 0; ks < 2; ks++) {
            const size_t base0 = ((size_t)(b * LL + r0)) * DD + h * HD + ks * 16 + 2 * tg;
            const size_t base8 = base0 + 8ull * DD;
            aqh[mt][ks][0] = *(const uint32_t*)&qh[base0];
            aqh[mt][ks][1] = *(const uint32_t*)&qh[base8];
            aqh[mt][ks][2] = *(const uint32_t*)&qh[base0 + 8];
            aqh[mt][ks][3] = *(const uint32_t*)&qh[base8 + 8];
            aql[mt][ks][0] = *(const uint32_t*)&ql[base0];
            aql[mt][ks][1] = *(const uint32_t*)&ql[base8];
            aql[mt][ks][2] = *(const uint32_t*)&ql[base0 + 8];
            aql[mt][ks][3] = *(const uint32_t*)&ql[base8 + 8];
        }
    }

    float co[2][4][4];
#pragma unroll
    for (int mt = 0; mt < 2; mt++)
#pragma unroll
        for (int n = 0; n < 4; n++)
#pragma unroll
            for (int j = 0; j < 4; j++) co[mt][n][j] = 0.f;
    float dn[2][2] = {{0.f,0.f},{0.f,0.f}};

    for (int t = 0; t < LL / 32; t++) {
        const int kb = t * 32;
        {
            const int j = tid >> 2, d0 = (tid & 3) * 8;
            const size_t src = ((size_t)(b * LL + kb + j)) * DD + h * HD + d0;
            *(uint4*)&Ksh[j][d0] = *(const uint4*)&kh[src];
            *(uint4*)&Ksl[j][d0] = *(const uint4*)&kl[src];
            uint4 v4h = *(const uint4*)&vh[src];
            uint4 v4l = *(const uint4*)&vl[src];
            const __nv_bfloat16* ph = (const __nv_bfloat16*)&v4h;
            const __nv_bfloat16* pl = (const __nv_bfloat16*)&v4l;
#pragma unroll
            for (int i = 0; i < 8; i++) {
                Vth[d0 + i][j] = ph[i];
                Vtl[d0 + i][j] = pl[i];
            }
            Msk[tid] = mbits[((size_t)(b * LL + qb + tid)) * 32 + t];
        }
        __syncthreads();

        uint32_t bKh[2][4][2], bKl[2][4][2];
#pragma unroll
        for (int ks = 0; ks < 2; ks++)
#pragma unroll
            for (int n = 0; n < 4; n++) {
                bKh[ks][n][0] = *(const uint32_t*)&Ksh[n * 8 + g][ks * 16 + 2 * tg];
                bKh[ks][n][1] = *(const uint32_t*)&Ksh[n * 8 + g][ks * 16 + 2 * tg + 8];
                bKl[ks][n][0] = *(const uint32_t*)&Ksl[n * 8 + g][ks * 16 + 2 * tg];
                bKl[ks][n][1] = *(const uint32_t*)&Ksl[n * 8 + g][ks * 16 + 2 * tg + 8];
            }
        float cs[2][4][4];
#pragma unroll
        for (int mt = 0; mt < 2; mt++)
#pragma unroll
            for (int n = 0; n < 4; n++)
#pragma unroll
                for (int j = 0; j < 4; j++) cs[mt][n][j] = 0.f;
#pragma unroll
        for (int ks = 0; ks < 2; ks++)
#pragma unroll
            for (int mt = 0; mt < 2; mt++)
#pragma unroll
                for (int n = 0; n < 4; n++) {
                    mma_bf16(cs[mt][n], aqh[mt][ks], bKh[ks][n]);
                    mma_bf16(cs[mt][n], aql[mt][ks], bKh[ks][n]);
                    mma_bf16(cs[mt][n], aqh[mt][ks], bKl[ks][n]);
                }

        uint32_t bVh[2][4][2], bVl[2][4][2];
#pragma unroll
        for (int kp = 0; kp < 2; kp++)
#pragma unroll
            for (int n = 0; n < 4; n++) {
                bVh[kp][n][0] = *(const uint32_t*)&Vth[n * 8 + g][kp * 16 + 2 * tg];
                bVh[kp][n][1] = *(const uint32_t*)&Vth[n * 8 + g][kp * 16 + 2 * tg + 8];
                bVl[kp][n][0] = *(const uint32_t*)&Vtl[n * 8 + g][kp * 16 + 2 * tg];
                bVl[kp][n][1] = *(const uint32_t*)&Vtl[n * 8 + g][kp * 16 + 2 * tg + 8];
            }

#pragma unroll
        for (int mt = 0; mt < 2; mt++) {
            const int rbase = warp * 32 + mt * 16;
            const unsigned w0 = Msk[rbase + g];
            const unsigned w8 = Msk[rbase + g + 8];
            float pr[4][4];
#pragma unroll
            for (int n = 0; n < 4; n++) {
                const int c0 = n * 8 + 2 * tg;
                const float m00 = (float)((w0 >> c0) & 1u);
                const float m01 = (float)((w0 >> (c0 + 1)) & 1u);
                const float m10 = (float)((w8 >> c0) & 1u);
                const float m11 = (float)((w8 >> (c0 + 1)) & 1u);
                pr[n][0] = fexp(cs[mt][n][0]) * m00;
                pr[n][1] = fexp(cs[mt][n][1]) * m01;
                pr[n][2] = fexp(cs[mt][n][2]) * m10;
                pr[n][3] = fexp(cs[mt][n][3]) * m11;
                dn[mt][0] += pr[n][0] + pr[n][1];
                dn[mt][1] += pr[n][2] + pr[n][3];
            }
#pragma unroll
            for (int kp = 0; kp < 2; kp++) {
                float e00 = pr[kp*2][0], e01 = pr[kp*2][1], e02 = pr[kp*2][2], e03 = pr[kp*2][3];
                float e10 = pr[kp*2+1][0], e11 = pr[kp*2+1][1], e12 = pr[kp*2+1][2], e13 = pr[kp*2+1][3];
                uint32_t pah[4], pal[4];
                pah[0] = pack_bf2(e00, e01);
                pah[1] = pack_bf2(e02, e03);
                pah[2] = pack_bf2(e10, e11);
                pah[3] = pack_bf2(e12, e13);
                __nv_bfloat162 t0 = *(__nv_bfloat162*)&pah[0];
                __nv_bfloat162 t1 = *(__nv_bfloat162*)&pah[1];
                __nv_bfloat162 t2 = *(__nv_bfloat162*)&pah[2];
                __nv_bfloat162 t3 = *(__nv_bfloat162*)&pah[3];
                pal[0] = pack_bf2(e00 - __bfloat162float(t0.x), e01 - __bfloat162float(t0.y));
                pal[1] = pack_bf2(e02 - __bfloat162float(t1.x), e03 - __bfloat162float(t1.y));
                pal[2] = pack_bf2(e10 - __bfloat162float(t2.x), e11 - __bfloat162float(t2.y));
                pal[3] = pack_bf2(e12 - __bfloat162float(t3.x), e13 - __bfloat162float(t3.y));
#pragma unroll
                for (int n = 0; n < 4; n++) {
                    mma_bf16(co[mt][n], pah, bVh[kp][n]);
                    mma_bf16(co[mt][n], pal, bVh[kp][n]);
                    mma_bf16(co[mt][n], pah, bVl[kp][n]);
                }
            }
        }
        __syncthreads();
    }

#pragma unroll
    for (int mt = 0; mt < 2; mt++)
#pragma unroll
        for (int rh = 0; rh < 2; rh++) {
            float d = dn[mt][rh];
            d += __shfl_xor_sync(0xFFFFFFFFu, d, 1);
            d += __shfl_xor_sync(0xFFFFFFFFu, d, 2);
            dn[mt][rh] = (d > 0.f) ? 1.0f / d : 0.f;
        }

#pragma unroll
    for (int mt = 0; mt < 2; mt++) {
        const int r0 = qb + warp * 32 + mt * 16 + g;
#pragma unroll
        for (int n = 0; n < 4; n++) {
            const int col = h * HD + n * 8 + 2 * tg;
            *(float2*)&y[((size_t)(b * LL + r0)) * DD + col] =
                make_float2(co[mt][n][0] * dn[mt][0], co[mt][n][1] * dn[mt][0]);
            *(float2*)&y[((size_t)(b * LL + r0 + 8)) * DD + col] =
                make_float2(co[mt][n][2] * dn[mt][1], co[mt][n][3] * dn[mt][1]);
        }
    }
}

// ---------------- launch ------------------------------------------------------
extern "C" void kernel_launch(void* const* d_in, const int* in_sizes, int n_in,
                              void* d_out, int out_size) {
    const float* obs  = (const float*)d_in[0];
    const float* act  = (const float*)d_in[1];
    const int*   msk  = (const int*)  d_in[2];
    const float* Wq   = (const float*)d_in[3];
    const float* bq   = (const float*)d_in[4];
    const float* Wk   = (const float*)d_in[5];
    const float* bk   = (const float*)d_in[6];
    const float* Wv   = (const float*)d_in[7];
    const float* bv   = (const float*)d_in[8];
    const float* Wobs = (const float*)d_in[9];
    const float* bobs = (const float*)d_in[10];
    const float* gob  = (const float*)d_in[11];
    const float* bob  = (const float*)d_in[12];
    const float* g1   = (const float*)d_in[13];
    const float* b1   = (const float*)d_in[14];
    const float* Wp   = (const float*)d_in[15];
    const float* bp   = (const float*)d_in[16];
    const float* g2   = (const float*)d_in[17];
    const float* b2   = (const float*)d_in[18];

    float *obsp, *obs2, *yb, *hb;
    float2* stats;
    unsigned* mb;
    cudaGetSymbolAddress((void**)&obsp,  g_obsp);
    cudaGetSymbolAddress((void**)&obs2,  g_obs2);
    cudaGetSymbolAddress((void**)&yb,    g_y);
    cudaGetSymbolAddress((void**)&hb,    g_h);
    cudaGetSymbolAddress((void**)&stats, g_stats);
    cudaGetSymbolAddress((void**)&mb,    g_mbits);

    __nv_bfloat16 *qh,*ql,*kh,*kl,*vh,*vl;
    cudaGetSymbolAddress((void**)&qh, g_qh); cudaGetSymbolAddress((void**)&ql, g_ql);
    cudaGetSymbolAddress((void**)&kh, g_kh); cudaGetSymbolAddress((void**)&kl, g_kl);
    cudaGetSymbolAddress((void**)&vh, g_vh); cudaGetSymbolAddress((void**)&vl, g_vl);

    pack_mask_kernel<<<dim3(LL, BB), 128>>>(msk, mb);

    // q + obsp merged (A=obs, K=256)
    gemm2_kernel<<<dim3(8, 128), 256>>>(obs, obs, 256, Wq, Wobs, bq, bobs,
                                        nullptr, qh, ql, obsp, nullptr, nullptr,
                                        nullptr, nullptr, nullptr, 256);
    // k + v merged (A=[obs|act], K=512)
    gemm2_kernel<<<dim3(8, 128), 256>>>(obs, act, 256, Wk, Wv, bk, bv,
                                        nullptr, kh, kl, nullptr, vh, vl,
                                        nullptr, nullptr, nullptr, 512);

    gelu_ln_kernel<<<MROWS, 256>>>(obsp, gob, bob, obs2);

    attn_tc_kernel<<<dim3(LL / 128, HH, BB), 128>>>(qh, ql, kh, kl, vh, vl, mb, yb);

    // row stats of z=[y|obs2], then Wp GEMM with fused LayerNorm on A
    ln_stats_kernel<<<MROWS, 512>>>(yb, obs2, stats);
    gemm2_kernel<<<dim3(4, 128), 256>>>(yb, obs2, 256, Wp, Wp, bp, bp,
                                        hb, nullptr, nullptr, hb, nullptr, nullptr,
                                        stats, g1, b1, 512);

    gelu_ln_kernel<<<MROWS, 256>>>(hb, g2, b2, (float*)d_out);
}

// round 12
// speedup vs baseline: 1.0865x; 1.0502x over previous
#include <cuda_runtime.h>
#include <cuda_bf16.h>
#include <math.h>
#include <cstdint>

// Shapes (fixed)
#define BB 8
#define LL 1024
#define DD 256
#define HH 8
#define HD 32
#define MROWS (BB*LL)   // 8192

// ---------------- scratch (device globals) -----------------------------------
__device__ float g_obsp[MROWS * DD];
__device__ float g_obs2[MROWS * DD];
__device__ float g_y   [MROWS * DD];
__device__ float g_h   [MROWS * DD];
__device__ float2 g_stats[MROWS];
__device__ unsigned g_mbits[BB * LL * (LL/32)];

__device__ __nv_bfloat16 g_qh[MROWS * DD], g_ql[MROWS * DD];
__device__ __nv_bfloat16 g_kh[MROWS * DD], g_kl[MROWS * DD];
__device__ __nv_bfloat16 g_vh[MROWS * DD], g_vl[MROWS * DD];

// ---------------- helpers -----------------------------------------------------
__device__ __forceinline__ uint32_t smem_u32(const void* p) {
    return (uint32_t)__cvta_generic_to_shared(p);
}
__device__ __forceinline__ void split1(float x, __nv_bfloat16& h, __nv_bfloat16& l) {
    h = __float2bfloat16(x);
    l = __float2bfloat16(x - __bfloat162float(h));
}
// truncation split: hi = top16 bits (exact), lo = rn_bf16(x - hi); a -> low half
__device__ __forceinline__ uint32_t hi_pack(float a, float b) {
    uint32_t r;
    asm("prmt.b32 %0, %1, %2, 0x7632;" : "=r"(r)
        : "r"(__float_as_int(a)), "r"(__float_as_int(b)));
    return r;
}
__device__ __forceinline__ uint32_t lo_pack(float a, float b) {
    float la = a - __int_as_float(__float_as_int(a) & 0xFFFF0000u);
    float lb = b - __int_as_float(__float_as_int(b) & 0xFFFF0000u);
    uint32_t r;
    asm("cvt.rn.bf16x2.f32 %0, %1, %2;" : "=r"(r) : "f"(lb), "f"(la));
    return r;
}
// fast exp on FMA pipe, degree-4
__device__ __forceinline__ float fexp(float s) {
    const float L2E = 1.4426950408889634f;
    float t  = fmaf(s, L2E, 12582912.0f);
    int   ei = __float_as_int(t) << 23;
    float n  = t - 12582912.0f;
    float f  = fmaf(s, L2E, -n);
    float r  = 9.6181291e-3f;
    r = fmaf(r, f, 5.5504109e-2f);
    r = fmaf(r, f, 2.4022651e-1f);
    r = fmaf(r, f, 6.9314718e-1f);
    r = fmaf(r, f, 1.0f);
    return __int_as_float(__float_as_int(r) + ei);
}

#define CP_ASYNC16(dst, src) \
    asm volatile("cp.async.ca.shared.global [%0], [%1], 16;" :: "r"(dst), "l"(src))
#define CP_ASYNC4(dst, src) \
    asm volatile("cp.async.ca.shared.global [%0], [%1], 4;" :: "r"(dst), "l"(src))
#define CP_COMMIT() asm volatile("cp.async.commit_group;" ::: "memory")
#define CP_WAIT(n)  asm volatile("cp.async.wait_group %0;" :: "n"(n) : "memory")

__device__ __forceinline__ void ldsm4(uint32_t& r0, uint32_t& r1, uint32_t& r2,
                                      uint32_t& r3, uint32_t addr) {
    asm volatile("ldmatrix.sync.aligned.m8n8.x4.shared.b16 {%0,%1,%2,%3},[%4];"
        : "=r"(r0), "=r"(r1), "=r"(r2), "=r"(r3) : "r"(addr));
}
__device__ __forceinline__ void ldsm4t(uint32_t& r0, uint32_t& r1, uint32_t& r2,
                                       uint32_t& r3, uint32_t addr) {
    asm volatile("ldmatrix.sync.aligned.m8n8.x4.trans.shared.b16 {%0,%1,%2,%3},[%4];"
        : "=r"(r0), "=r"(r1), "=r"(r2), "=r"(r3) : "r"(addr));
}

// pack mask (diagonal cleared) into bitwords
__global__ __launch_bounds__(128)
void pack_mask_kernel(const int* __restrict__ mask, unsigned* __restrict__ bits) {
    int b = blockIdx.y, row = blockIdx.x;
    int lane = threadIdx.x & 31, warp = threadIdx.x >> 5;
    const int* mrow = mask + ((size_t)b * LL + row) * LL;
    for (int w = warp; w < 32; w += 4) {
        int col = w * 32 + lane;
        unsigned bit = (unsigned)((mrow[col] != 0) && (col != row));
        unsigned word = __ballot_sync(0xFFFFFFFFu, bit);
        if (lane == 0) bits[((size_t)b * LL + row) * 32 + w] = word;
    }
}

// ---------------- block reduction (parallel final stage) -----------------------
__device__ __forceinline__ void blockReduce2(float& a, float& b, float* sh) {
    int lane = threadIdx.x & 31, warp = threadIdx.x >> 5;
#pragma unroll
    for (int o = 16; o > 0; o >>= 1) {
        a += __shfl_xor_sync(0xFFFFFFFFu, a, o);
        b += __shfl_xor_sync(0xFFFFFFFFu, b, o);
    }
    if (lane == 0) { sh[warp * 2] = a; sh[warp * 2 + 1] = b; }
    __syncthreads();
    int nw = blockDim.x >> 5;
    if (warp == 0) {
        float sa = (lane < nw) ? sh[lane * 2]     : 0.f;
        float sb = (lane < nw) ? sh[lane * 2 + 1] : 0.f;
#pragma unroll
        for (int o = 8; o > 0; o >>= 1) {
            sa += __shfl_xor_sync(0xFFFFFFFFu, sa, o);
            sb += __shfl_xor_sync(0xFFFFFFFFu, sb, o);
        }
        if (lane == 0) { sh[0] = sa; sh[1] = sb; }
    }
    __syncthreads();
    a = sh[0]; b = sh[1];
}

// ---------------- dual-output fused-split GEMM via mma.sync --------------------
#define APAD 8

__device__ __forceinline__ void mma_bf16(float* c, const uint32_t* a, const uint32_t* b) {
    asm volatile(
        "mma.sync.aligned.m16n8k16.row.col.f32.bf16.bf16.f32 "
        "{%0,%1,%2,%3},{%4,%5,%6,%7},{%8,%9},{%0,%1,%2,%3};"
        : "+f"(c[0]), "+f"(c[1]), "+f"(c[2]), "+f"(c[3])
        : "r"(a[0]), "r"(a[1]), "r"(a[2]), "r"(a[3]), "r"(b[0]), "r"(b[1]));
}

__device__ __forceinline__ void split8s(float4 f0, float4 f1,
                                        __nv_bfloat16* hiDst, __nv_bfloat16* loDst) {
    uint4 hi, lo;
    hi.x = hi_pack(f0.x, f0.y); lo.x = lo_pack(f0.x, f0.y);
    hi.y = hi_pack(f0.z, f0.w); lo.y = lo_pack(f0.z, f0.w);
    hi.z = hi_pack(f1.x, f1.y); lo.z = lo_pack(f1.x, f1.y);
    hi.w = hi_pack(f1.z, f1.w); lo.w = lo_pack(f1.z, f1.w);
    *(uint4*)hiDst = hi;
    *(uint4*)loDst = lo;
}

__global__ __launch_bounds__(256)
void gemm2_kernel(const float* __restrict__ A0, const float* __restrict__ A1, int K0,
                  const float* __restrict__ W0, const float* __restrict__ W1,
                  const float* __restrict__ bias0, const float* __restrict__ bias1,
                  float* __restrict__ C0, __nv_bfloat16* __restrict__ C0h,
                  __nv_bfloat16* __restrict__ C0l,
                  float* __restrict__ C1, __nv_bfloat16* __restrict__ C1h,
                  __nv_bfloat16* __restrict__ C1l,
                  const float2* __restrict__ lnStats,
                  const float* __restrict__ lnG, const float* __restrict__ lnB, int K) {
    __shared__ __nv_bfloat16 Ash[64][32 + APAD];
    __shared__ __nv_bfloat16 Asl[64][32 + APAD];
    __shared__ __nv_bfloat16 Wsh[64][32 + APAD];
    __shared__ __nv_bfloat16 Wsl[64][32 + APAD];

    const int tid = threadIdx.x;
    const int bn = blockIdx.x * 64;
    const int bm = blockIdx.y * 64;
    const int wid = tid >> 5, lane = tid & 31;
    const int wm = (wid >> 2) * 32;
    const int wn = (wid & 3) * 16;
    const int g  = lane >> 2;
    const int tg = lane & 3;

    const bool half0 = (bn < 256);
    const float* W    = half0 ? W0 : W1;
    const float* bias = half0 ? bias0 : bias1;
    float* C          = half0 ? C0 : C1;
    __nv_bfloat16* Ch = half0 ? C0h : C1h;
    __nv_bfloat16* Cl = half0 ? C0l : C1l;
    const int cb = bn & 255;

    const int ar = tid >> 2;
    const int ac = tid & 3;

    float2 st = make_float2(0.f, 1.f);
    if (lnStats) st = lnStats[bm + ar];

    float acc[2][2][4];
#pragma unroll
    for (int mt = 0; mt < 2; mt++)
#pragma unroll
        for (int nt = 0; nt < 2; nt++)
#pragma unroll
            for (int j = 0; j < 4; j++) acc[mt][nt][j] = 0.f;

    float4 fa0, fa1, fw0, fw1;
    {
        const float* Ab; int As;
        if (0 < K0) { Ab = A0; As = K0; } else { Ab = A1; As = K - K0; }
        const float* pa = Ab + (size_t)(bm + ar) * As + ac * 8;
        fa0 = ((const float4*)pa)[0]; fa1 = ((const float4*)pa)[1];
        const float* pw = W + (size_t)(cb + ar) * K + ac * 8;
        fw0 = ((const float4*)pw)[0]; fw1 = ((const float4*)pw)[1];
    }

    const int nkb = K / 32;
    for (int kb = 0; kb < nkb; kb++) {
        if (lnStats) {
            const int kcur = kb * 32 + ac * 8;
            float4 gg0 = *(const float4*)&lnG[kcur];
            float4 gg1 = *(const float4*)&lnG[kcur + 4];
            float4 bb0 = *(const float4*)&lnB[kcur];
            float4 bb1 = *(const float4*)&lnB[kcur + 4];
            fa0.x = fmaf((fa0.x - st.x) * st.y, gg0.x, bb0.x);
            fa0.y = fmaf((fa0.y - st.x) * st.y, gg0.y, bb0.y);
            fa0.z = fmaf((fa0.z - st.x) * st.y, gg0.z, bb0.z);
            fa0.w = fmaf((fa0.w - st.x) * st.y, gg0.w, bb0.w);
            fa1.x = fmaf((fa1.x - st.x) * st.y, gg1.x, bb1.x);
            fa1.y = fmaf((fa1.y - st.x) * st.y, gg1.y, bb1.y);
            fa1.z = fmaf((fa1.z - st.x) * st.y, gg1.z, bb1.z);
            fa1.w = fmaf((fa1.w - st.x) * st.y, gg1.w, bb1.w);
        }
        split8s(fa0, fa1, &Ash[ar][ac * 8], &Asl[ar][ac * 8]);
        split8s(fw0, fw1, &Wsh[ar][ac * 8], &Wsl[ar][ac * 8]);
        __syncthreads();

        if (kb + 1 < nkb) {
            const int k0 = (kb + 1) * 32;
            const float* Ab; int As;
            if (k0 < K0) { Ab = A0 + k0; As = K0; } else { Ab = A1 + (k0 - K0); As = K - K0; }
            const float* pa = Ab + (size_t)(bm + ar) * As + ac * 8;
            fa0 = ((const float4*)pa)[0]; fa1 = ((const float4*)pa)[1];
            const float* pw = W + (size_t)(cb + ar) * K + k0 + ac * 8;
            fw0 = ((const float4*)pw)[0]; fw1 = ((const float4*)pw)[1];
        }

#pragma unroll
        for (int ks = 0; ks < 2; ks++) {
            const int kk = ks * 16;
            uint32_t ah[2][4], al[2][4], bh[2][2], bl[2][2];
#pragma unroll
            for (int mt = 0; mt < 2; mt++) {
                const int rb = wm + mt * 16;
                ah[mt][0] = *(const uint32_t*)&Ash[rb + g    ][kk + 2*tg];
                ah[mt][1] = *(const uint32_t*)&Ash[rb + g + 8][kk + 2*tg];
                ah[mt][2] = *(const uint32_t*)&Ash[rb + g    ][kk + 2*tg + 8];
                ah[mt][3] = *(const uint32_t*)&Ash[rb + g + 8][kk + 2*tg + 8];
                al[mt][0] = *(const uint32_t*)&Asl[rb + g    ][kk + 2*tg];
                al[mt][1] = *(const uint32_t*)&Asl[rb + g + 8][kk + 2*tg];
                al[mt][2] = *(const uint32_t*)&Asl[rb + g    ][kk + 2*tg + 8];
                al[mt][3] = *(const uint32_t*)&Asl[rb + g + 8][kk + 2*tg + 8];
            }
#pragma unroll
            for (int nt = 0; nt < 2; nt++) {
                const int nb = wn + nt * 8;
                bh[nt][0] = *(const uint32_t*)&Wsh[nb + g][kk + 2*tg];
                bh[nt][1] = *(const uint32_t*)&Wsh[nb + g][kk + 2*tg + 8];
                bl[nt][0] = *(const uint32_t*)&Wsl[nb + g][kk + 2*tg];
                bl[nt][1] = *(const uint32_t*)&Wsl[nb + g][kk + 2*tg + 8];
            }
#pragma unroll
            for (int mt = 0; mt < 2; mt++)
#pragma unroll
                for (int nt = 0; nt < 2; nt++) {
                    mma_bf16(acc[mt][nt], ah[mt], bh[nt]);
                    mma_bf16(acc[mt][nt], al[mt], bh[nt]);
                    mma_bf16(acc[mt][nt], ah[mt], bl[nt]);
                }
        }
        __syncthreads();
    }

#pragma unroll
    for (int mt = 0; mt < 2; mt++) {
#pragma unroll
        for (int nt = 0; nt < 2; nt++) {
            const int col = cb + wn + nt * 8 + 2 * tg;
            const float bx = bias[col], by = bias[col + 1];
            const int r0 = bm + wm + mt * 16 + g;
            float v0 = acc[mt][nt][0] + bx, v1 = acc[mt][nt][1] + by;
            float v2 = acc[mt][nt][2] + bx, v3 = acc[mt][nt][3] + by;
            if (C) {
                *(float2*)&C[(size_t)r0 * DD + col]       = make_float2(v0, v1);
                *(float2*)&C[(size_t)(r0 + 8) * DD + col] = make_float2(v2, v3);
            } else {
                __nv_bfloat16 h0,l0,h1,l1,h2,l2,h3,l3;
                split1(v0,h0,l0); split1(v1,h1,l1); split1(v2,h2,l2); split1(v3,h3,l3);
                *(__nv_bfloat162*)&Ch[(size_t)r0 * DD + col]       = __halves2bfloat162(h0,h1);
                *(__nv_bfloat162*)&Cl[(size_t)r0 * DD + col]       = __halves2bfloat162(l0,l1);
                *(__nv_bfloat162*)&Ch[(size_t)(r0 + 8) * DD + col] = __halves2bfloat162(h2,h3);
                *(__nv_bfloat162*)&Cl[(size_t)(r0 + 8) * DD + col] = __halves2bfloat162(l2,l3);
            }
        }
    }
}

// ---------------- gelu (exact) + LayerNorm (D=256) ----------------------------
__global__ __launch_bounds__(256)
void gelu_ln_kernel(const float* __restrict__ in, const float* __restrict__ g,
                    const float* __restrict__ b, float* __restrict__ out) {
    __shared__ float sh[64];
    int row = blockIdx.x, tid = threadIdx.x;
    float x  = in[(size_t)row * 256 + tid];
    float ge = 0.5f * x * (1.f + erff(x * 0.70710678118654752f));
    float s = ge, s2 = ge * ge;
    blockReduce2(s, s2, sh);
    float mean = s * (1.f / 256.f);
    float var  = s2 * (1.f / 256.f) - mean * mean;
    out[(size_t)row * 256 + tid] = (ge - mean) * rsqrtf(var + 1e-5f) * g[tid] + b[tid];
}

// row stats of virtual z=[y|obs2] (D=512): mean + rstd
__global__ __launch_bounds__(512)
void ln_stats_kernel(const float* __restrict__ y, const float* __restrict__ o2,
                     float2* __restrict__ stats) {
    __shared__ float sh[64];
    int row = blockIdx.x, tid = threadIdx.x;
    float x = (tid < 256) ? y[(size_t)row * 256 + tid]
                          : o2[(size_t)row * 256 + tid - 256];
    float s = x, s2 = x * x;
    blockReduce2(s, s2, sh);
    if (tid == 0) {
        float mean = s * (1.f / 512.f);
        float var  = s2 * (1.f / 512.f) - mean * mean;
        stats[row] = make_float2(mean, rsqrtf(var + 1e-5f));
    }
}

// ---------------- tensor-core attention: cp.async double-buffer + ldmatrix -----
#define KVS 40          // row stride in bf16 (32 + 8 pad) -> 80 bytes
__global__ __launch_bounds__(128)
void attn_tc_kernel(const __nv_bfloat16* __restrict__ qh, const __nv_bfloat16* __restrict__ ql,
                    const __nv_bfloat16* __restrict__ kh, const __nv_bfloat16* __restrict__ kl,
                    const __nv_bfloat16* __restrict__ vh, const __nv_bfloat16* __restrict__ vl,
                    const unsigned* __restrict__ mbits, float* __restrict__ y) {
    // [buf][hi/lo][key 32][KVS], natural [key][dim] layout for BOTH K and V
    __shared__ __align__(16) __nv_bfloat16 Ks[2][2][32][KVS];
    __shared__ __align__(16) __nv_bfloat16 Vs[2][2][32][KVS];
    __shared__ unsigned Msk[2][128];

    const int b = blockIdx.z, h = blockIdx.y;
    const int qb = blockIdx.x * 128;
    const int tid = threadIdx.x;
    const int warp = tid >> 5, lane = tid & 31;
    const int g = lane >> 2, tg = lane & 3;

    const uint32_t ksBase = smem_u32(&Ks[0][0][0][0]);
    const uint32_t vsBase = smem_u32(&Vs[0][0][0][0]);
    const uint32_t mkBase = smem_u32(&Msk[0][0]);
    const uint32_t planeB = 32 * KVS * 2;   // bytes per [32][KVS] plane

    // ldmatrix lane roles
    const int li = lane >> 3, lr = lane & 7;

    // Q fragments (resident)
    uint32_t aqh[2][2][4], aql[2][2][4];
#pragma unroll
    for (int mt = 0; mt < 2; mt++) {
        const int r0 = qb + warp * 32 + mt * 16 + g;
#pragma unroll
        for (int ks = 0; ks < 2; ks++) {
            const size_t base0 = ((size_t)(b * LL + r0)) * DD + h * HD + ks * 16 + 2 * tg;
            const size_t base8 = base0 + 8ull * DD;
            aqh[mt][ks][0] = *(const uint32_t*)&qh[base0];
            aqh[mt][ks][1] = *(const uint32_t*)&qh[base8];
            aqh[mt][ks][2] = *(const uint32_t*)&qh[base0 + 8];
            aqh[mt][ks][3] = *(const uint32_t*)&qh[base8 + 8];
            aql[mt][ks][0] = *(const uint32_t*)&ql[base0];
            aql[mt][ks][1] = *(const uint32_t*)&ql[base8];
            aql[mt][ks][2] = *(const uint32_t*)&ql[base0 + 8];
            aql[mt][ks][3] = *(const uint32_t*)&ql[base8 + 8];
        }
    }

    float co[2][4][4];
#pragma unroll
    for (int mt = 0; mt < 2; mt++)
#pragma unroll
        for (int n = 0; n < 4; n++)
#pragma unroll
            for (int j = 0; j < 4; j++) co[mt][n][j] = 0.f;
    float dn[2][2] = {{0.f,0.f},{0.f,0.f}};

    const int lrow = tid >> 2, lc = tid & 3;    // loader: key row, 16B chunk

    // issue tile 0
    {
        const size_t src = ((size_t)(b * LL + 0 + lrow)) * DD + h * HD + lc * 8;
        const uint32_t off = (uint32_t)lrow * (KVS * 2) + lc * 16;
        CP_ASYNC16(ksBase + off,              kh + src);
        CP_ASYNC16(ksBase + planeB + off,     kl + src);
        CP_ASYNC16(vsBase + off,              vh + src);
        CP_ASYNC16(vsBase + planeB + off,     vl + src);
        CP_ASYNC4(mkBase + tid * 4, mbits + ((size_t)(b * LL + qb + tid)) * 32 + 0);
        CP_COMMIT();
    }

    const int NT = LL / 32;
    for (int t = 0; t < NT; t++) {
        const int buf = t & 1;
        if (t + 1 < NT) {
            const int nb = (t + 1) & 1;
            const size_t src = ((size_t)(b * LL + (t + 1) * 32 + lrow)) * DD + h * HD + lc * 8;
            const uint32_t off = (uint32_t)(nb * 2) * planeB
                               + (uint32_t)lrow * (KVS * 2) + lc * 16;
            CP_ASYNC16(ksBase + off,          kh + src);
            CP_ASYNC16(ksBase + planeB + off, kl + src);
            CP_ASYNC16(vsBase + off,          vh + src);
            CP_ASYNC16(vsBase + planeB + off, vl + src);
            CP_ASYNC4(mkBase + (nb * 128 + tid) * 4,
                      mbits + ((size_t)(b * LL + qb + tid)) * 32 + t + 1);
            CP_COMMIT();
            CP_WAIT(1);
        } else {
            CP_WAIT(0);
        }
        __syncthreads();

        // ---- fragment loads via ldmatrix ----
        const uint32_t kB0 = ksBase + (uint32_t)(buf * 2) * planeB;         // K hi
        const uint32_t kB1 = kB0 + planeB;                                  // K lo
        const uint32_t vB0 = vsBase + (uint32_t)(buf * 2) * planeB;         // V hi
        const uint32_t vB1 = vB0 + planeB;                                  // V lo

        uint32_t bKh[2][4][2], bKl[2][4][2];
#pragma unroll
        for (int ks = 0; ks < 2; ks++)
#pragma unroll
            for (int np = 0; np < 2; np++) {
                // tiles: keys np*16 + (li>>1)*8 + lr ; dims ks*16 + (li&1)*8
                const uint32_t off = (uint32_t)(np * 16 + ((li >> 1) << 3) + lr) * (KVS * 2)
                                   + (uint32_t)(ks * 16 + ((li & 1) << 3)) * 2;
                ldsm4(bKh[ks][np*2][0], bKh[ks][np*2][1],
                      bKh[ks][np*2+1][0], bKh[ks][np*2+1][1], kB0 + off);
                ldsm4(bKl[ks][np*2][0], bKl[ks][np*2][1],
                      bKl[ks][np*2+1][0], bKl[ks][np*2+1][1], kB1 + off);
            }

        float cs[2][4][4];
#pragma unroll
        for (int mt = 0; mt < 2; mt++)
#pragma unroll
            for (int n = 0; n < 4; n++)
#pragma unroll
                for (int j = 0; j < 4; j++) cs[mt][n][j] = 0.f;
#pragma unroll
        for (int ks = 0; ks < 2; ks++)
#pragma unroll
            for (int mt = 0; mt < 2; mt++)
#pragma unroll
                for (int n = 0; n < 4; n++) {
                    mma_bf16(cs[mt][n], aqh[mt][ks], bKh[ks][n]);
                    mma_bf16(cs[mt][n], aql[mt][ks], bKh[ks][n]);
                    mma_bf16(cs[mt][n], aqh[mt][ks], bKl[ks][n]);
                }

        uint32_t bVh[2][4][2], bVl[2][4][2];
#pragma unroll
        for (int kp = 0; kp < 2; kp++)
#pragma unroll
            for (int np = 0; np < 2; np++) {
                // tiles (trans): keys kp*16 + (li&1)*8 + lr ; dims np*16 + (li>>1)*8
                const uint32_t off = (uint32_t)(kp * 16 + ((li & 1) << 3) + lr) * (KVS * 2)
                                   + (uint32_t)(np * 16 + ((li >> 1) << 3)) * 2;
                ldsm4t(bVh[kp][np*2][0], bVh[kp][np*2][1],
                       bVh[kp][np*2+1][0], bVh[kp][np*2+1][1], vB0 + off);
                ldsm4t(bVl[kp][np*2][0], bVl[kp][np*2][1],
                       bVl[kp][np*2+1][0], bVl[kp][np*2+1][1], vB1 + off);
            }

#pragma unroll
        for (int mt = 0; mt < 2; mt++) {
            const int rbase = warp * 32 + mt * 16;
            const unsigned w0 = Msk[buf][rbase + g];
            const unsigned w8 = Msk[buf][rbase + g + 8];
            float pr[4][4];
#pragma unroll
            for (int n = 0; n < 4; n++) {
                const int c0 = n * 8 + 2 * tg;
                const float m00 = (float)((w0 >> c0) & 1u);
                const float m01 = (float)((w0 >> (c0 + 1)) & 1u);
                const float m10 = (float)((w8 >> c0) & 1u);
                const float m11 = (float)((w8 >> (c0 + 1)) & 1u);
                pr[n][0] = fexp(cs[mt][n][0]) * m00;
                pr[n][1] = fexp(cs[mt][n][1]) * m01;
                pr[n][2] = fexp(cs[mt][n][2]) * m10;
                pr[n][3] = fexp(cs[mt][n][3]) * m11;
                dn[mt][0] += pr[n][0] + pr[n][1];
                dn[mt][1] += pr[n][2] + pr[n][3];
            }
#pragma unroll
            for (int kp = 0; kp < 2; kp++) {
                float e00 = pr[kp*2][0], e01 = pr[kp*2][1], e02 = pr[kp*2][2], e03 = pr[kp*2][3];
                float e10 = pr[kp*2+1][0], e11 = pr[kp*2+1][1], e12 = pr[kp*2+1][2], e13 = pr[kp*2+1][3];
                uint32_t pah[4], pal[4];
                pah[0] = hi_pack(e00, e01); pal[0] = lo_pack(e00, e01);
                pah[1] = hi_pack(e02, e03); pal[1] = lo_pack(e02, e03);
                pah[2] = hi_pack(e10, e11); pal[2] = lo_pack(e10, e11);
                pah[3] = hi_pack(e12, e13); pal[3] = lo_pack(e12, e13);
#pragma unroll
                for (int n = 0; n < 4; n++) {
                    mma_bf16(co[mt][n], pah, bVh[kp][n]);
                    mma_bf16(co[mt][n], pal, bVh[kp][n]);
                    mma_bf16(co[mt][n], pah, bVl[kp][n]);
                }
            }
        }
        __syncthreads();
    }

#pragma unroll
    for (int mt = 0; mt < 2; mt++)
#pragma unroll
        for (int rh = 0; rh < 2; rh++) {
            float d = dn[mt][rh];
            d += __shfl_xor_sync(0xFFFFFFFFu, d, 1);
            d += __shfl_xor_sync(0xFFFFFFFFu, d, 2);
            dn[mt][rh] = (d > 0.f) ? 1.0f / d : 0.f;
        }

#pragma unroll
    for (int mt = 0; mt < 2; mt++) {
        const int r0 = qb + warp * 32 + mt * 16 + g;
#pragma unroll
        for (int n = 0; n < 4; n++) {
            const int col = h * HD + n * 8 + 2 * tg;
            *(float2*)&y[((size_t)(b * LL + r0)) * DD + col] =
                make_float2(co[mt][n][0] * dn[mt][0], co[mt][n][1] * dn[mt][0]);
            *(float2*)&y[((size_t)(b * LL + r0 + 8)) * DD + col] =
                make_float2(co[mt][n][2] * dn[mt][1], co[mt][n][3] * dn[mt][1]);
        }
    }
}

// ---------------- launch ------------------------------------------------------
extern "C" void kernel_launch(void* const* d_in, const int* in_sizes, int n_in,
                              void* d_out, int out_size) {
    const float* obs  = (const float*)d_in[0];
    const float* act  = (const float*)d_in[1];
    const int*   msk  = (const int*)  d_in[2];
    const float* Wq   = (const float*)d_in[3];
    const float* bq   = (const float*)d_in[4];
    const float* Wk   = (const float*)d_in[5];
    const float* bk   = (const float*)d_in[6];
    const float* Wv   = (const float*)d_in[7];
    const float* bv   = (const float*)d_in[8];
    const float* Wobs = (const float*)d_in[9];
    const float* bobs = (const float*)d_in[10];
    const float* gob  = (const float*)d_in[11];
    const float* bob  = (const float*)d_in[12];
    const float* g1   = (const float*)d_in[13];
    const float* b1   = (const float*)d_in[14];
    const float* Wp   = (const float*)d_in[15];
    const float* bp   = (const float*)d_in[16];
    const float* g2   = (const float*)d_in[17];
    const float* b2   = (const float*)d_in[18];

    float *obsp, *obs2, *yb, *hb;
    float2* stats;
    unsigned* mb;
    cudaGetSymbolAddress((void**)&obsp,  g_obsp);
    cudaGetSymbolAddress((void**)&obs2,  g_obs2);
    cudaGetSymbolAddress((void**)&yb,    g_y);
    cudaGetSymbolAddress((void**)&hb,    g_h);
    cudaGetSymbolAddress((void**)&stats, g_stats);
    cudaGetSymbolAddress((void**)&mb,    g_mbits);

    __nv_bfloat16 *qh,*ql,*kh,*kl,*vh,*vl;
    cudaGetSymbolAddress((void**)&qh, g_qh); cudaGetSymbolAddress((void**)&ql, g_ql);
    cudaGetSymbolAddress((void**)&kh, g_kh); cudaGetSymbolAddress((void**)&kl, g_kl);
    cudaGetSymbolAddress((void**)&vh, g_vh); cudaGetSymbolAddress((void**)&vl, g_vl);

    pack_mask_kernel<<<dim3(LL, BB), 128>>>(msk, mb);

    // q + obsp merged (A=obs, K=256)
    gemm2_kernel<<<dim3(8, 128), 256>>>(obs, obs, 256, Wq, Wobs, bq, bobs,
                                        nullptr, qh, ql, obsp, nullptr, nullptr,
                                        nullptr, nullptr, nullptr, 256);
    // k + v merged (A=[obs|act], K=512)
    gemm2_kernel<<<dim3(8, 128), 256>>>(obs, act, 256, Wk, Wv, bk, bv,
                                        nullptr, kh, kl, nullptr, vh, vl,
                                        nullptr, nullptr, nullptr, 512);

    gelu_ln_kernel<<<MROWS, 256>>>(obsp, gob, bob, obs2);

    attn_tc_kernel<<<dim3(LL / 128, HH, BB), 128>>>(qh, ql, kh, kl, vh, vl, mb, yb);

    // row stats of z=[y|obs2], then Wp GEMM with fused LayerNorm on A
    ln_stats_kernel<<<MROWS, 512>>>(yb, obs2, stats);
    gemm2_kernel<<<dim3(4, 128), 256>>>(yb, obs2, 256, Wp, Wp, bp, bp,
                                        hb, nullptr, nullptr, hb, nullptr, nullptr,
                                        stats, g1, b1, 512);

    gelu_ln_kernel<<<MROWS, 256>>>(hb, g2, b2, (float*)d_out);
}

// round 13
// speedup vs baseline: 1.2232x; 1.1258x over previous
#include <cuda_runtime.h>
#include <cuda_bf16.h>
#include <math.h>
#include <cstdint>

// Shapes (fixed)
#define BB 8
#define LL 1024
#define DD 256
#define HH 8
#define HD 32
#define MROWS (BB*LL)   // 8192

// ---------------- scratch (device globals) -----------------------------------
__device__ float g_obsp[MROWS * DD];
__device__ float g_obs2[MROWS * DD];
__device__ float g_y   [MROWS * DD];
__device__ float g_h   [MROWS * DD];
__device__ float2 g_stats[MROWS];
__device__ unsigned g_mbits[BB * LL * (LL/32)];

__device__ __nv_bfloat16 g_qh[MROWS * DD], g_ql[MROWS * DD];
__device__ __nv_bfloat16 g_kh[MROWS * DD], g_kl[MROWS * DD];
__device__ __nv_bfloat16 g_vh[MROWS * DD], g_vl[MROWS * DD];

// ---------------- helpers -----------------------------------------------------
__device__ __forceinline__ uint32_t smem_u32(const void* p) {
    return (uint32_t)__cvta_generic_to_shared(p);
}
__device__ __forceinline__ void split1(float x, __nv_bfloat16& h, __nv_bfloat16& l) {
    h = __float2bfloat16(x);
    l = __float2bfloat16(x - __bfloat162float(h));
}
// truncation split: hi = top16 bits (exact), lo = rn_bf16(x - hi); a -> low half
__device__ __forceinline__ uint32_t hi_pack(float a, float b) {
    uint32_t r;
    asm("prmt.b32 %0, %1, %2, 0x7632;" : "=r"(r)
        : "r"(__float_as_int(a)), "r"(__float_as_int(b)));
    return r;
}
__device__ __forceinline__ uint32_t lo_pack(float a, float b) {
    float la = a - __int_as_float(__float_as_int(a) & 0xFFFF0000u);
    float lb = b - __int_as_float(__float_as_int(b) & 0xFFFF0000u);
    uint32_t r;
    asm("cvt.rn.bf16x2.f32 %0, %1, %2;" : "=r"(r) : "f"(lb), "f"(la));
    return r;
}
// fast exp on FMA pipe, degree-4
__device__ __forceinline__ float fexp(float s) {
    const float L2E = 1.4426950408889634f;
    float t  = fmaf(s, L2E, 12582912.0f);
    int   ei = __float_as_int(t) << 23;
    float n  = t - 12582912.0f;
    float f  = fmaf(s, L2E, -n);
    float r  = 9.6181291e-3f;
    r = fmaf(r, f, 5.5504109e-2f);
    r = fmaf(r, f, 2.4022651e-1f);
    r = fmaf(r, f, 6.9314718e-1f);
    r = fmaf(r, f, 1.0f);
    return __int_as_float(__float_as_int(r) + ei);
}

#define CP_ASYNC16(dst, src) \
    asm volatile("cp.async.ca.shared.global [%0], [%1], 16;" :: "r"(dst), "l"(src))
#define CP_ASYNC4(dst, src) \
    asm volatile("cp.async.ca.shared.global [%0], [%1], 4;" :: "r"(dst), "l"(src))
#define CP_COMMIT() asm volatile("cp.async.commit_group;" ::: "memory")
#define CP_WAIT(n)  asm volatile("cp.async.wait_group %0;" :: "n"(n) : "memory")

__device__ __forceinline__ void ldsm4(uint32_t& r0, uint32_t& r1, uint32_t& r2,
                                      uint32_t& r3, uint32_t addr) {
    asm volatile("ldmatrix.sync.aligned.m8n8.x4.shared.b16 {%0,%1,%2,%3},[%4];"
        : "=r"(r0), "=r"(r1), "=r"(r2), "=r"(r3) : "r"(addr));
}
__device__ __forceinline__ void ldsm4t(uint32_t& r0, uint32_t& r1, uint32_t& r2,
                                       uint32_t& r3, uint32_t addr) {
    asm volatile("ldmatrix.sync.aligned.m8n8.x4.trans.shared.b16 {%0,%1,%2,%3},[%4];"
        : "=r"(r0), "=r"(r1), "=r"(r2), "=r"(r3) : "r"(addr));
}

// pack mask (diagonal cleared) into bitwords
__global__ __launch_bounds__(128)
void pack_mask_kernel(const int* __restrict__ mask, unsigned* __restrict__ bits) {
    int b = blockIdx.y, row = blockIdx.x;
    int lane = threadIdx.x & 31, warp = threadIdx.x >> 5;
    const int* mrow = mask + ((size_t)b * LL + row) * LL;
    for (int w = warp; w < 32; w += 4) {
        int col = w * 32 + lane;
        unsigned bit = (unsigned)((mrow[col] != 0) && (col != row));
        unsigned word = __ballot_sync(0xFFFFFFFFu, bit);
        if (lane == 0) bits[((size_t)b * LL + row) * 32 + w] = word;
    }
}

// ---------------- dual-output fused-split GEMM via mma.sync --------------------
#define APAD 8

__device__ __forceinline__ void mma_bf16(float* c, const uint32_t* a, const uint32_t* b) {
    asm volatile(
        "mma.sync.aligned.m16n8k16.row.col.f32.bf16.bf16.f32 "
        "{%0,%1,%2,%3},{%4,%5,%6,%7},{%8,%9},{%0,%1,%2,%3};"
        : "+f"(c[0]), "+f"(c[1]), "+f"(c[2]), "+f"(c[3])
        : "r"(a[0]), "r"(a[1]), "r"(a[2]), "r"(a[3]), "r"(b[0]), "r"(b[1]));
}

__device__ __forceinline__ void split8s(float4 f0, float4 f1,
                                        __nv_bfloat16* hiDst, __nv_bfloat16* loDst) {
    uint4 hi, lo;
    hi.x = hi_pack(f0.x, f0.y); lo.x = lo_pack(f0.x, f0.y);
    hi.y = hi_pack(f0.z, f0.w); lo.y = lo_pack(f0.z, f0.w);
    hi.z = hi_pack(f1.x, f1.y); lo.z = lo_pack(f1.x, f1.y);
    hi.w = hi_pack(f1.z, f1.w); lo.w = lo_pack(f1.z, f1.w);
    *(uint4*)hiDst = hi;
    *(uint4*)loDst = lo;
}

__global__ __launch_bounds__(256)
void gemm2_kernel(const float* __restrict__ A0, const float* __restrict__ A1, int K0,
                  const float* __restrict__ W0, const float* __restrict__ W1,
                  const float* __restrict__ bias0, const float* __restrict__ bias1,
                  float* __restrict__ C0, __nv_bfloat16* __restrict__ C0h,
                  __nv_bfloat16* __restrict__ C0l,
                  float* __restrict__ C1, __nv_bfloat16* __restrict__ C1h,
                  __nv_bfloat16* __restrict__ C1l,
                  const float2* __restrict__ lnStats,
                  const float* __restrict__ lnG, const float* __restrict__ lnB, int K) {
    __shared__ __nv_bfloat16 Ash[64][32 + APAD];
    __shared__ __nv_bfloat16 Asl[64][32 + APAD];
    __shared__ __nv_bfloat16 Wsh[64][32 + APAD];
    __shared__ __nv_bfloat16 Wsl[64][32 + APAD];

    const int tid = threadIdx.x;
    const int bn = blockIdx.x * 64;
    const int bm = blockIdx.y * 64;
    const int wid = tid >> 5, lane = tid & 31;
    const int wm = (wid >> 2) * 32;
    const int wn = (wid & 3) * 16;
    const int g  = lane >> 2;
    const int tg = lane & 3;

    const bool half0 = (bn < 256);
    const float* W    = half0 ? W0 : W1;
    const float* bias = half0 ? bias0 : bias1;
    float* C          = half0 ? C0 : C1;
    __nv_bfloat16* Ch = half0 ? C0h : C1h;
    __nv_bfloat16* Cl = half0 ? C0l : C1l;
    const int cb = bn & 255;

    const int ar = tid >> 2;
    const int ac = tid & 3;

    float2 st = make_float2(0.f, 1.f);
    if (lnStats) st = lnStats[bm + ar];

    float acc[2][2][4];
#pragma unroll
    for (int mt = 0; mt < 2; mt++)
#pragma unroll
        for (int nt = 0; nt < 2; nt++)
#pragma unroll
            for (int j = 0; j < 4; j++) acc[mt][nt][j] = 0.f;

    float4 fa0, fa1, fw0, fw1;
    {
        const float* Ab; int As;
        if (0 < K0) { Ab = A0; As = K0; } else { Ab = A1; As = K - K0; }
        const float* pa = Ab + (size_t)(bm + ar) * As + ac * 8;
        fa0 = ((const float4*)pa)[0]; fa1 = ((const float4*)pa)[1];
        const float* pw = W + (size_t)(cb + ar) * K + ac * 8;
        fw0 = ((const float4*)pw)[0]; fw1 = ((const float4*)pw)[1];
    }

    const int nkb = K / 32;
    for (int kb = 0; kb < nkb; kb++) {
        if (lnStats) {
            const int kcur = kb * 32 + ac * 8;
            float4 gg0 = *(const float4*)&lnG[kcur];
            float4 gg1 = *(const float4*)&lnG[kcur + 4];
            float4 bb0 = *(const float4*)&lnB[kcur];
            float4 bb1 = *(const float4*)&lnB[kcur + 4];
            fa0.x = fmaf((fa0.x - st.x) * st.y, gg0.x, bb0.x);
            fa0.y = fmaf((fa0.y - st.x) * st.y, gg0.y, bb0.y);
            fa0.z = fmaf((fa0.z - st.x) * st.y, gg0.z, bb0.z);
            fa0.w = fmaf((fa0.w - st.x) * st.y, gg0.w, bb0.w);
            fa1.x = fmaf((fa1.x - st.x) * st.y, gg1.x, bb1.x);
            fa1.y = fmaf((fa1.y - st.x) * st.y, gg1.y, bb1.y);
            fa1.z = fmaf((fa1.z - st.x) * st.y, gg1.z, bb1.z);
            fa1.w = fmaf((fa1.w - st.x) * st.y, gg1.w, bb1.w);
        }
        split8s(fa0, fa1, &Ash[ar][ac * 8], &Asl[ar][ac * 8]);
        split8s(fw0, fw1, &Wsh[ar][ac * 8], &Wsl[ar][ac * 8]);
        __syncthreads();

        if (kb + 1 < nkb) {
            const int k0 = (kb + 1) * 32;
            const float* Ab; int As;
            if (k0 < K0) { Ab = A0 + k0; As = K0; } else { Ab = A1 + (k0 - K0); As = K - K0; }
            const float* pa = Ab + (size_t)(bm + ar) * As + ac * 8;
            fa0 = ((const float4*)pa)[0]; fa1 = ((const float4*)pa)[1];
            const float* pw = W + (size_t)(cb + ar) * K + k0 + ac * 8;
            fw0 = ((const float4*)pw)[0]; fw1 = ((const float4*)pw)[1];
        }

#pragma unroll
        for (int ks = 0; ks < 2; ks++) {
            const int kk = ks * 16;
            uint32_t ah[2][4], al[2][4], bh[2][2], bl[2][2];
#pragma unroll
            for (int mt = 0; mt < 2; mt++) {
                const int rb = wm + mt * 16;
                ah[mt][0] = *(const uint32_t*)&Ash[rb + g    ][kk + 2*tg];
                ah[mt][1] = *(const uint32_t*)&Ash[rb + g + 8][kk + 2*tg];
                ah[mt][2] = *(const uint32_t*)&Ash[rb + g    ][kk + 2*tg + 8];
                ah[mt][3] = *(const uint32_t*)&Ash[rb + g + 8][kk + 2*tg + 8];
                al[mt][0] = *(const uint32_t*)&Asl[rb + g    ][kk + 2*tg];
                al[mt][1] = *(const uint32_t*)&Asl[rb + g + 8][kk + 2*tg];
                al[mt][2] = *(const uint32_t*)&Asl[rb + g    ][kk + 2*tg + 8];
                al[mt][3] = *(const uint32_t*)&Asl[rb + g + 8][kk + 2*tg + 8];
            }
#pragma unroll
            for (int nt = 0; nt < 2; nt++) {
                const int nb = wn + nt * 8;
                bh[nt][0] = *(const uint32_t*)&Wsh[nb + g][kk + 2*tg];
                bh[nt][1] = *(const uint32_t*)&Wsh[nb + g][kk + 2*tg + 8];
                bl[nt][0] = *(const uint32_t*)&Wsl[nb + g][kk + 2*tg];
                bl[nt][1] = *(const uint32_t*)&Wsl[nb + g][kk + 2*tg + 8];
            }
#pragma unroll
            for (int mt = 0; mt < 2; mt++)
#pragma unroll
                for (int nt = 0; nt < 2; nt++) {
                    mma_bf16(acc[mt][nt], ah[mt], bh[nt]);
                    mma_bf16(acc[mt][nt], al[mt], bh[nt]);
                    mma_bf16(acc[mt][nt], ah[mt], bl[nt]);
                }
        }
        __syncthreads();
    }

#pragma unroll
    for (int mt = 0; mt < 2; mt++) {
#pragma unroll
        for (int nt = 0; nt < 2; nt++) {
            const int col = cb + wn + nt * 8 + 2 * tg;
            const float bx = bias[col], by = bias[col + 1];
            const int r0 = bm + wm + mt * 16 + g;
            float v0 = acc[mt][nt][0] + bx, v1 = acc[mt][nt][1] + by;
            float v2 = acc[mt][nt][2] + bx, v3 = acc[mt][nt][3] + by;
            if (C) {
                *(float2*)&C[(size_t)r0 * DD + col]       = make_float2(v0, v1);
                *(float2*)&C[(size_t)(r0 + 8) * DD + col] = make_float2(v2, v3);
            } else {
                __nv_bfloat16 h0,l0,h1,l1,h2,l2,h3,l3;
                split1(v0,h0,l0); split1(v1,h1,l1); split1(v2,h2,l2); split1(v3,h3,l3);
                *(__nv_bfloat162*)&Ch[(size_t)r0 * DD + col]       = __halves2bfloat162(h0,h1);
                *(__nv_bfloat162*)&Cl[(size_t)r0 * DD + col]       = __halves2bfloat162(l0,l1);
                *(__nv_bfloat162*)&Ch[(size_t)(r0 + 8) * DD + col] = __halves2bfloat162(h2,h3);
                *(__nv_bfloat162*)&Cl[(size_t)(r0 + 8) * DD + col] = __halves2bfloat162(l2,l3);
            }
        }
    }
}

// ---------------- warp-per-row gelu (exact) + LayerNorm (D=256) ----------------
// 8 rows per 256-thr block; no barriers, no smem; lane handles 8 columns.
__global__ __launch_bounds__(256)
void gelu_ln_warp_kernel(const float* __restrict__ in, const float* __restrict__ g,
                         const float* __restrict__ b, float* __restrict__ out) {
    const int warp = threadIdx.x >> 5, lane = threadIdx.x & 31;
    const int row = blockIdx.x * 8 + warp;
    const int c0 = lane * 8;
    const float* ip = in + (size_t)row * 256 + c0;
    float4 x0 = ((const float4*)ip)[0];
    float4 x1 = ((const float4*)ip)[1];
    float xs[8] = {x0.x, x0.y, x0.z, x0.w, x1.x, x1.y, x1.z, x1.w};
    float ge[8];
    float s = 0.f, s2 = 0.f;
#pragma unroll
    for (int i = 0; i < 8; i++) {
        float v = 0.5f * xs[i] * (1.f + erff(xs[i] * 0.70710678118654752f));
        ge[i] = v; s += v; s2 += v * v;
    }
#pragma unroll
    for (int o = 16; o > 0; o >>= 1) {
        s  += __shfl_xor_sync(0xFFFFFFFFu, s, o);
        s2 += __shfl_xor_sync(0xFFFFFFFFu, s2, o);
    }
    const float mean = s * (1.f / 256.f);
    const float var  = s2 * (1.f / 256.f) - mean * mean;
    const float rstd = rsqrtf(var + 1e-5f);
    float4 g0 = *(const float4*)&g[c0], g1v = *(const float4*)&g[c0 + 4];
    float4 b0 = *(const float4*)&b[c0], b1v = *(const float4*)&b[c0 + 4];
    float gs[8] = {g0.x, g0.y, g0.z, g0.w, g1v.x, g1v.y, g1v.z, g1v.w};
    float bs[8] = {b0.x, b0.y, b0.z, b0.w, b1v.x, b1v.y, b1v.z, b1v.w};
    float4 o0, o1;
    float* op = out + (size_t)row * 256 + c0;
    o0.x = fmaf((ge[0] - mean) * rstd, gs[0], bs[0]);
    o0.y = fmaf((ge[1] - mean) * rstd, gs[1], bs[1]);
    o0.z = fmaf((ge[2] - mean) * rstd, gs[2], bs[2]);
    o0.w = fmaf((ge[3] - mean) * rstd, gs[3], bs[3]);
    o1.x = fmaf((ge[4] - mean) * rstd, gs[4], bs[4]);
    o1.y = fmaf((ge[5] - mean) * rstd, gs[5], bs[5]);
    o1.z = fmaf((ge[6] - mean) * rstd, gs[6], bs[6]);
    o1.w = fmaf((ge[7] - mean) * rstd, gs[7], bs[7]);
    ((float4*)op)[0] = o0;
    ((float4*)op)[1] = o1;
}

// warp-per-row stats of virtual z=[y|obs2] (D=512): mean + rstd
__global__ __launch_bounds__(256)
void ln_stats_warp_kernel(const float* __restrict__ y, const float* __restrict__ o2,
                          float2* __restrict__ stats) {
    const int warp = threadIdx.x >> 5, lane = threadIdx.x & 31;
    const int row = blockIdx.x * 8 + warp;
    const int c0 = lane * 8;
    const float* yp = y  + (size_t)row * 256 + c0;
    const float* op = o2 + (size_t)row * 256 + c0;
    float4 a0 = ((const float4*)yp)[0], a1 = ((const float4*)yp)[1];
    float4 b0 = ((const float4*)op)[0], b1 = ((const float4*)op)[1];
    float s  = a0.x + a0.y + a0.z + a0.w + a1.x + a1.y + a1.z + a1.w
             + b0.x + b0.y + b0.z + b0.w + b1.x + b1.y + b1.z + b1.w;
    float s2 = a0.x*a0.x + a0.y*a0.y + a0.z*a0.z + a0.w*a0.w
             + a1.x*a1.x + a1.y*a1.y + a1.z*a1.z + a1.w*a1.w
             + b0.x*b0.x + b0.y*b0.y + b0.z*b0.z + b0.w*b0.w
             + b1.x*b1.x + b1.y*b1.y + b1.z*b1.z + b1.w*b1.w;
#pragma unroll
    for (int o = 16; o > 0; o >>= 1) {
        s  += __shfl_xor_sync(0xFFFFFFFFu, s, o);
        s2 += __shfl_xor_sync(0xFFFFFFFFu, s2, o);
    }
    if (lane == 0) {
        float mean = s * (1.f / 512.f);
        float var  = s2 * (1.f / 512.f) - mean * mean;
        stats[row] = make_float2(mean, rsqrtf(var + 1e-5f));
    }
}

// ---------------- tensor-core attention: cp.async double-buffer + ldmatrix -----
#define KVS 40          // row stride in bf16 (32 + 8 pad) -> 80 bytes
__global__ __launch_bounds__(128, 3)
void attn_tc_kernel(const __nv_bfloat16* __restrict__ qh, const __nv_bfloat16* __restrict__ ql,
                    const __nv_bfloat16* __restrict__ kh, const __nv_bfloat16* __restrict__ kl,
                    const __nv_bfloat16* __restrict__ vh, const __nv_bfloat16* __restrict__ vl,
                    const unsigned* __restrict__ mbits, float* __restrict__ y) {
    __shared__ __align__(16) __nv_bfloat16 Ks[2][2][32][KVS];
    __shared__ __align__(16) __nv_bfloat16 Vs[2][2][32][KVS];
    __shared__ unsigned Msk[2][128];

    const int b = blockIdx.z, h = blockIdx.y;
    const int qb = blockIdx.x * 128;
    const int tid = threadIdx.x;
    const int warp = tid >> 5, lane = tid & 31;
    const int g = lane >> 2, tg = lane & 3;

    const uint32_t ksBase = smem_u32(&Ks[0][0][0][0]);
    const uint32_t vsBase = smem_u32(&Vs[0][0][0][0]);
    const uint32_t mkBase = smem_u32(&Msk[0][0]);
    const uint32_t planeB = 32 * KVS * 2;

    const int li = lane >> 3, lr = lane & 7;

    uint32_t aqh[2][2][4], aql[2][2][4];
#pragma unroll
    for (int mt = 0; mt < 2; mt++) {
        const int r0 = qb + warp * 32 + mt * 16 + g;
#pragma unroll
        for (int ks = 0; ks < 2; ks++) {
            const size_t base0 = ((size_t)(b * LL + r0)) * DD + h * HD + ks * 16 + 2 * tg;
            const size_t base8 = base0 + 8ull * DD;
            aqh[mt][ks][0] = *(const uint32_t*)&qh[base0];
            aqh[mt][ks][1] = *(const uint32_t*)&qh[base8];
            aqh[mt][ks][2] = *(const uint32_t*)&qh[base0 + 8];
            aqh[mt][ks][3] = *(const uint32_t*)&qh[base8 + 8];
            aql[mt][ks][0] = *(const uint32_t*)&ql[base0];
            aql[mt][ks][1] = *(const uint32_t*)&ql[base8];
            aql[mt][ks][2] = *(const uint32_t*)&ql[base0 + 8];
            aql[mt][ks][3] = *(const uint32_t*)&ql[base8 + 8];
        }
    }

    float co[2][4][4];
#pragma unroll
    for (int mt = 0; mt < 2; mt++)
#pragma unroll
        for (int n = 0; n < 4; n++)
#pragma unroll
            for (int j = 0; j < 4; j++) co[mt][n][j] = 0.f;
    float dn[2][2] = {{0.f,0.f},{0.f,0.f}};

    const int lrow = tid >> 2, lc = tid & 3;

    {
        const size_t src = ((size_t)(b * LL + 0 + lrow)) * DD + h * HD + lc * 8;
        const uint32_t off = (uint32_t)lrow * (KVS * 2) + lc * 16;
        CP_ASYNC16(ksBase + off,              kh + src);
        CP_ASYNC16(ksBase + planeB + off,     kl + src);
        CP_ASYNC16(vsBase + off,              vh + src);
        CP_ASYNC16(vsBase + planeB + off,     vl + src);
        CP_ASYNC4(mkBase + tid * 4, mbits + ((size_t)(b * LL + qb + tid)) * 32 + 0);
        CP_COMMIT();
    }

    const int NT = LL / 32;
    for (int t = 0; t < NT; t++) {
        const int buf = t & 1;
        if (t + 1 < NT) {
            const int nb = (t + 1) & 1;
            const size_t src = ((size_t)(b * LL + (t + 1) * 32 + lrow)) * DD + h * HD + lc * 8;
            const uint32_t off = (uint32_t)(nb * 2) * planeB
                               + (uint32_t)lrow * (KVS * 2) + lc * 16;
            CP_ASYNC16(ksBase + off,          kh + src);
            CP_ASYNC16(ksBase + planeB + off, kl + src);
            CP_ASYNC16(vsBase + off,          vh + src);
            CP_ASYNC16(vsBase + planeB + off, vl + src);
            CP_ASYNC4(mkBase + (nb * 128 + tid) * 4,
                      mbits + ((size_t)(b * LL + qb + tid)) * 32 + t + 1);
            CP_COMMIT();
            CP_WAIT(1);
        } else {
            CP_WAIT(0);
        }
        __syncthreads();

        const uint32_t kB0 = ksBase + (uint32_t)(buf * 2) * planeB;
        const uint32_t kB1 = kB0 + planeB;
        const uint32_t vB0 = vsBase + (uint32_t)(buf * 2) * planeB;
        const uint32_t vB1 = vB0 + planeB;

        uint32_t bKh[2][4][2], bKl[2][4][2];
#pragma unroll
        for (int ks = 0; ks < 2; ks++)
#pragma unroll
            for (int np = 0; np < 2; np++) {
                const uint32_t off = (uint32_t)(np * 16 + ((li >> 1) << 3) + lr) * (KVS * 2)
                                   + (uint32_t)(ks * 16 + ((li & 1) << 3)) * 2;
                ldsm4(bKh[ks][np*2][0], bKh[ks][np*2][1],
                      bKh[ks][np*2+1][0], bKh[ks][np*2+1][1], kB0 + off);
                ldsm4(bKl[ks][np*2][0], bKl[ks][np*2][1],
                      bKl[ks][np*2+1][0], bKl[ks][np*2+1][1], kB1 + off);
            }

        float cs[2][4][4];
#pragma unroll
        for (int mt = 0; mt < 2; mt++)
#pragma unroll
            for (int n = 0; n < 4; n++)
#pragma unroll
                for (int j = 0; j < 4; j++) cs[mt][n][j] = 0.f;
#pragma unroll
        for (int ks = 0; ks < 2; ks++)
#pragma unroll
            for (int mt = 0; mt < 2; mt++)
#pragma unroll
                for (int n = 0; n < 4; n++) {
                    mma_bf16(cs[mt][n], aqh[mt][ks], bKh[ks][n]);
                    mma_bf16(cs[mt][n], aql[mt][ks], bKh[ks][n]);
                    mma_bf16(cs[mt][n], aqh[mt][ks], bKl[ks][n]);
                }

        uint32_t bVh[2][4][2], bVl[2][4][2];
#pragma unroll
        for (int kp = 0; kp < 2; kp++)
#pragma unroll
            for (int np = 0; np < 2; np++) {
                const uint32_t off = (uint32_t)(kp * 16 + ((li & 1) << 3) + lr) * (KVS * 2)
                                   + (uint32_t)(np * 16 + ((li >> 1) << 3)) * 2;
                ldsm4t(bVh[kp][np*2][0], bVh[kp][np*2][1],
                       bVh[kp][np*2+1][0], bVh[kp][np*2+1][1], vB0 + off);
                ldsm4t(bVl[kp][np*2][0], bVl[kp][np*2][1],
                       bVl[kp][np*2+1][0], bVl[kp][np*2+1][1], vB1 + off);
            }

#pragma unroll
        for (int mt = 0; mt < 2; mt++) {
            const int rbase = warp * 32 + mt * 16;
            const unsigned w0 = Msk[buf][rbase + g];
            const unsigned w8 = Msk[buf][rbase + g + 8];
            float pr[4][4];
#pragma unroll
            for (int n = 0; n < 4; n++) {
                const int c0 = n * 8 + 2 * tg;
                const float m00 = (float)((w0 >> c0) & 1u);
                const float m01 = (float)((w0 >> (c0 + 1)) & 1u);
                const float m10 = (float)((w8 >> c0) & 1u);
                const float m11 = (float)((w8 >> (c0 + 1)) & 1u);
                pr[n][0] = fexp(cs[mt][n][0]) * m00;
                pr[n][1] = fexp(cs[mt][n][1]) * m01;
                pr[n][2] = fexp(cs[mt][n][2]) * m10;
                pr[n][3] = fexp(cs[mt][n][3]) * m11;
                dn[mt][0] += pr[n][0] + pr[n][1];
                dn[mt][1] += pr[n][2] + pr[n][3];
            }
#pragma unroll
            for (int kp = 0; kp < 2; kp++) {
                float e00 = pr[kp*2][0], e01 = pr[kp*2][1], e02 = pr[kp*2][2], e03 = pr[kp*2][3];
                float e10 = pr[kp*2+1][0], e11 = pr[kp*2+1][1], e12 = pr[kp*2+1][2], e13 = pr[kp*2+1][3];
                uint32_t pah[4], pal[4];
                pah[0] = hi_pack(e00, e01); pal[0] = lo_pack(e00, e01);
                pah[1] = hi_pack(e02, e03); pal[1] = lo_pack(e02, e03);
                pah[2] = hi_pack(e10, e11); pal[2] = lo_pack(e10, e11);
                pah[3] = hi_pack(e12, e13); pal[3] = lo_pack(e12, e13);
#pragma unroll
                for (int n = 0; n < 4; n++) {
                    mma_bf16(co[mt][n], pah, bVh[kp][n]);
                    mma_bf16(co[mt][n], pal, bVh[kp][n]);
                    mma_bf16(co[mt][n], pah, bVl[kp][n]);
                }
            }
        }
        __syncthreads();
    }

#pragma unroll
    for (int mt = 0; mt < 2; mt++)
#pragma unroll
        for (int rh = 0; rh < 2; rh++) {
            float d = dn[mt][rh];
            d += __shfl_xor_sync(0xFFFFFFFFu, d, 1);
            d += __shfl_xor_sync(0xFFFFFFFFu, d, 2);
            dn[mt][rh] = (d > 0.f) ? 1.0f / d : 0.f;
        }

#pragma unroll
    for (int mt = 0; mt < 2; mt++) {
        const int r0 = qb + warp * 32 + mt * 16 + g;
#pragma unroll
        for (int n = 0; n < 4; n++) {
            const int col = h * HD + n * 8 + 2 * tg;
            *(float2*)&y[((size_t)(b * LL + r0)) * DD + col] =
                make_float2(co[mt][n][0] * dn[mt][0], co[mt][n][1] * dn[mt][0]);
            *(float2*)&y[((size_t)(b * LL + r0 + 8)) * DD + col] =
                make_float2(co[mt][n][2] * dn[mt][1], co[mt][n][3] * dn[mt][1]);
        }
    }
}

// ---------------- launch ------------------------------------------------------
extern "C" void kernel_launch(void* const* d_in, const int* in_sizes, int n_in,
                              void* d_out, int out_size) {
    const float* obs  = (const float*)d_in[0];
    const float* act  = (const float*)d_in[1];
    const int*   msk  = (const int*)  d_in[2];
    const float* Wq   = (const float*)d_in[3];
    const float* bq   = (const float*)d_in[4];
    const float* Wk   = (const float*)d_in[5];
    const float* bk   = (const float*)d_in[6];
    const float* Wv   = (const float*)d_in[7];
    const float* bv   = (const float*)d_in[8];
    const float* Wobs = (const float*)d_in[9];
    const float* bobs = (const float*)d_in[10];
    const float* gob  = (const float*)d_in[11];
    const float* bob  = (const float*)d_in[12];
    const float* g1   = (const float*)d_in[13];
    const float* b1   = (const float*)d_in[14];
    const float* Wp   = (const float*)d_in[15];
    const float* bp   = (const float*)d_in[16];
    const float* g2   = (const float*)d_in[17];
    const float* b2   = (const float*)d_in[18];

    float *obsp, *obs2, *yb, *hb;
    float2* stats;
    unsigned* mb;
    cudaGetSymbolAddress((void**)&obsp,  g_obsp);
    cudaGetSymbolAddress((void**)&obs2,  g_obs2);
    cudaGetSymbolAddress((void**)&yb,    g_y);
    cudaGetSymbolAddress((void**)&hb,    g_h);
    cudaGetSymbolAddress((void**)&stats, g_stats);
    cudaGetSymbolAddress((void**)&mb,    g_mbits);

    __nv_bfloat16 *qh,*ql,*kh,*kl,*vh,*vl;
    cudaGetSymbolAddress((void**)&qh, g_qh); cudaGetSymbolAddress((void**)&ql, g_ql);
    cudaGetSymbolAddress((void**)&kh, g_kh); cudaGetSymbolAddress((void**)&kl, g_kl);
    cudaGetSymbolAddress((void**)&vh, g_vh); cudaGetSymbolAddress((void**)&vl, g_vl);

    pack_mask_kernel<<<dim3(LL, BB), 128>>>(msk, mb);

    // q + obsp merged (A=obs, K=256)
    gemm2_kernel<<<dim3(8, 128), 256>>>(obs, obs, 256, Wq, Wobs, bq, bobs,
                                        nullptr, qh, ql, obsp, nullptr, nullptr,
                                        nullptr, nullptr, nullptr, 256);
    // k + v merged (A=[obs|act], K=512)
    gemm2_kernel<<<dim3(8, 128), 256>>>(obs, act, 256, Wk, Wv, bk, bv,
                                        nullptr, kh, kl, nullptr, vh, vl,
                                        nullptr, nullptr, nullptr, 512);

    gelu_ln_warp_kernel<<<MROWS / 8, 256>>>(obsp, gob, bob, obs2);

    attn_tc_kernel<<<dim3(LL / 128, HH, BB), 128>>>(qh, ql, kh, kl, vh, vl, mb, yb);

    // row stats of z=[y|obs2], then Wp GEMM with fused LayerNorm on A
    ln_stats_warp_kernel<<<MROWS / 8, 256>>>(yb, obs2, stats);
    gemm2_kernel<<<dim3(4, 128), 256>>>(yb, obs2, 256, Wp, Wp, bp, bp,
                                        hb, nullptr, nullptr, hb, nullptr, nullptr,
                                        stats, g1, b1, 512);

    gelu_ln_warp_kernel<<<MROWS / 8, 256>>>(hb, g2, b2, (float*)d_out);
}

// round 14
// speedup vs baseline: 1.2458x; 1.0185x over previous
#include <cuda_runtime.h>
#include <cuda_bf16.h>
#include <math.h>
#include <cstdint>

// Shapes (fixed)
#define BB 8
#define LL 1024
#define DD 256
#define HH 8
#define HD 32
#define MROWS (BB*LL)   // 8192

// ---------------- scratch (device globals) -----------------------------------
__device__ float g_obsp[MROWS * DD];
__device__ float g_obs2[MROWS * DD];
__device__ float g_y   [MROWS * DD];
__device__ float g_h   [MROWS * DD];
__device__ float2 g_stats[MROWS];
__device__ unsigned g_mbits[BB * LL * (LL/32)];

__device__ __nv_bfloat16 g_qh[MROWS * DD], g_ql[MROWS * DD];
__device__ __nv_bfloat16 g_kh[MROWS * DD], g_kl[MROWS * DD];
__device__ __nv_bfloat16 g_vh[MROWS * DD], g_vl[MROWS * DD];

// ---------------- helpers -----------------------------------------------------
__device__ __forceinline__ uint32_t smem_u32(const void* p) {
    return (uint32_t)__cvta_generic_to_shared(p);
}
__device__ __forceinline__ void split1(float x, __nv_bfloat16& h, __nv_bfloat16& l) {
    h = __float2bfloat16(x);
    l = __float2bfloat16(x - __bfloat162float(h));
}
// truncation split: hi = top16 bits (exact), lo = rn_bf16(x - hi); a -> low half
__device__ __forceinline__ uint32_t hi_pack(float a, float b) {
    uint32_t r;
    asm("prmt.b32 %0, %1, %2, 0x7632;" : "=r"(r)
        : "r"(__float_as_int(a)), "r"(__float_as_int(b)));
    return r;
}
__device__ __forceinline__ uint32_t lo_pack(float a, float b) {
    float la = a - __int_as_float(__float_as_int(a) & 0xFFFF0000u);
    float lb = b - __int_as_float(__float_as_int(b) & 0xFFFF0000u);
    uint32_t r;
    asm("cvt.rn.bf16x2.f32 %0, %1, %2;" : "=r"(r) : "f"(lb), "f"(la));
    return r;
}
// fast exp on FMA pipe, degree-4
__device__ __forceinline__ float fexp(float s) {
    const float L2E = 1.4426950408889634f;
    float t  = fmaf(s, L2E, 12582912.0f);
    int   ei = __float_as_int(t) << 23;
    float n  = t - 12582912.0f;
    float f  = fmaf(s, L2E, -n);
    float r  = 9.6181291e-3f;
    r = fmaf(r, f, 5.5504109e-2f);
    r = fmaf(r, f, 2.4022651e-1f);
    r = fmaf(r, f, 6.9314718e-1f);
    r = fmaf(r, f, 1.0f);
    return __int_as_float(__float_as_int(r) + ei);
}

#define CP_ASYNC16(dst, src) \
    asm volatile("cp.async.ca.shared.global [%0], [%1], 16;" :: "r"(dst), "l"(src))
#define CP_ASYNC4(dst, src) \
    asm volatile("cp.async.ca.shared.global [%0], [%1], 4;" :: "r"(dst), "l"(src))
#define CP_COMMIT() asm volatile("cp.async.commit_group;" ::: "memory")
#define CP_WAIT(n)  asm volatile("cp.async.wait_group %0;" :: "n"(n) : "memory")

__device__ __forceinline__ void ldsm4(uint32_t& r0, uint32_t& r1, uint32_t& r2,
                                      uint32_t& r3, uint32_t addr) {
    asm volatile("ldmatrix.sync.aligned.m8n8.x4.shared.b16 {%0,%1,%2,%3},[%4];"
        : "=r"(r0), "=r"(r1), "=r"(r2), "=r"(r3) : "r"(addr));
}
__device__ __forceinline__ void ldsm4t(uint32_t& r0, uint32_t& r1, uint32_t& r2,
                                       uint32_t& r3, uint32_t addr) {
    asm volatile("ldmatrix.sync.aligned.m8n8.x4.trans.shared.b16 {%0,%1,%2,%3},[%4];"
        : "=r"(r0), "=r"(r1), "=r"(r2), "=r"(r3) : "r"(addr));
}

// pack mask (diagonal cleared) into bitwords
__global__ __launch_bounds__(128)
void pack_mask_kernel(const int* __restrict__ mask, unsigned* __restrict__ bits) {
    int b = blockIdx.y, row = blockIdx.x;
    int lane = threadIdx.x & 31, warp = threadIdx.x >> 5;
    const int* mrow = mask + ((size_t)b * LL + row) * LL;
    for (int w = warp; w < 32; w += 4) {
        int col = w * 32 + lane;
        unsigned bit = (unsigned)((mrow[col] != 0) && (col != row));
        unsigned word = __ballot_sync(0xFFFFFFFFu, bit);
        if (lane == 0) bits[((size_t)b * LL + row) * 32 + w] = word;
    }
}

// ---------------- dual-output fused-split GEMM (double-buffered) ---------------
#define APAD 8

__device__ __forceinline__ void mma_bf16(float* c, const uint32_t* a, const uint32_t* b) {
    asm volatile(
        "mma.sync.aligned.m16n8k16.row.col.f32.bf16.bf16.f32 "
        "{%0,%1,%2,%3},{%4,%5,%6,%7},{%8,%9},{%0,%1,%2,%3};"
        : "+f"(c[0]), "+f"(c[1]), "+f"(c[2]), "+f"(c[3])
        : "r"(a[0]), "r"(a[1]), "r"(a[2]), "r"(a[3]), "r"(b[0]), "r"(b[1]));
}

__device__ __forceinline__ void split8s(float4 f0, float4 f1,
                                        __nv_bfloat16* hiDst, __nv_bfloat16* loDst) {
    uint4 hi, lo;
    hi.x = hi_pack(f0.x, f0.y); lo.x = lo_pack(f0.x, f0.y);
    hi.y = hi_pack(f0.z, f0.w); lo.y = lo_pack(f0.z, f0.w);
    hi.z = hi_pack(f1.x, f1.y); lo.z = lo_pack(f1.x, f1.y);
    hi.w = hi_pack(f1.z, f1.w); lo.w = lo_pack(f1.z, f1.w);
    *(uint4*)hiDst = hi;
    *(uint4*)loDst = lo;
}

__global__ __launch_bounds__(256)
void gemm2_kernel(const float* __restrict__ A0, const float* __restrict__ A1, int K0,
                  const float* __restrict__ W0, const float* __restrict__ W1,
                  const float* __restrict__ bias0, const float* __restrict__ bias1,
                  float* __restrict__ C0, __nv_bfloat16* __restrict__ C0h,
                  __nv_bfloat16* __restrict__ C0l,
                  float* __restrict__ C1, __nv_bfloat16* __restrict__ C1h,
                  __nv_bfloat16* __restrict__ C1l,
                  const float2* __restrict__ lnStats,
                  const float* __restrict__ lnG, const float* __restrict__ lnB, int K) {
    __shared__ __nv_bfloat16 Ash[2][64][32 + APAD];
    __shared__ __nv_bfloat16 Asl[2][64][32 + APAD];
    __shared__ __nv_bfloat16 Wsh[2][64][32 + APAD];
    __shared__ __nv_bfloat16 Wsl[2][64][32 + APAD];

    const int tid = threadIdx.x;
    const int bn = blockIdx.x * 64;
    const int bm = blockIdx.y * 64;
    const int wid = tid >> 5, lane = tid & 31;
    const int wm = (wid >> 2) * 32;
    const int wn = (wid & 3) * 16;
    const int g  = lane >> 2;
    const int tg = lane & 3;

    const bool half0 = (bn < 256);
    const float* W    = half0 ? W0 : W1;
    const float* bias = half0 ? bias0 : bias1;
    float* C          = half0 ? C0 : C1;
    __nv_bfloat16* Ch = half0 ? C0h : C1h;
    __nv_bfloat16* Cl = half0 ? C0l : C1l;
    const int cb = bn & 255;

    const int ar = tid >> 2;
    const int ac = tid & 3;

    float2 st = make_float2(0.f, 1.f);
    if (lnStats) st = lnStats[bm + ar];

    float acc[2][2][4];
#pragma unroll
    for (int mt = 0; mt < 2; mt++)
#pragma unroll
        for (int nt = 0; nt < 2; nt++)
#pragma unroll
            for (int j = 0; j < 4; j++) acc[mt][nt][j] = 0.f;

    float4 fa0, fa1, fw0, fw1;
    {
        const float* Ab; int As;
        if (0 < K0) { Ab = A0; As = K0; } else { Ab = A1; As = K - K0; }
        const float* pa = Ab + (size_t)(bm + ar) * As + ac * 8;
        fa0 = ((const float4*)pa)[0]; fa1 = ((const float4*)pa)[1];
        const float* pw = W + (size_t)(cb + ar) * K + ac * 8;
        fw0 = ((const float4*)pw)[0]; fw1 = ((const float4*)pw)[1];
    }

    const int nkb = K / 32;
    for (int kb = 0; kb < nkb; kb++) {
        const int buf = kb & 1;
        // apply fused LN (if any) to block kb regs, then split-store to buf
        if (lnStats) {
            const int kcur = kb * 32 + ac * 8;
            float4 gg0 = *(const float4*)&lnG[kcur];
            float4 gg1 = *(const float4*)&lnG[kcur + 4];
            float4 bb0 = *(const float4*)&lnB[kcur];
            float4 bb1 = *(const float4*)&lnB[kcur + 4];
            fa0.x = fmaf((fa0.x - st.x) * st.y, gg0.x, bb0.x);
            fa0.y = fmaf((fa0.y - st.x) * st.y, gg0.y, bb0.y);
            fa0.z = fmaf((fa0.z - st.x) * st.y, gg0.z, bb0.z);
            fa0.w = fmaf((fa0.w - st.x) * st.y, gg0.w, bb0.w);
            fa1.x = fmaf((fa1.x - st.x) * st.y, gg1.x, bb1.x);
            fa1.y = fmaf((fa1.y - st.x) * st.y, gg1.y, bb1.y);
            fa1.z = fmaf((fa1.z - st.x) * st.y, gg1.z, bb1.z);
            fa1.w = fmaf((fa1.w - st.x) * st.y, gg1.w, bb1.w);
        }
        split8s(fa0, fa1, &Ash[buf][ar][ac * 8], &Asl[buf][ar][ac * 8]);
        split8s(fw0, fw1, &Wsh[buf][ar][ac * 8], &Wsl[buf][ar][ac * 8]);

        // prefetch regs for block kb+1 (consumed at next iteration's store)
        if (kb + 1 < nkb) {
            const int k0 = (kb + 1) * 32;
            const float* Ab; int As;
            if (k0 < K0) { Ab = A0 + k0; As = K0; } else { Ab = A1 + (k0 - K0); As = K - K0; }
            const float* pa = Ab + (size_t)(bm + ar) * As + ac * 8;
            fa0 = ((const float4*)pa)[0]; fa1 = ((const float4*)pa)[1];
            const float* pw = W + (size_t)(cb + ar) * K + k0 + ac * 8;
            fw0 = ((const float4*)pw)[0]; fw1 = ((const float4*)pw)[1];
        }

        __syncthreads();   // single barrier per k-block

#pragma unroll
        for (int ks = 0; ks < 2; ks++) {
            const int kk = ks * 16;
            uint32_t ah[2][4], al[2][4], bh[2][2], bl[2][2];
#pragma unroll
            for (int mt = 0; mt < 2; mt++) {
                const int rb = wm + mt * 16;
                ah[mt][0] = *(const uint32_t*)&Ash[buf][rb + g    ][kk + 2*tg];
                ah[mt][1] = *(const uint32_t*)&Ash[buf][rb + g + 8][kk + 2*tg];
                ah[mt][2] = *(const uint32_t*)&Ash[buf][rb + g    ][kk + 2*tg + 8];
                ah[mt][3] = *(const uint32_t*)&Ash[buf][rb + g + 8][kk + 2*tg + 8];
                al[mt][0] = *(const uint32_t*)&Asl[buf][rb + g    ][kk + 2*tg];
                al[mt][1] = *(const uint32_t*)&Asl[buf][rb + g + 8][kk + 2*tg];
                al[mt][2] = *(const uint32_t*)&Asl[buf][rb + g    ][kk + 2*tg + 8];
                al[mt][3] = *(const uint32_t*)&Asl[buf][rb + g + 8][kk + 2*tg + 8];
            }
#pragma unroll
            for (int nt = 0; nt < 2; nt++) {
                const int nb = wn + nt * 8;
                bh[nt][0] = *(const uint32_t*)&Wsh[buf][nb + g][kk + 2*tg];
                bh[nt][1] = *(const uint32_t*)&Wsh[buf][nb + g][kk + 2*tg + 8];
                bl[nt][0] = *(const uint32_t*)&Wsl[buf][nb + g][kk + 2*tg];
                bl[nt][1] = *(const uint32_t*)&Wsl[buf][nb + g][kk + 2*tg + 8];
            }
#pragma unroll
            for (int mt = 0; mt < 2; mt++)
#pragma unroll
                for (int nt = 0; nt < 2; nt++) {
                    mma_bf16(acc[mt][nt], ah[mt], bh[nt]);
                    mma_bf16(acc[mt][nt], al[mt], bh[nt]);
                    mma_bf16(acc[mt][nt], ah[mt], bl[nt]);
                }
        }
    }

#pragma unroll
    for (int mt = 0; mt < 2; mt++) {
#pragma unroll
        for (int nt = 0; nt < 2; nt++) {
            const int col = cb + wn + nt * 8 + 2 * tg;
            const float bx = bias[col], by = bias[col + 1];
            const int r0 = bm + wm + mt * 16 + g;
            float v0 = acc[mt][nt][0] + bx, v1 = acc[mt][nt][1] + by;
            float v2 = acc[mt][nt][2] + bx, v3 = acc[mt][nt][3] + by;
            if (C) {
                *(float2*)&C[(size_t)r0 * DD + col]       = make_float2(v0, v1);
                *(float2*)&C[(size_t)(r0 + 8) * DD + col] = make_float2(v2, v3);
            } else {
                __nv_bfloat16 h0,l0,h1,l1,h2,l2,h3,l3;
                split1(v0,h0,l0); split1(v1,h1,l1); split1(v2,h2,l2); split1(v3,h3,l3);
                *(__nv_bfloat162*)&Ch[(size_t)r0 * DD + col]       = __halves2bfloat162(h0,h1);
                *(__nv_bfloat162*)&Cl[(size_t)r0 * DD + col]       = __halves2bfloat162(l0,l1);
                *(__nv_bfloat162*)&Ch[(size_t)(r0 + 8) * DD + col] = __halves2bfloat162(h2,h3);
                *(__nv_bfloat162*)&Cl[(size_t)(r0 + 8) * DD + col] = __halves2bfloat162(l2,l3);
            }
        }
    }
}

// ---------------- warp-per-row gelu (exact) + LayerNorm (D=256) ----------------
__global__ __launch_bounds__(256)
void gelu_ln_warp_kernel(const float* __restrict__ in, const float* __restrict__ g,
                         const float* __restrict__ b, float* __restrict__ out) {
    const int warp = threadIdx.x >> 5, lane = threadIdx.x & 31;
    const int row = blockIdx.x * 8 + warp;
    const int c0 = lane * 8;
    const float* ip = in + (size_t)row * 256 + c0;
    float4 x0 = ((const float4*)ip)[0];
    float4 x1 = ((const float4*)ip)[1];
    float xs[8] = {x0.x, x0.y, x0.z, x0.w, x1.x, x1.y, x1.z, x1.w};
    float ge[8];
    float s = 0.f, s2 = 0.f;
#pragma unroll
    for (int i = 0; i < 8; i++) {
        float v = 0.5f * xs[i] * (1.f + erff(xs[i] * 0.70710678118654752f));
        ge[i] = v; s += v; s2 += v * v;
    }
#pragma unroll
    for (int o = 16; o > 0; o >>= 1) {
        s  += __shfl_xor_sync(0xFFFFFFFFu, s, o);
        s2 += __shfl_xor_sync(0xFFFFFFFFu, s2, o);
    }
    const float mean = s * (1.f / 256.f);
    const float var  = s2 * (1.f / 256.f) - mean * mean;
    const float rstd = rsqrtf(var + 1e-5f);
    float4 g0 = *(const float4*)&g[c0], g1v = *(const float4*)&g[c0 + 4];
    float4 b0 = *(const float4*)&b[c0], b1v = *(const float4*)&b[c0 + 4];
    float gs[8] = {g0.x, g0.y, g0.z, g0.w, g1v.x, g1v.y, g1v.z, g1v.w};
    float bs[8] = {b0.x, b0.y, b0.z, b0.w, b1v.x, b1v.y, b1v.z, b1v.w};
    float4 o0, o1;
    float* op = out + (size_t)row * 256 + c0;
    o0.x = fmaf((ge[0] - mean) * rstd, gs[0], bs[0]);
    o0.y = fmaf((ge[1] - mean) * rstd, gs[1], bs[1]);
    o0.z = fmaf((ge[2] - mean) * rstd, gs[2], bs[2]);
    o0.w = fmaf((ge[3] - mean) * rstd, gs[3], bs[3]);
    o1.x = fmaf((ge[4] - mean) * rstd, gs[4], bs[4]);
    o1.y = fmaf((ge[5] - mean) * rstd, gs[5], bs[5]);
    o1.z = fmaf((ge[6] - mean) * rstd, gs[6], bs[6]);
    o1.w = fmaf((ge[7] - mean) * rstd, gs[7], bs[7]);
    ((float4*)op)[0] = o0;
    ((float4*)op)[1] = o1;
}

// warp-per-row stats of virtual z=[y|obs2] (D=512): mean + rstd
__global__ __launch_bounds__(256)
void ln_stats_warp_kernel(const float* __restrict__ y, const float* __restrict__ o2,
                          float2* __restrict__ stats) {
    const int warp = threadIdx.x >> 5, lane = threadIdx.x & 31;
    const int row = blockIdx.x * 8 + warp;
    const int c0 = lane * 8;
    const float* yp = y  + (size_t)row * 256 + c0;
    const float* op = o2 + (size_t)row * 256 + c0;
    float4 a0 = ((const float4*)yp)[0], a1 = ((const float4*)yp)[1];
    float4 b0 = ((const float4*)op)[0], b1 = ((const float4*)op)[1];
    float s  = a0.x + a0.y + a0.z + a0.w + a1.x + a1.y + a1.z + a1.w
             + b0.x + b0.y + b0.z + b0.w + b1.x + b1.y + b1.z + b1.w;
    float s2 = a0.x*a0.x + a0.y*a0.y + a0.z*a0.z + a0.w*a0.w
             + a1.x*a1.x + a1.y*a1.y + a1.z*a1.z + a1.w*a1.w
             + b0.x*b0.x + b0.y*b0.y + b0.z*b0.z + b0.w*b0.w
             + b1.x*b1.x + b1.y*b1.y + b1.z*b1.z + b1.w*b1.w;
#pragma unroll
    for (int o = 16; o > 0; o >>= 1) {
        s  += __shfl_xor_sync(0xFFFFFFFFu, s, o);
        s2 += __shfl_xor_sync(0xFFFFFFFFu, s2, o);
    }
    if (lane == 0) {
        float mean = s * (1.f / 512.f);
        float var  = s2 * (1.f / 512.f) - mean * mean;
        stats[row] = make_float2(mean, rsqrtf(var + 1e-5f));
    }
}

// ---------------- tensor-core attention: cp.async double-buffer + ldmatrix -----
#define KVS 40          // row stride in bf16 (32 + 8 pad) -> 80 bytes
__global__ __launch_bounds__(128, 3)
void attn_tc_kernel(const __nv_bfloat16* __restrict__ qh, const __nv_bfloat16* __restrict__ ql,
                    const __nv_bfloat16* __restrict__ kh, const __nv_bfloat16* __restrict__ kl,
                    const __nv_bfloat16* __restrict__ vh, const __nv_bfloat16* __restrict__ vl,
                    const unsigned* __restrict__ mbits, float* __restrict__ y) {
    __shared__ __align__(16) __nv_bfloat16 Ks[2][2][32][KVS];
    __shared__ __align__(16) __nv_bfloat16 Vs[2][2][32][KVS];
    __shared__ unsigned Msk[2][128];

    const int b = blockIdx.z, h = blockIdx.y;
    const int qb = blockIdx.x * 128;
    const int tid = threadIdx.x;
    const int warp = tid >> 5, lane = tid & 31;
    const int g = lane >> 2, tg = lane & 3;

    const uint32_t ksBase = smem_u32(&Ks[0][0][0][0]);
    const uint32_t vsBase = smem_u32(&Vs[0][0][0][0]);
    const uint32_t mkBase = smem_u32(&Msk[0][0]);
    const uint32_t planeB = 32 * KVS * 2;

    const int li = lane >> 3, lr = lane & 7;

    uint32_t aqh[2][2][4], aql[2][2][4];
#pragma unroll
    for (int mt = 0; mt < 2; mt++) {
        const int r0 = qb + warp * 32 + mt * 16 + g;
#pragma unroll
        for (int ks = 0; ks < 2; ks++) {
            const size_t base0 = ((size_t)(b * LL + r0)) * DD + h * HD + ks * 16 + 2 * tg;
            const size_t base8 = base0 + 8ull * DD;
            aqh[mt][ks][0] = *(const uint32_t*)&qh[base0];
            aqh[mt][ks][1] = *(const uint32_t*)&qh[base8];
            aqh[mt][ks][2] = *(const uint32_t*)&qh[base0 + 8];
            aqh[mt][ks][3] = *(const uint32_t*)&qh[base8 + 8];
            aql[mt][ks][0] = *(const uint32_t*)&ql[base0];
            aql[mt][ks][1] = *(const uint32_t*)&ql[base8];
            aql[mt][ks][2] = *(const uint32_t*)&ql[base0 + 8];
            aql[mt][ks][3] = *(const uint32_t*)&ql[base8 + 8];
        }
    }

    float co[2][4][4];
#pragma unroll
    for (int mt = 0; mt < 2; mt++)
#pragma unroll
        for (int n = 0; n < 4; n++)
#pragma unroll
            for (int j = 0; j < 4; j++) co[mt][n][j] = 0.f;
    float dn[2][2] = {{0.f,0.f},{0.f,0.f}};

    const int lrow = tid >> 2, lc = tid & 3;

    {
        const size_t src = ((size_t)(b * LL + 0 + lrow)) * DD + h * HD + lc * 8;
        const uint32_t off = (uint32_t)lrow * (KVS * 2) + lc * 16;
        CP_ASYNC16(ksBase + off,              kh + src);
        CP_ASYNC16(ksBase + planeB + off,     kl + src);
        CP_ASYNC16(vsBase + off,              vh + src);
        CP_ASYNC16(vsBase + planeB + off,     vl + src);
        CP_ASYNC4(mkBase + tid * 4, mbits + ((size_t)(b * LL + qb + tid)) * 32 + 0);
        CP_COMMIT();
    }

    const int NT = LL / 32;
    for (int t = 0; t < NT; t++) {
        const int buf = t & 1;
        if (t + 1 < NT) {
            const int nb = (t + 1) & 1;
            const size_t src = ((size_t)(b * LL + (t + 1) * 32 + lrow)) * DD + h * HD + lc * 8;
            const uint32_t off = (uint32_t)(nb * 2) * planeB
                               + (uint32_t)lrow * (KVS * 2) + lc * 16;
            CP_ASYNC16(ksBase + off,          kh + src);
            CP_ASYNC16(ksBase + planeB + off, kl + src);
            CP_ASYNC16(vsBase + off,          vh + src);
            CP_ASYNC16(vsBase + planeB + off, vl + src);
            CP_ASYNC4(mkBase + (nb * 128 + tid) * 4,
                      mbits + ((size_t)(b * LL + qb + tid)) * 32 + t + 1);
            CP_COMMIT();
            CP_WAIT(1);
        } else {
            CP_WAIT(0);
        }
        __syncthreads();

        const uint32_t kB0 = ksBase + (uint32_t)(buf * 2) * planeB;
        const uint32_t kB1 = kB0 + planeB;
        const uint32_t vB0 = vsBase + (uint32_t)(buf * 2) * planeB;
        const uint32_t vB1 = vB0 + planeB;

        uint32_t bKh[2][4][2], bKl[2][4][2];
#pragma unroll
        for (int ks = 0; ks < 2; ks++)
#pragma unroll
            for (int np = 0; np < 2; np++) {
                const uint32_t off = (uint32_t)(np * 16 + ((li >> 1) << 3) + lr) * (KVS * 2)
                                   + (uint32_t)(ks * 16 + ((li & 1) << 3)) * 2;
                ldsm4(bKh[ks][np*2][0], bKh[ks][np*2][1],
                      bKh[ks][np*2+1][0], bKh[ks][np*2+1][1], kB0 + off);
                ldsm4(bKl[ks][np*2][0], bKl[ks][np*2][1],
                      bKl[ks][np*2+1][0], bKl[ks][np*2+1][1], kB1 + off);
            }

        float cs[2][4][4];
#pragma unroll
        for (int mt = 0; mt < 2; mt++)
#pragma unroll
            for (int n = 0; n < 4; n++)
#pragma unroll
                for (int j = 0; j < 4; j++) cs[mt][n][j] = 0.f;
#pragma unroll
        for (int ks = 0; ks < 2; ks++)
#pragma unroll
            for (int mt = 0; mt < 2; mt++)
#pragma unroll
                for (int n = 0; n < 4; n++) {
                    mma_bf16(cs[mt][n], aqh[mt][ks], bKh[ks][n]);
                    mma_bf16(cs[mt][n], aql[mt][ks], bKh[ks][n]);
                    mma_bf16(cs[mt][n], aqh[mt][ks], bKl[ks][n]);
                }

        uint32_t bVh[2][4][2], bVl[2][4][2];
#pragma unroll
        for (int kp = 0; kp < 2; kp++)
#pragma unroll
            for (int np = 0; np < 2; np++) {
                const uint32_t off = (uint32_t)(kp * 16 + ((li & 1) << 3) + lr) * (KVS * 2)
                                   + (uint32_t)(np * 16 + ((li >> 1) << 3)) * 2;
                ldsm4t(bVh[kp][np*2][0], bVh[kp][np*2][1],
                       bVh[kp][np*2+1][0], bVh[kp][np*2+1][1], vB0 + off);
                ldsm4t(bVl[kp][np*2][0], bVl[kp][np*2][1],
                       bVl[kp][np*2+1][0], bVl[kp][np*2+1][1], vB1 + off);
            }

#pragma unroll
        for (int mt = 0; mt < 2; mt++) {
            const int rbase = warp * 32 + mt * 16;
            const unsigned w0 = Msk[buf][rbase + g];
            const unsigned w8 = Msk[buf][rbase + g + 8];
            float pr[4][4];
#pragma unroll
            for (int n = 0; n < 4; n++) {
                const int c0 = n * 8 + 2 * tg;
                const float m00 = (float)((w0 >> c0) & 1u);
                const float m01 = (float)((w0 >> (c0 + 1)) & 1u);
                const float m10 = (float)((w8 >> c0) & 1u);
                const float m11 = (float)((w8 >> (c0 + 1)) & 1u);
                pr[n][0] = fexp(cs[mt][n][0]) * m00;
                pr[n][1] = fexp(cs[mt][n][1]) * m01;
                pr[n][2] = fexp(cs[mt][n][2]) * m10;
                pr[n][3] = fexp(cs[mt][n][3]) * m11;
                dn[mt][0] += pr[n][0] + pr[n][1];
                dn[mt][1] += pr[n][2] + pr[n][3];
            }
#pragma unroll
            for (int kp = 0; kp < 2; kp++) {
                float e00 = pr[kp*2][0], e01 = pr[kp*2][1], e02 = pr[kp*2][2], e03 = pr[kp*2][3];
                float e10 = pr[kp*2+1][0], e11 = pr[kp*2+1][1], e12 = pr[kp*2+1][2], e13 = pr[kp*2+1][3];
                uint32_t pah[4], pal[4];
                pah[0] = hi_pack(e00, e01); pal[0] = lo_pack(e00, e01);
                pah[1] = hi_pack(e02, e03); pal[1] = lo_pack(e02, e03);
                pah[2] = hi_pack(e10, e11); pal[2] = lo_pack(e10, e11);
                pah[3] = hi_pack(e12, e13); pal[3] = lo_pack(e12, e13);
#pragma unroll
                for (int n = 0; n < 4; n++) {
                    mma_bf16(co[mt][n], pah, bVh[kp][n]);
                    mma_bf16(co[mt][n], pal, bVh[kp][n]);
                    mma_bf16(co[mt][n], pah, bVl[kp][n]);
                }
            }
        }
        __syncthreads();
    }

#pragma unroll
    for (int mt = 0; mt < 2; mt++)
#pragma unroll
        for (int rh = 0; rh < 2; rh++) {
            float d = dn[mt][rh];
            d += __shfl_xor_sync(0xFFFFFFFFu, d, 1);
            d += __shfl_xor_sync(0xFFFFFFFFu, d, 2);
            dn[mt][rh] = (d > 0.f) ? 1.0f / d : 0.f;
        }

#pragma unroll
    for (int mt = 0; mt < 2; mt++) {
        const int r0 = qb + warp * 32 + mt * 16 + g;
#pragma unroll
        for (int n = 0; n < 4; n++) {
            const int col = h * HD + n * 8 + 2 * tg;
            *(float2*)&y[((size_t)(b * LL + r0)) * DD + col] =
                make_float2(co[mt][n][0] * dn[mt][0], co[mt][n][1] * dn[mt][0]);
            *(float2*)&y[((size_t)(b * LL + r0 + 8)) * DD + col] =
                make_float2(co[mt][n][2] * dn[mt][1], co[mt][n][3] * dn[mt][1]);
        }
    }
}

// ---------------- launch ------------------------------------------------------
extern "C" void kernel_launch(void* const* d_in, const int* in_sizes, int n_in,
                              void* d_out, int out_size) {
    const float* obs  = (const float*)d_in[0];
    const float* act  = (const float*)d_in[1];
    const int*   msk  = (const int*)  d_in[2];
    const float* Wq   = (const float*)d_in[3];
    const float* bq   = (const float*)d_in[4];
    const float* Wk   = (const float*)d_in[5];
    const float* bk   = (const float*)d_in[6];
    const float* Wv   = (const float*)d_in[7];
    const float* bv   = (const float*)d_in[8];
    const float* Wobs = (const float*)d_in[9];
    const float* bobs = (const float*)d_in[10];
    const float* gob  = (const float*)d_in[11];
    const float* bob  = (const float*)d_in[12];
    const float* g1   = (const float*)d_in[13];
    const float* b1   = (const float*)d_in[14];
    const float* Wp   = (const float*)d_in[15];
    const float* bp   = (const float*)d_in[16];
    const float* g2   = (const float*)d_in[17];
    const float* b2   = (const float*)d_in[18];

    float *obsp, *obs2, *yb, *hb;
    float2* stats;
    unsigned* mb;
    cudaGetSymbolAddress((void**)&obsp,  g_obsp);
    cudaGetSymbolAddress((void**)&obs2,  g_obs2);
    cudaGetSymbolAddress((void**)&yb,    g_y);
    cudaGetSymbolAddress((void**)&hb,    g_h);
    cudaGetSymbolAddress((void**)&stats, g_stats);
    cudaGetSymbolAddress((void**)&mb,    g_mbits);

    __nv_bfloat16 *qh,*ql,*kh,*kl,*vh,*vl;
    cudaGetSymbolAddress((void**)&qh, g_qh); cudaGetSymbolAddress((void**)&ql, g_ql);
    cudaGetSymbolAddress((void**)&kh, g_kh); cudaGetSymbolAddress((void**)&kl, g_kl);
    cudaGetSymbolAddress((void**)&vh, g_vh); cudaGetSymbolAddress((void**)&vl, g_vl);

    pack_mask_kernel<<<dim3(LL, BB), 128>>>(msk, mb);

    // q + obsp merged (A=obs, K=256)
    gemm2_kernel<<<dim3(8, 128), 256>>>(obs, obs, 256, Wq, Wobs, bq, bobs,
                                        nullptr, qh, ql, obsp, nullptr, nullptr,
                                        nullptr, nullptr, nullptr, 256);
    // k + v merged (A=[obs|act], K=512)
    gemm2_kernel<<<dim3(8, 128), 256>>>(obs, act, 256, Wk, Wv, bk, bv,
                                        nullptr, kh, kl, nullptr, vh, vl,
                                        nullptr, nullptr, nullptr, 512);

    gelu_ln_warp_kernel<<<MROWS / 8, 256>>>(obsp, gob, bob, obs2);

    attn_tc_kernel<<<dim3(LL / 128, HH, BB), 128>>>(qh, ql, kh, kl, vh, vl, mb, yb);

    // row stats of z=[y|obs2], then Wp GEMM with fused LayerNorm on A
    ln_stats_warp_kernel<<<MROWS / 8, 256>>>(yb, obs2, stats);
    gemm2_kernel<<<dim3(4, 128), 256>>>(yb, obs2, 256, Wp, Wp, bp, bp,
                                        hb, nullptr, nullptr, hb, nullptr, nullptr,
                                        stats, g1, b1, 512);

    gelu_ln_warp_kernel<<<MROWS / 8, 256>>>(hb, g2, b2, (float*)d_out);
}

// round 15
// speedup vs baseline: 1.2590x; 1.0106x over previous
#include <cuda_runtime.h>
#include <cuda_bf16.h>
#include <math.h>
#include <cstdint>

// Shapes (fixed)
#define BB 8
#define LL 1024
#define DD 256
#define HH 8
#define HD 32
#define MROWS (BB*LL)   // 8192

// ---------------- scratch (device globals) -----------------------------------
__device__ float g_obs2[MROWS * DD];
__device__ float g_y   [MROWS * DD];
__device__ float2 g_stats[MROWS];
__device__ unsigned g_mbits[BB * LL * (LL/32)];

__device__ __nv_bfloat16 g_qh[MROWS * DD], g_ql[MROWS * DD];
__device__ __nv_bfloat16 g_kh[MROWS * DD], g_kl[MROWS * DD];
__device__ __nv_bfloat16 g_vh[MROWS * DD], g_vl[MROWS * DD];

// ---------------- helpers -----------------------------------------------------
__device__ __forceinline__ uint32_t smem_u32(const void* p) {
    return (uint32_t)__cvta_generic_to_shared(p);
}
__device__ __forceinline__ void split1(float x, __nv_bfloat16& h, __nv_bfloat16& l) {
    h = __float2bfloat16(x);
    l = __float2bfloat16(x - __bfloat162float(h));
}
// truncation split: hi = top16 bits (exact), lo = rn_bf16(x - hi); a -> low half
__device__ __forceinline__ uint32_t hi_pack(float a, float b) {
    uint32_t r;
    asm("prmt.b32 %0, %1, %2, 0x7632;" : "=r"(r)
        : "r"(__float_as_int(a)), "r"(__float_as_int(b)));
    return r;
}
__device__ __forceinline__ uint32_t lo_pack(float a, float b) {
    float la = a - __int_as_float(__float_as_int(a) & 0xFFFF0000u);
    float lb = b - __int_as_float(__float_as_int(b) & 0xFFFF0000u);
    uint32_t r;
    asm("cvt.rn.bf16x2.f32 %0, %1, %2;" : "=r"(r) : "f"(lb), "f"(la));
    return r;
}
// fast exp on FMA pipe, degree-4
__device__ __forceinline__ float fexp(float s) {
    const float L2E = 1.4426950408889634f;
    float t  = fmaf(s, L2E, 12582912.0f);
    int   ei = __float_as_int(t) << 23;
    float n  = t - 12582912.0f;
    float f  = fmaf(s, L2E, -n);
    float r  = 9.6181291e-3f;
    r = fmaf(r, f, 5.5504109e-2f);
    r = fmaf(r, f, 2.4022651e-1f);
    r = fmaf(r, f, 6.9314718e-1f);
    r = fmaf(r, f, 1.0f);
    return __int_as_float(__float_as_int(r) + ei);
}

#define CP_ASYNC16(dst, src) \
    asm volatile("cp.async.ca.shared.global [%0], [%1], 16;" :: "r"(dst), "l"(src))
#define CP_ASYNC4(dst, src) \
    asm volatile("cp.async.ca.shared.global [%0], [%1], 4;" :: "r"(dst), "l"(src))
#define CP_COMMIT() asm volatile("cp.async.commit_group;" ::: "memory")
#define CP_WAIT(n)  asm volatile("cp.async.wait_group %0;" :: "n"(n) : "memory")

__device__ __forceinline__ void ldsm4(uint32_t& r0, uint32_t& r1, uint32_t& r2,
                                      uint32_t& r3, uint32_t addr) {
    asm volatile("ldmatrix.sync.aligned.m8n8.x4.shared.b16 {%0,%1,%2,%3},[%4];"
        : "=r"(r0), "=r"(r1), "=r"(r2), "=r"(r3) : "r"(addr));
}
__device__ __forceinline__ void ldsm4t(uint32_t& r0, uint32_t& r1, uint32_t& r2,
                                       uint32_t& r3, uint32_t addr) {
    asm volatile("ldmatrix.sync.aligned.m8n8.x4.trans.shared.b16 {%0,%1,%2,%3},[%4];"
        : "=r"(r0), "=r"(r1), "=r"(r2), "=r"(r3) : "r"(addr));
}

// pack mask (diagonal cleared) into bitwords
__global__ __launch_bounds__(128)
void pack_mask_kernel(const int* __restrict__ mask, unsigned* __restrict__ bits) {
    int b = blockIdx.y, row = blockIdx.x;
    int lane = threadIdx.x & 31, warp = threadIdx.x >> 5;
    const int* mrow = mask + ((size_t)b * LL + row) * LL;
    for (int w = warp; w < 32; w += 4) {
        int col = w * 32 + lane;
        unsigned bit = (unsigned)((mrow[col] != 0) && (col != row));
        unsigned word = __ballot_sync(0xFFFFFFFFu, bit);
        if (lane == 0) bits[((size_t)b * LL + row) * 32 + w] = word;
    }
}

// ---------------- shared GEMM pieces -------------------------------------------
#define APAD 8

__device__ __forceinline__ void mma_bf16(float* c, const uint32_t* a, const uint32_t* b) {
    asm volatile(
        "mma.sync.aligned.m16n8k16.row.col.f32.bf16.bf16.f32 "
        "{%0,%1,%2,%3},{%4,%5,%6,%7},{%8,%9},{%0,%1,%2,%3};"
        : "+f"(c[0]), "+f"(c[1]), "+f"(c[2]), "+f"(c[3])
        : "r"(a[0]), "r"(a[1]), "r"(a[2]), "r"(a[3]), "r"(b[0]), "r"(b[1]));
}

__device__ __forceinline__ void split8s(float4 f0, float4 f1,
                                        __nv_bfloat16* hiDst, __nv_bfloat16* loDst) {
    uint4 hi, lo;
    hi.x = hi_pack(f0.x, f0.y); lo.x = lo_pack(f0.x, f0.y);
    hi.y = hi_pack(f0.z, f0.w); lo.y = lo_pack(f0.z, f0.w);
    hi.z = hi_pack(f1.x, f1.y); lo.z = lo_pack(f1.x, f1.y);
    hi.w = hi_pack(f1.z, f1.w); lo.w = lo_pack(f1.z, f1.w);
    *(uint4*)hiDst = hi;
    *(uint4*)loDst = lo;
}

// ---------------- dual-output fused-split GEMM (double-buffered) ---------------
__global__ __launch_bounds__(256)
void gemm2_kernel(const float* __restrict__ A0, const float* __restrict__ A1, int K0,
                  const float* __restrict__ W0, const float* __restrict__ W1,
                  const float* __restrict__ bias0, const float* __restrict__ bias1,
                  __nv_bfloat16* __restrict__ C0h, __nv_bfloat16* __restrict__ C0l,
                  __nv_bfloat16* __restrict__ C1h, __nv_bfloat16* __restrict__ C1l,
                  int K) {
    __shared__ __nv_bfloat16 Ash[2][64][32 + APAD];
    __shared__ __nv_bfloat16 Asl[2][64][32 + APAD];
    __shared__ __nv_bfloat16 Wsh[2][64][32 + APAD];
    __shared__ __nv_bfloat16 Wsl[2][64][32 + APAD];

    const int tid = threadIdx.x;
    const int bn = blockIdx.x * 64;
    const int bm = blockIdx.y * 64;
    const int wid = tid >> 5, lane = tid & 31;
    const int wm = (wid >> 2) * 32;
    const int wn = (wid & 3) * 16;
    const int g  = lane >> 2;
    const int tg = lane & 3;

    const bool half0 = (bn < 256);
    const float* W    = half0 ? W0 : W1;
    const float* bias = half0 ? bias0 : bias1;
    __nv_bfloat16* Ch = half0 ? C0h : C1h;
    __nv_bfloat16* Cl = half0 ? C0l : C1l;
    const int cb = bn & 255;

    const int ar = tid >> 2;
    const int ac = tid & 3;

    float acc[2][2][4];
#pragma unroll
    for (int mt = 0; mt < 2; mt++)
#pragma unroll
        for (int nt = 0; nt < 2; nt++)
#pragma unroll
            for (int j = 0; j < 4; j++) acc[mt][nt][j] = 0.f;

    float4 fa0, fa1, fw0, fw1;
    {
        const float* Ab; int As;
        if (0 < K0) { Ab = A0; As = K0; } else { Ab = A1; As = K - K0; }
        const float* pa = Ab + (size_t)(bm + ar) * As + ac * 8;
        fa0 = ((const float4*)pa)[0]; fa1 = ((const float4*)pa)[1];
        const float* pw = W + (size_t)(cb + ar) * K + ac * 8;
        fw0 = ((const float4*)pw)[0]; fw1 = ((const float4*)pw)[1];
    }

    const int nkb = K / 32;
    for (int kb = 0; kb < nkb; kb++) {
        const int buf = kb & 1;
        split8s(fa0, fa1, &Ash[buf][ar][ac * 8], &Asl[buf][ar][ac * 8]);
        split8s(fw0, fw1, &Wsh[buf][ar][ac * 8], &Wsl[buf][ar][ac * 8]);

        if (kb + 1 < nkb) {
            const int k0 = (kb + 1) * 32;
            const float* Ab; int As;
            if (k0 < K0) { Ab = A0 + k0; As = K0; } else { Ab = A1 + (k0 - K0); As = K - K0; }
            const float* pa = Ab + (size_t)(bm + ar) * As + ac * 8;
            fa0 = ((const float4*)pa)[0]; fa1 = ((const float4*)pa)[1];
            const float* pw = W + (size_t)(cb + ar) * K + k0 + ac * 8;
            fw0 = ((const float4*)pw)[0]; fw1 = ((const float4*)pw)[1];
        }

        __syncthreads();

#pragma unroll
        for (int ks = 0; ks < 2; ks++) {
            const int kk = ks * 16;
            uint32_t ah[2][4], al[2][4], bh[2][2], bl[2][2];
#pragma unroll
            for (int mt = 0; mt < 2; mt++) {
                const int rb = wm + mt * 16;
                ah[mt][0] = *(const uint32_t*)&Ash[buf][rb + g    ][kk + 2*tg];
                ah[mt][1] = *(const uint32_t*)&Ash[buf][rb + g + 8][kk + 2*tg];
                ah[mt][2] = *(const uint32_t*)&Ash[buf][rb + g    ][kk + 2*tg + 8];
                ah[mt][3] = *(const uint32_t*)&Ash[buf][rb + g + 8][kk + 2*tg + 8];
                al[mt][0] = *(const uint32_t*)&Asl[buf][rb + g    ][kk + 2*tg];
                al[mt][1] = *(const uint32_t*)&Asl[buf][rb + g + 8][kk + 2*tg];
                al[mt][2] = *(const uint32_t*)&Asl[buf][rb + g    ][kk + 2*tg + 8];
                al[mt][3] = *(const uint32_t*)&Asl[buf][rb + g + 8][kk + 2*tg + 8];
            }
#pragma unroll
            for (int nt = 0; nt < 2; nt++) {
                const int nb = wn + nt * 8;
                bh[nt][0] = *(const uint32_t*)&Wsh[buf][nb + g][kk + 2*tg];
                bh[nt][1] = *(const uint32_t*)&Wsh[buf][nb + g][kk + 2*tg + 8];
                bl[nt][0] = *(const uint32_t*)&Wsl[buf][nb + g][kk + 2*tg];
                bl[nt][1] = *(const uint32_t*)&Wsl[buf][nb + g][kk + 2*tg + 8];
            }
#pragma unroll
            for (int mt = 0; mt < 2; mt++)
#pragma unroll
                for (int nt = 0; nt < 2; nt++) {
                    mma_bf16(acc[mt][nt], ah[mt], bh[nt]);
                    mma_bf16(acc[mt][nt], al[mt], bh[nt]);
                    mma_bf16(acc[mt][nt], ah[mt], bl[nt]);
                }
        }
    }

#pragma unroll
    for (int mt = 0; mt < 2; mt++) {
#pragma unroll
        for (int nt = 0; nt < 2; nt++) {
            const int col = cb + wn + nt * 8 + 2 * tg;
            const float bx = bias[col], by = bias[col + 1];
            const int r0 = bm + wm + mt * 16 + g;
            float v0 = acc[mt][nt][0] + bx, v1 = acc[mt][nt][1] + by;
            float v2 = acc[mt][nt][2] + bx, v3 = acc[mt][nt][3] + by;
            __nv_bfloat16 h0,l0,h1,l1,h2,l2,h3,l3;
            split1(v0,h0,l0); split1(v1,h1,l1); split1(v2,h2,l2); split1(v3,h3,l3);
            *(__nv_bfloat162*)&Ch[(size_t)r0 * DD + col]       = __halves2bfloat162(h0,h1);
            *(__nv_bfloat162*)&Cl[(size_t)r0 * DD + col]       = __halves2bfloat162(l0,l1);
            *(__nv_bfloat162*)&Ch[(size_t)(r0 + 8) * DD + col] = __halves2bfloat162(h2,h3);
            *(__nv_bfloat162*)&Cl[(size_t)(r0 + 8) * DD + col] = __halves2bfloat162(l2,l3);
        }
    }
}

// ---------------- fused GEMM -> gelu -> LayerNorm ------------------------------
// out[r, 0:256] = LN(gelu(A[r] @ W^T + bias)) with optional pre-LN on A (stats).
// CTA: M=32, N=256 (full rows). 256 thr, warp w owns cols [w*32, w*32+32).
__global__ __launch_bounds__(256)
void gemm_gelu_ln_kernel(const float* __restrict__ A0, const float* __restrict__ A1, int K0,
                         const float* __restrict__ W, const float* __restrict__ bias,
                         const float2* __restrict__ lnStats,
                         const float* __restrict__ lnG, const float* __restrict__ lnB,
                         const float* __restrict__ g2, const float* __restrict__ b2,
                         float* __restrict__ out, int K) {
    __shared__ __nv_bfloat16 Ash[32][32 + APAD];
    __shared__ __nv_bfloat16 Asl[32][32 + APAD];
    __shared__ __nv_bfloat16 Wsh[256][32 + APAD];
    __shared__ __nv_bfloat16 Wsl[256][32 + APAD];
    __shared__ float red[8][32][2];
    __shared__ float fin[32][2];

    const int tid = threadIdx.x;
    const int bm = blockIdx.x * 32;
    const int warp = tid >> 5, lane = tid & 31;
    const int wn = warp * 32;
    const int g  = lane >> 2;
    const int tg = lane & 3;

    const int ar = tid >> 2, ac = tid & 3;   // A loader (tid<128)
    float2 st = make_float2(0.f, 1.f);
    if (lnStats && tid < 128) st = lnStats[bm + ar];

    float acc[2][4][4];
#pragma unroll
    for (int mt = 0; mt < 2; mt++)
#pragma unroll
        for (int nt = 0; nt < 4; nt++)
#pragma unroll
            for (int j = 0; j < 4; j++) acc[mt][nt][j] = 0.f;

    // prefetch regs
    float4 fa0, fa1, fw[4][2];
    {
        const float* Ab; int As;
        if (0 < K0) { Ab = A0; As = K0; } else { Ab = A1; As = K - K0; }
        if (tid < 128) {
            const float* pa = Ab + (size_t)(bm + ar) * As + ac * 8;
            fa0 = ((const float4*)pa)[0]; fa1 = ((const float4*)pa)[1];
        }
#pragma unroll
        for (int i = 0; i < 4; i++) {
            const int ch = i * 256 + tid;
            const float* pw = W + (size_t)(ch >> 2) * K + (ch & 3) * 8;
            fw[i][0] = ((const float4*)pw)[0]; fw[i][1] = ((const float4*)pw)[1];
        }
    }

    const int nkb = K / 32;
    for (int kb = 0; kb < nkb; kb++) {
        if (tid < 128) {
            if (lnStats) {
                const int kcur = kb * 32 + ac * 8;
                float4 gg0 = *(const float4*)&lnG[kcur];
                float4 gg1 = *(const float4*)&lnG[kcur + 4];
                float4 bb0 = *(const float4*)&lnB[kcur];
                float4 bb1 = *(const float4*)&lnB[kcur + 4];
                fa0.x = fmaf((fa0.x - st.x) * st.y, gg0.x, bb0.x);
                fa0.y = fmaf((fa0.y - st.x) * st.y, gg0.y, bb0.y);
                fa0.z = fmaf((fa0.z - st.x) * st.y, gg0.z, bb0.z);
                fa0.w = fmaf((fa0.w - st.x) * st.y, gg0.w, bb0.w);
                fa1.x = fmaf((fa1.x - st.x) * st.y, gg1.x, bb1.x);
                fa1.y = fmaf((fa1.y - st.x) * st.y, gg1.y, bb1.y);
                fa1.z = fmaf((fa1.z - st.x) * st.y, gg1.z, bb1.z);
                fa1.w = fmaf((fa1.w - st.x) * st.y, gg1.w, bb1.w);
            }
            split8s(fa0, fa1, &Ash[ar][ac * 8], &Asl[ar][ac * 8]);
        }
#pragma unroll
        for (int i = 0; i < 4; i++) {
            const int ch = i * 256 + tid;
            split8s(fw[i][0], fw[i][1], &Wsh[ch >> 2][(ch & 3) * 8], &Wsl[ch >> 2][(ch & 3) * 8]);
        }
        __syncthreads();

        if (kb + 1 < nkb) {
            const int k0 = (kb + 1) * 32;
            const float* Ab; int As;
            if (k0 < K0) { Ab = A0 + k0; As = K0; } else { Ab = A1 + (k0 - K0); As = K - K0; }
            if (tid < 128) {
                const float* pa = Ab + (size_t)(bm + ar) * As + ac * 8;
                fa0 = ((const float4*)pa)[0]; fa1 = ((const float4*)pa)[1];
            }
#pragma unroll
            for (int i = 0; i < 4; i++) {
                const int ch = i * 256 + tid;
                const float* pw = W + (size_t)(ch >> 2) * K + k0 + (ch & 3) * 8;
                fw[i][0] = ((const float4*)pw)[0]; fw[i][1] = ((const float4*)pw)[1];
            }
        }

#pragma unroll
        for (int ks = 0; ks < 2; ks++) {
            const int kk = ks * 16;
            uint32_t ah[2][4], al[2][4], bh[4][2], bl[4][2];
#pragma unroll
            for (int mt = 0; mt < 2; mt++) {
                const int rb = mt * 16;
                ah[mt][0] = *(const uint32_t*)&Ash[rb + g    ][kk + 2*tg];
                ah[mt][1] = *(const uint32_t*)&Ash[rb + g + 8][kk + 2*tg];
                ah[mt][2] = *(const uint32_t*)&Ash[rb + g    ][kk + 2*tg + 8];
                ah[mt][3] = *(const uint32_t*)&Ash[rb + g + 8][kk + 2*tg + 8];
                al[mt][0] = *(const uint32_t*)&Asl[rb + g    ][kk + 2*tg];
                al[mt][1] = *(const uint32_t*)&Asl[rb + g + 8][kk + 2*tg];
                al[mt][2] = *(const uint32_t*)&Asl[rb + g    ][kk + 2*tg + 8];
                al[mt][3] = *(const uint32_t*)&Asl[rb + g + 8][kk + 2*tg + 8];
            }
#pragma unroll
            for (int nt = 0; nt < 4; nt++) {
                const int nb = wn + nt * 8;
                bh[nt][0] = *(const uint32_t*)&Wsh[nb + g][kk + 2*tg];
                bh[nt][1] = *(const uint32_t*)&Wsh[nb + g][kk + 2*tg + 8];
                bl[nt][0] = *(const uint32_t*)&Wsl[nb + g][kk + 2*tg];
                bl[nt][1] = *(const uint32_t*)&Wsl[nb + g][kk + 2*tg + 8];
            }
#pragma unroll
            for (int mt = 0; mt < 2; mt++)
#pragma unroll
                for (int nt = 0; nt < 4; nt++) {
                    mma_bf16(acc[mt][nt], ah[mt], bh[nt]);
                    mma_bf16(acc[mt][nt], al[mt], bh[nt]);
                    mma_bf16(acc[mt][nt], ah[mt], bl[nt]);
                }
        }
        __syncthreads();
    }

    // ---- epilogue: bias -> gelu -> row LN over full 256 cols ----
    float rs[2][2] = {{0.f,0.f},{0.f,0.f}};   // [mt][rowhalf] sums
    float rq[2][2] = {{0.f,0.f},{0.f,0.f}};   // sums of squares
#pragma unroll
    for (int mt = 0; mt < 2; mt++)
#pragma unroll
        for (int nt = 0; nt < 4; nt++) {
            const int col = wn + nt * 8 + 2 * tg;
            const float bx = bias[col], by = bias[col + 1];
            float v0 = acc[mt][nt][0] + bx, v1 = acc[mt][nt][1] + by;
            float v2 = acc[mt][nt][2] + bx, v3 = acc[mt][nt][3] + by;
            v0 = 0.5f * v0 * (1.f + erff(v0 * 0.70710678118654752f));
            v1 = 0.5f * v1 * (1.f + erff(v1 * 0.70710678118654752f));
            v2 = 0.5f * v2 * (1.f + erff(v2 * 0.70710678118654752f));
            v3 = 0.5f * v3 * (1.f + erff(v3 * 0.70710678118654752f));
            acc[mt][nt][0] = v0; acc[mt][nt][1] = v1;
            acc[mt][nt][2] = v2; acc[mt][nt][3] = v3;
            rs[mt][0] += v0 + v1; rq[mt][0] += v0 * v0 + v1 * v1;
            rs[mt][1] += v2 + v3; rq[mt][1] += v2 * v2 + v3 * v3;
        }
    // reduce over the 4 tg lanes of each quad
#pragma unroll
    for (int o = 1; o <= 2; o <<= 1)
#pragma unroll
        for (int mt = 0; mt < 2; mt++)
#pragma unroll
            for (int rh = 0; rh < 2; rh++) {
                rs[mt][rh] += __shfl_xor_sync(0xFFFFFFFFu, rs[mt][rh], o);
                rq[mt][rh] += __shfl_xor_sync(0xFFFFFFFFu, rq[mt][rh], o);
            }
    if (tg == 0) {
#pragma unroll
        for (int mt = 0; mt < 2; mt++) {
            red[warp][mt * 16 + g][0]     = rs[mt][0];
            red[warp][mt * 16 + g][1]     = rq[mt][0];
            red[warp][mt * 16 + 8 + g][0] = rs[mt][1];
            red[warp][mt * 16 + 8 + g][1] = rq[mt][1];
        }
    }
    __syncthreads();
    if (tid < 64) {
        const int r = tid & 31, which = tid >> 5;
        float tsum = 0.f;
#pragma unroll
        for (int w = 0; w < 8; w++) tsum += red[w][r][which];
        fin[r][which] = tsum;
    }
    __syncthreads();
#pragma unroll
    for (int mt = 0; mt < 2; mt++) {
        const int rowL = mt * 16 + g, rowH = rowL + 8;
        const float mL = fin[rowL][0] * (1.f / 256.f);
        const float vL = fin[rowL][1] * (1.f / 256.f) - mL * mL;
        const float rL = rsqrtf(vL + 1e-5f);
        const float mH = fin[rowH][0] * (1.f / 256.f);
        const float vH = fin[rowH][1] * (1.f / 256.f) - mH * mH;
        const float rH = rsqrtf(vH + 1e-5f);
#pragma unroll
        for (int nt = 0; nt < 4; nt++) {
            const int col = wn + nt * 8 + 2 * tg;
            const float gx = g2[col], gy = g2[col + 1];
            const float bx = b2[col], by = b2[col + 1];
            *(float2*)&out[(size_t)(bm + rowL) * DD + col] = make_float2(
                fmaf((acc[mt][nt][0] - mL) * rL, gx, bx),
                fmaf((acc[mt][nt][1] - mL) * rL, gy, by));
            *(float2*)&out[(size_t)(bm + rowH) * DD + col] = make_float2(
                fmaf((acc[mt][nt][2] - mH) * rH, gx, bx),
                fmaf((acc[mt][nt][3] - mH) * rH, gy, by));
        }
    }
}

// warp-per-row stats of virtual z=[y|obs2] (D=512): mean + rstd
__global__ __launch_bounds__(256)
void ln_stats_warp_kernel(const float* __restrict__ y, const float* __restrict__ o2,
                          float2* __restrict__ stats) {
    const int warp = threadIdx.x >> 5, lane = threadIdx.x & 31;
    const int row = blockIdx.x * 8 + warp;
    const int c0 = lane * 8;
    const float* yp = y  + (size_t)row * 256 + c0;
    const float* op = o2 + (size_t)row * 256 + c0;
    float4 a0 = ((const float4*)yp)[0], a1 = ((const float4*)yp)[1];
    float4 b0 = ((const float4*)op)[0], b1 = ((const float4*)op)[1];
    float s  = a0.x + a0.y + a0.z + a0.w + a1.x + a1.y + a1.z + a1.w
             + b0.x + b0.y + b0.z + b0.w + b1.x + b1.y + b1.z + b1.w;
    float s2 = a0.x*a0.x + a0.y*a0.y + a0.z*a0.z + a0.w*a0.w
             + a1.x*a1.x + a1.y*a1.y + a1.z*a1.z + a1.w*a1.w
             + b0.x*b0.x + b0.y*b0.y + b0.z*b0.z + b0.w*b0.w
             + b1.x*b1.x + b1.y*b1.y + b1.z*b1.z + b1.w*b1.w;
#pragma unroll
    for (int o = 16; o > 0; o >>= 1) {
        s  += __shfl_xor_sync(0xFFFFFFFFu, s, o);
        s2 += __shfl_xor_sync(0xFFFFFFFFu, s2, o);
    }
    if (lane == 0) {
        float mean = s * (1.f / 512.f);
        float var  = s2 * (1.f / 512.f) - mean * mean;
        stats[row] = make_float2(mean, rsqrtf(var + 1e-5f));
    }
}

// ---------------- tensor-core attention: cp.async double-buffer + ldmatrix -----
#define KVS 40
__global__ __launch_bounds__(128, 3)
void attn_tc_kernel(const __nv_bfloat16* __restrict__ qh, const __nv_bfloat16* __restrict__ ql,
                    const __nv_bfloat16* __restrict__ kh, const __nv_bfloat16* __restrict__ kl,
                    const __nv_bfloat16* __restrict__ vh, const __nv_bfloat16* __restrict__ vl,
                    const unsigned* __restrict__ mbits, float* __restrict__ y) {
    __shared__ __align__(16) __nv_bfloat16 Ks[2][2][32][KVS];
    __shared__ __align__(16) __nv_bfloat16 Vs[2][2][32][KVS];
    __shared__ unsigned Msk[2][128];

    const int b = blockIdx.z, h = blockIdx.y;
    const int qb = blockIdx.x * 128;
    const int tid = threadIdx.x;
    const int warp = tid >> 5, lane = tid & 31;
    const int g = lane >> 2, tg = lane & 3;

    const uint32_t ksBase = smem_u32(&Ks[0][0][0][0]);
    const uint32_t vsBase = smem_u32(&Vs[0][0][0][0]);
    const uint32_t mkBase = smem_u32(&Msk[0][0]);
    const uint32_t planeB = 32 * KVS * 2;

    const int li = lane >> 3, lr = lane & 7;

    uint32_t aqh[2][2][4], aql[2][2][4];
#pragma unroll
    for (int mt = 0; mt < 2; mt++) {
        const int r0 = qb + warp * 32 + mt * 16 + g;
#pragma unroll
        for (int ks = 0; ks < 2; ks++) {
            const size_t base0 = ((size_t)(b * LL + r0)) * DD + h * HD + ks * 16 + 2 * tg;
            const size_t base8 = base0 + 8ull * DD;
            aqh[mt][ks][0] = *(const uint32_t*)&qh[base0];
            aqh[mt][ks][1] = *(const uint32_t*)&qh[base8];
            aqh[mt][ks][2] = *(const uint32_t*)&qh[base0 + 8];
            aqh[mt][ks][3] = *(const uint32_t*)&qh[base8 + 8];
            aql[mt][ks][0] = *(const uint32_t*)&ql[base0];
            aql[mt][ks][1] = *(const uint32_t*)&ql[base8];
            aql[mt][ks][2] = *(const uint32_t*)&ql[base0 + 8];
            aql[mt][ks][3] = *(const uint32_t*)&ql[base8 + 8];
        }
    }

    float co[2][4][4];
#pragma unroll
    for (int mt = 0; mt < 2; mt++)
#pragma unroll
        for (int n = 0; n < 4; n++)
#pragma unroll
            for (int j = 0; j < 4; j++) co[mt][n][j] = 0.f;
    float dn[2][2] = {{0.f,0.f},{0.f,0.f}};

    const int lrow = tid >> 2, lc = tid & 3;

    {
        const size_t src = ((size_t)(b * LL + 0 + lrow)) * DD + h * HD + lc * 8;
        const uint32_t off = (uint32_t)lrow * (KVS * 2) + lc * 16;
        CP_ASYNC16(ksBase + off,              kh + src);
        CP_ASYNC16(ksBase + planeB + off,     kl + src);
        CP_ASYNC16(vsBase + off,              vh + src);
        CP_ASYNC16(vsBase + planeB + off,     vl + src);
        CP_ASYNC4(mkBase + tid * 4, mbits + ((size_t)(b * LL + qb + tid)) * 32 + 0);
        CP_COMMIT();
    }

    const int NT = LL / 32;
    for (int t = 0; t < NT; t++) {
        const int buf = t & 1;
        if (t + 1 < NT) {
            const int nb = (t + 1) & 1;
            const size_t src = ((size_t)(b * LL + (t + 1) * 32 + lrow)) * DD + h * HD + lc * 8;
            const uint32_t off = (uint32_t)(nb * 2) * planeB
                               + (uint32_t)lrow * (KVS * 2) + lc * 16;
            CP_ASYNC16(ksBase + off,          kh + src);
            CP_ASYNC16(ksBase + planeB + off, kl + src);
            CP_ASYNC16(vsBase + off,          vh + src);
            CP_ASYNC16(vsBase + planeB + off, vl + src);
            CP_ASYNC4(mkBase + (nb * 128 + tid) * 4,
                      mbits + ((size_t)(b * LL + qb + tid)) * 32 + t + 1);
            CP_COMMIT();
            CP_WAIT(1);
        } else {
            CP_WAIT(0);
        }
        __syncthreads();

        const uint32_t kB0 = ksBase + (uint32_t)(buf * 2) * planeB;
        const uint32_t kB1 = kB0 + planeB;
        const uint32_t vB0 = vsBase + (uint32_t)(buf * 2) * planeB;
        const uint32_t vB1 = vB0 + planeB;

        uint32_t bKh[2][4][2], bKl[2][4][2];
#pragma unroll
        for (int ks = 0; ks < 2; ks++)
#pragma unroll
            for (int np = 0; np < 2; np++) {
                const uint32_t off = (uint32_t)(np * 16 + ((li >> 1) << 3) + lr) * (KVS * 2)
                                   + (uint32_t)(ks * 16 + ((li & 1) << 3)) * 2;
                ldsm4(bKh[ks][np*2][0], bKh[ks][np*2][1],
                      bKh[ks][np*2+1][0], bKh[ks][np*2+1][1], kB0 + off);
                ldsm4(bKl[ks][np*2][0], bKl[ks][np*2][1],
                      bKl[ks][np*2+1][0], bKl[ks][np*2+1][1], kB1 + off);
            }

        float cs[2][4][4];
#pragma unroll
        for (int mt = 0; mt < 2; mt++)
#pragma unroll
            for (int n = 0; n < 4; n++)
#pragma unroll
                for (int j = 0; j < 4; j++) cs[mt][n][j] = 0.f;
#pragma unroll
        for (int ks = 0; ks < 2; ks++)
#pragma unroll
            for (int mt = 0; mt < 2; mt++)
#pragma unroll
                for (int n = 0; n < 4; n++) {
                    mma_bf16(cs[mt][n], aqh[mt][ks], bKh[ks][n]);
                    mma_bf16(cs[mt][n], aql[mt][ks], bKh[ks][n]);
                    mma_bf16(cs[mt][n], aqh[mt][ks], bKl[ks][n]);
                }

        uint32_t bVh[2][4][2], bVl[2][4][2];
#pragma unroll
        for (int kp = 0; kp < 2; kp++)
#pragma unroll
            for (int np = 0; np < 2; np++) {
                const uint32_t off = (uint32_t)(kp * 16 + ((li & 1) << 3) + lr) * (KVS * 2)
                                   + (uint32_t)(np * 16 + ((li >> 1) << 3)) * 2;
                ldsm4t(bVh[kp][np*2][0], bVh[kp][np*2][1],
                       bVh[kp][np*2+1][0], bVh[kp][np*2+1][1], vB0 + off);
                ldsm4t(bVl[kp][np*2][0], bVl[kp][np*2][1],
                       bVl[kp][np*2+1][0], bVl[kp][np*2+1][1], vB1 + off);
            }

#pragma unroll
        for (int mt = 0; mt < 2; mt++) {
            const int rbase = warp * 32 + mt * 16;
            const unsigned w0 = Msk[buf][rbase + g];
            const unsigned w8 = Msk[buf][rbase + g + 8];
            float pr[4][4];
#pragma unroll
            for (int n = 0; n < 4; n++) {
                const int c0 = n * 8 + 2 * tg;
                const float m00 = (float)((w0 >> c0) & 1u);
                const float m01 = (float)((w0 >> (c0 + 1)) & 1u);
                const float m10 = (float)((w8 >> c0) & 1u);
                const float m11 = (float)((w8 >> (c0 + 1)) & 1u);
                pr[n][0] = fexp(cs[mt][n][0]) * m00;
                pr[n][1] = fexp(cs[mt][n][1]) * m01;
                pr[n][2] = fexp(cs[mt][n][2]) * m10;
                pr[n][3] = fexp(cs[mt][n][3]) * m11;
                dn[mt][0] += pr[n][0] + pr[n][1];
                dn[mt][1] += pr[n][2] + pr[n][3];
            }
#pragma unroll
            for (int kp = 0; kp < 2; kp++) {
                float e00 = pr[kp*2][0], e01 = pr[kp*2][1], e02 = pr[kp*2][2], e03 = pr[kp*2][3];
                float e10 = pr[kp*2+1][0], e11 = pr[kp*2+1][1], e12 = pr[kp*2+1][2], e13 = pr[kp*2+1][3];
                uint32_t pah[4], pal[4];
                pah[0] = hi_pack(e00, e01); pal[0] = lo_pack(e00, e01);
                pah[1] = hi_pack(e02, e03); pal[1] = lo_pack(e02, e03);
                pah[2] = hi_pack(e10, e11); pal[2] = lo_pack(e10, e11);
                pah[3] = hi_pack(e12, e13); pal[3] = lo_pack(e12, e13);
#pragma unroll
                for (int n = 0; n < 4; n++) {
                    mma_bf16(co[mt][n], pah, bVh[kp][n]);
                    mma_bf16(co[mt][n], pal, bVh[kp][n]);
                    mma_bf16(co[mt][n], pah, bVl[kp][n]);
                }
            }
        }
        __syncthreads();
    }

#pragma unroll
    for (int mt = 0; mt < 2; mt++)
#pragma unroll
        for (int rh = 0; rh < 2; rh++) {
            float d = dn[mt][rh];
            d += __shfl_xor_sync(0xFFFFFFFFu, d, 1);
            d += __shfl_xor_sync(0xFFFFFFFFu, d, 2);
            dn[mt][rh] = (d > 0.f) ? 1.0f / d : 0.f;
        }

#pragma unroll
    for (int mt = 0; mt < 2; mt++) {
        const int r0 = qb + warp * 32 + mt * 16 + g;
#pragma unroll
        for (int n = 0; n < 4; n++) {
            const int col = h * HD + n * 8 + 2 * tg;
            *(float2*)&y[((size_t)(b * LL + r0)) * DD + col] =
                make_float2(co[mt][n][0] * dn[mt][0], co[mt][n][1] * dn[mt][0]);
            *(float2*)&y[((size_t)(b * LL + r0 + 8)) * DD + col] =
                make_float2(co[mt][n][2] * dn[mt][1], co[mt][n][3] * dn[mt][1]);
        }
    }
}

// ---------------- launch ------------------------------------------------------
extern "C" void kernel_launch(void* const* d_in, const int* in_sizes, int n_in,
                              void* d_out, int out_size) {
    const float* obs  = (const float*)d_in[0];
    const float* act  = (const float*)d_in[1];
    const int*   msk  = (const int*)  d_in[2];
    const float* Wq   = (const float*)d_in[3];
    const float* bq   = (const float*)d_in[4];
    const float* Wk   = (const float*)d_in[5];
    const float* bk   = (const float*)d_in[6];
    const float* Wv   = (const float*)d_in[7];
    const float* bv   = (const float*)d_in[8];
    const float* Wobs = (const float*)d_in[9];
    const float* bobs = (const float*)d_in[10];
    const float* gob  = (const float*)d_in[11];
    const float* bob  = (const float*)d_in[12];
    const float* g1   = (const float*)d_in[13];
    const float* b1   = (const float*)d_in[14];
    const float* Wp   = (const float*)d_in[15];
    const float* bp   = (const float*)d_in[16];
    const float* g2   = (const float*)d_in[17];
    const float* b2   = (const float*)d_in[18];

    float *obs2, *yb;
    float2* stats;
    unsigned* mb;
    cudaGetSymbolAddress((void**)&obs2,  g_obs2);
    cudaGetSymbolAddress((void**)&yb,    g_y);
    cudaGetSymbolAddress((void**)&stats, g_stats);
    cudaGetSymbolAddress((void**)&mb,    g_mbits);

    __nv_bfloat16 *qh,*ql,*kh,*kl,*vh,*vl;
    cudaGetSymbolAddress((void**)&qh, g_qh); cudaGetSymbolAddress((void**)&ql, g_ql);
    cudaGetSymbolAddress((void**)&kh, g_kh); cudaGetSymbolAddress((void**)&kl, g_kl);
    cudaGetSymbolAddress((void**)&vh, g_vh); cudaGetSymbolAddress((void**)&vl, g_vl);

    pack_mask_kernel<<<dim3(LL, BB), 128>>>(msk, mb);

    // q projection (A=obs, K=256), bf16-split out; grid.x=4 -> half0 only
    gemm2_kernel<<<dim3(4, 128), 256>>>(obs, obs, 256, Wq, Wq, bq, bq,
                                        qh, ql, qh, ql, 256);
    // k + v merged (A=[obs|act], K=512)
    gemm2_kernel<<<dim3(8, 128), 256>>>(obs, act, 256, Wk, Wv, bk, bv,
                                        kh, kl, vh, vl, 512);

    // obs branch fused: obs2 = LN(gelu(obs @ Wobs^T + bobs))
    gemm_gelu_ln_kernel<<<MROWS / 32, 256>>>(obs, obs, 256, Wobs, bobs,
                                             nullptr, nullptr, nullptr,
                                             gob, bob, obs2, 256);

    attn_tc_kernel<<<dim3(LL / 128, HH, BB), 128>>>(qh, ql, kh, kl, vh, vl, mb, yb);

    // final stage fused: out = LN(gelu(LN_z([y|obs2]) @ Wp^T + bp))
    ln_stats_warp_kernel<<<MROWS / 8, 256>>>(yb, obs2, stats);
    gemm_gelu_ln_kernel<<<MROWS / 32, 256>>>(yb, obs2, 256, Wp, bp,
                                             stats, g1, b1,
                                             g2, b2, (float*)d_out, 512);
}

// round 17
// speedup vs baseline: 1.2874x; 1.0225x over previous
#include <cuda_runtime.h>
#include <cuda_bf16.h>
#include <math.h>
#include <cstdint>

// Shapes (fixed)
#define BB 8
#define LL 1024
#define DD 256
#define HH 8
#define HD 32
#define MROWS (BB*LL)   // 8192

// ---------------- scratch (device globals) -----------------------------------
__device__ float g_obs2[MROWS * DD];
__device__ float g_y   [MROWS * DD];
__device__ float2 g_stats[MROWS];
__device__ unsigned g_mbits[BB * LL * (LL/32)];

__device__ __nv_bfloat16 g_qh[MROWS * DD], g_ql[MROWS * DD];
__device__ __nv_bfloat16 g_kh[MROWS * DD], g_kl[MROWS * DD];
__device__ __nv_bfloat16 g_vh[MROWS * DD], g_vl[MROWS * DD];

// ---------------- helpers -----------------------------------------------------
__device__ __forceinline__ uint32_t smem_u32(const void* p) {
    return (uint32_t)__cvta_generic_to_shared(p);
}
__device__ __forceinline__ void split1(float x, __nv_bfloat16& h, __nv_bfloat16& l) {
    h = __float2bfloat16(x);
    l = __float2bfloat16(x - __bfloat162float(h));
}
// truncation split: hi = top16 bits (exact), lo = rn_bf16(x - hi); a -> low half
__device__ __forceinline__ uint32_t hi_pack(float a, float b) {
    uint32_t r;
    asm("prmt.b32 %0, %1, %2, 0x7632;" : "=r"(r)
        : "r"(__float_as_int(a)), "r"(__float_as_int(b)));
    return r;
}
__device__ __forceinline__ uint32_t lo_pack(float a, float b) {
    float la = a - __int_as_float(__float_as_int(a) & 0xFFFF0000u);
    float lb = b - __int_as_float(__float_as_int(b) & 0xFFFF0000u);
    uint32_t r;
    asm("cvt.rn.bf16x2.f32 %0, %1, %2;" : "=r"(r) : "f"(lb), "f"(la));
    return r;
}
// fast exp on FMA pipe, degree-4
__device__ __forceinline__ float fexp(float s) {
    const float L2E = 1.4426950408889634f;
    float t  = fmaf(s, L2E, 12582912.0f);
    int   ei = __float_as_int(t) << 23;
    float n  = t - 12582912.0f;
    float f  = fmaf(s, L2E, -n);
    float r  = 9.6181291e-3f;
    r = fmaf(r, f, 5.5504109e-2f);
    r = fmaf(r, f, 2.4022651e-1f);
    r = fmaf(r, f, 6.9314718e-1f);
    r = fmaf(r, f, 1.0f);
    return __int_as_float(__float_as_int(r) + ei);
}

#define CP_ASYNC16(dst, src) \
    asm volatile("cp.async.ca.shared.global [%0], [%1], 16;" :: "r"(dst), "l"(src))
#define CP_ASYNC4(dst, src) \
    asm volatile("cp.async.ca.shared.global [%0], [%1], 4;" :: "r"(dst), "l"(src))
#define CP_COMMIT() asm volatile("cp.async.commit_group;" ::: "memory")
#define CP_WAIT(n)  asm volatile("cp.async.wait_group %0;" :: "n"(n) : "memory")

__device__ __forceinline__ void ldsm4(uint32_t& r0, uint32_t& r1, uint32_t& r2,
                                      uint32_t& r3, uint32_t addr) {
    asm volatile("ldmatrix.sync.aligned.m8n8.x4.shared.b16 {%0,%1,%2,%3},[%4];"
        : "=r"(r0), "=r"(r1), "=r"(r2), "=r"(r3) : "r"(addr));
}
__device__ __forceinline__ void ldsm4t(uint32_t& r0, uint32_t& r1, uint32_t& r2,
                                       uint32_t& r3, uint32_t addr) {
    asm volatile("ldmatrix.sync.aligned.m8n8.x4.trans.shared.b16 {%0,%1,%2,%3},[%4];"
        : "=r"(r0), "=r"(r1), "=r"(r2), "=r"(r3) : "r"(addr));
}

// pack mask (diagonal cleared) into bitwords
__global__ __launch_bounds__(128)
void pack_mask_kernel(const int* __restrict__ mask, unsigned* __restrict__ bits) {
    int b = blockIdx.y, row = blockIdx.x;
    int lane = threadIdx.x & 31, warp = threadIdx.x >> 5;
    const int* mrow = mask + ((size_t)b * LL + row) * LL;
    for (int w = warp; w < 32; w += 4) {
        int col = w * 32 + lane;
        unsigned bit = (unsigned)((mrow[col] != 0) && (col != row));
        unsigned word = __ballot_sync(0xFFFFFFFFu, bit);
        if (lane == 0) bits[((size_t)b * LL + row) * 32 + w] = word;
    }
}

// ---------------- shared GEMM pieces -------------------------------------------
#define APAD 8

__device__ __forceinline__ void mma_bf16(float* c, const uint32_t* a, const uint32_t* b) {
    asm volatile(
        "mma.sync.aligned.m16n8k16.row.col.f32.bf16.bf16.f32 "
        "{%0,%1,%2,%3},{%4,%5,%6,%7},{%8,%9},{%0,%1,%2,%3};"
        : "+f"(c[0]), "+f"(c[1]), "+f"(c[2]), "+f"(c[3])
        : "r"(a[0]), "r"(a[1]), "r"(a[2]), "r"(a[3]), "r"(b[0]), "r"(b[1]));
}

__device__ __forceinline__ void split8s(float4 f0, float4 f1,
                                        __nv_bfloat16* hiDst, __nv_bfloat16* loDst) {
    uint4 hi, lo;
    hi.x = hi_pack(f0.x, f0.y); lo.x = lo_pack(f0.x, f0.y);
    hi.y = hi_pack(f0.z, f0.w); lo.y = lo_pack(f0.z, f0.w);
    hi.z = hi_pack(f1.x, f1.y); lo.z = lo_pack(f1.x, f1.y);
    hi.w = hi_pack(f1.z, f1.w); lo.w = lo_pack(f1.z, f1.w);
    *(uint4*)hiDst = hi;
    *(uint4*)loDst = lo;
}

// ---------------- dual-output fused-split GEMM (double-buffered) ---------------
__global__ __launch_bounds__(256)
void gemm2_kernel(const float* __restrict__ A0, const float* __restrict__ A1, int K0,
                  const float* __restrict__ W0, const float* __restrict__ W1,
                  const float* __restrict__ bias0, const float* __restrict__ bias1,
                  __nv_bfloat16* __restrict__ C0h, __nv_bfloat16* __restrict__ C0l,
                  __nv_bfloat16* __restrict__ C1h, __nv_bfloat16* __restrict__ C1l,
                  int K) {
    __shared__ __nv_bfloat16 Ash[2][64][32 + APAD];
    __shared__ __nv_bfloat16 Asl[2][64][32 + APAD];
    __shared__ __nv_bfloat16 Wsh[2][64][32 + APAD];
    __shared__ __nv_bfloat16 Wsl[2][64][32 + APAD];

    const int tid = threadIdx.x;
    const int bn = blockIdx.x * 64;
    const int bm = blockIdx.y * 64;
    const int wid = tid >> 5, lane = tid & 31;
    const int wm = (wid >> 2) * 32;
    const int wn = (wid & 3) * 16;
    const int g  = lane >> 2;
    const int tg = lane & 3;

    const bool half0 = (bn < 256);
    const float* W    = half0 ? W0 : W1;
    const float* bias = half0 ? bias0 : bias1;
    __nv_bfloat16* Ch = half0 ? C0h : C1h;
    __nv_bfloat16* Cl = half0 ? C0l : C1l;
    const int cb = bn & 255;

    const int ar = tid >> 2;
    const int ac = tid & 3;

    float acc[2][2][4];
#pragma unroll
    for (int mt = 0; mt < 2; mt++)
#pragma unroll
        for (int nt = 0; nt < 2; nt++)
#pragma unroll
            for (int j = 0; j < 4; j++) acc[mt][nt][j] = 0.f;

    float4 fa0, fa1, fw0, fw1;
    {
        const float* Ab; int As;
        if (0 < K0) { Ab = A0; As = K0; } else { Ab = A1; As = K - K0; }
        const float* pa = Ab + (size_t)(bm + ar) * As + ac * 8;
        fa0 = ((const float4*)pa)[0]; fa1 = ((const float4*)pa)[1];
        const float* pw = W + (size_t)(cb + ar) * K + ac * 8;
        fw0 = ((const float4*)pw)[0]; fw1 = ((const float4*)pw)[1];
    }

    const int nkb = K / 32;
    for (int kb = 0; kb < nkb; kb++) {
        const int buf = kb & 1;
        split8s(fa0, fa1, &Ash[buf][ar][ac * 8], &Asl[buf][ar][ac * 8]);
        split8s(fw0, fw1, &Wsh[buf][ar][ac * 8], &Wsl[buf][ar][ac * 8]);

        if (kb + 1 < nkb) {
            const int k0 = (kb + 1) * 32;
            const float* Ab; int As;
            if (k0 < K0) { Ab = A0 + k0; As = K0; } else { Ab = A1 + (k0 - K0); As = K - K0; }
            const float* pa = Ab + (size_t)(bm + ar) * As + ac * 8;
            fa0 = ((const float4*)pa)[0]; fa1 = ((const float4*)pa)[1];
            const float* pw = W + (size_t)(cb + ar) * K + k0 + ac * 8;
            fw0 = ((const float4*)pw)[0]; fw1 = ((const float4*)pw)[1];
        }

        __syncthreads();

#pragma unroll
        for (int ks = 0; ks < 2; ks++) {
            const int kk = ks * 16;
            uint32_t ah[2][4], al[2][4], bh[2][2], bl[2][2];
#pragma unroll
            for (int mt = 0; mt < 2; mt++) {
                const int rb = wm + mt * 16;
                ah[mt][0] = *(const uint32_t*)&Ash[buf][rb + g    ][kk + 2*tg];
                ah[mt][1] = *(const uint32_t*)&Ash[buf][rb + g + 8][kk + 2*tg];
                ah[mt][2] = *(const uint32_t*)&Ash[buf][rb + g    ][kk + 2*tg + 8];
                ah[mt][3] = *(const uint32_t*)&Ash[buf][rb + g + 8][kk + 2*tg + 8];
                al[mt][0] = *(const uint32_t*)&Asl[buf][rb + g    ][kk + 2*tg];
                al[mt][1] = *(const uint32_t*)&Asl[buf][rb + g + 8][kk + 2*tg];
                al[mt][2] = *(const uint32_t*)&Asl[buf][rb + g    ][kk + 2*tg + 8];
                al[mt][3] = *(const uint32_t*)&Asl[buf][rb + g + 8][kk + 2*tg + 8];
            }
#pragma unroll
            for (int nt = 0; nt < 2; nt++) {
                const int nb = wn + nt * 8;
                bh[nt][0] = *(const uint32_t*)&Wsh[buf][nb + g][kk + 2*tg];
                bh[nt][1] = *(const uint32_t*)&Wsh[buf][nb + g][kk + 2*tg + 8];
                bl[nt][0] = *(const uint32_t*)&Wsl[buf][nb + g][kk + 2*tg];
                bl[nt][1] = *(const uint32_t*)&Wsl[buf][nb + g][kk + 2*tg + 8];
            }
#pragma unroll
            for (int mt = 0; mt < 2; mt++)
#pragma unroll
                for (int nt = 0; nt < 2; nt++) {
                    mma_bf16(acc[mt][nt], ah[mt], bh[nt]);
                    mma_bf16(acc[mt][nt], al[mt], bh[nt]);
                    mma_bf16(acc[mt][nt], ah[mt], bl[nt]);
                }
        }
    }

#pragma unroll
    for (int mt = 0; mt < 2; mt++) {
#pragma unroll
        for (int nt = 0; nt < 2; nt++) {
            const int col = cb + wn + nt * 8 + 2 * tg;
            const float bx = bias[col], by = bias[col + 1];
            const int r0 = bm + wm + mt * 16 + g;
            float v0 = acc[mt][nt][0] + bx, v1 = acc[mt][nt][1] + by;
            float v2 = acc[mt][nt][2] + bx, v3 = acc[mt][nt][3] + by;
            __nv_bfloat16 h0,l0,h1,l1,h2,l2,h3,l3;
            split1(v0,h0,l0); split1(v1,h1,l1); split1(v2,h2,l2); split1(v3,h3,l3);
            *(__nv_bfloat162*)&Ch[(size_t)r0 * DD + col]       = __halves2bfloat162(h0,h1);
            *(__nv_bfloat162*)&Cl[(size_t)r0 * DD + col]       = __halves2bfloat162(l0,l1);
            *(__nv_bfloat162*)&Ch[(size_t)(r0 + 8) * DD + col] = __halves2bfloat162(h2,h3);
            *(__nv_bfloat162*)&Cl[(size_t)(r0 + 8) * DD + col] = __halves2bfloat162(l2,l3);
        }
    }
}

// ---------------- fused GEMM -> gelu -> LayerNorm ------------------------------
__global__ __launch_bounds__(256)
void gemm_gelu_ln_kernel(const float* __restrict__ A0, const float* __restrict__ A1, int K0,
                         const float* __restrict__ W, const float* __restrict__ bias,
                         const float2* __restrict__ lnStats,
                         const float* __restrict__ lnG, const float* __restrict__ lnB,
                         const float* __restrict__ g2, const float* __restrict__ b2,
                         float* __restrict__ out, int K) {
    __shared__ __nv_bfloat16 Ash[32][32 + APAD];
    __shared__ __nv_bfloat16 Asl[32][32 + APAD];
    __shared__ __nv_bfloat16 Wsh[256][32 + APAD];
    __shared__ __nv_bfloat16 Wsl[256][32 + APAD];
    __shared__ float red[8][32][2];
    __shared__ float fin[32][2];

    const int tid = threadIdx.x;
    const int bm = blockIdx.x * 32;
    const int warp = tid >> 5, lane = tid & 31;
    const int wn = warp * 32;
    const int g  = lane >> 2;
    const int tg = lane & 3;

    const int ar = tid >> 2, ac = tid & 3;
    float2 st = make_float2(0.f, 1.f);
    if (lnStats && tid < 128) st = lnStats[bm + ar];

    float acc[2][4][4];
#pragma unroll
    for (int mt = 0; mt < 2; mt++)
#pragma unroll
        for (int nt = 0; nt < 4; nt++)
#pragma unroll
            for (int j = 0; j < 4; j++) acc[mt][nt][j] = 0.f;

    float4 fa0, fa1, fw[4][2];
    {
        const float* Ab; int As;
        if (0 < K0) { Ab = A0; As = K0; } else { Ab = A1; As = K - K0; }
        if (tid < 128) {
            const float* pa = Ab + (size_t)(bm + ar) * As + ac * 8;
            fa0 = ((const float4*)pa)[0]; fa1 = ((const float4*)pa)[1];
        }
#pragma unroll
        for (int i = 0; i < 4; i++) {
            const int ch = i * 256 + tid;
            const float* pw = W + (size_t)(ch >> 2) * K + (ch & 3) * 8;
            fw[i][0] = ((const float4*)pw)[0]; fw[i][1] = ((const float4*)pw)[1];
        }
    }

    const int nkb = K / 32;
    for (int kb = 0; kb < nkb; kb++) {
        if (tid < 128) {
            if (lnStats) {
                const int kcur = kb * 32 + ac * 8;
                float4 gg0 = *(const float4*)&lnG[kcur];
                float4 gg1 = *(const float4*)&lnG[kcur + 4];
                float4 bb0 = *(const float4*)&lnB[kcur];
                float4 bb1 = *(const float4*)&lnB[kcur + 4];
                fa0.x = fmaf((fa0.x - st.x) * st.y, gg0.x, bb0.x);
                fa0.y = fmaf((fa0.y - st.x) * st.y, gg0.y, bb0.y);
                fa0.z = fmaf((fa0.z - st.x) * st.y, gg0.z, bb0.z);
                fa0.w = fmaf((fa0.w - st.x) * st.y, gg0.w, bb0.w);
                fa1.x = fmaf((fa1.x - st.x) * st.y, gg1.x, bb1.x);
                fa1.y = fmaf((fa1.y - st.x) * st.y, gg1.y, bb1.y);
                fa1.z = fmaf((fa1.z - st.x) * st.y, gg1.z, bb1.z);
                fa1.w = fmaf((fa1.w - st.x) * st.y, gg1.w, bb1.w);
            }
            split8s(fa0, fa1, &Ash[ar][ac * 8], &Asl[ar][ac * 8]);
        }
#pragma unroll
        for (int i = 0; i < 4; i++) {
            const int ch = i * 256 + tid;
            split8s(fw[i][0], fw[i][1], &Wsh[ch >> 2][(ch & 3) * 8], &Wsl[ch >> 2][(ch & 3) * 8]);
        }
        __syncthreads();

        if (kb + 1 < nkb) {
            const int k0 = (kb + 1) * 32;
            const float* Ab; int As;
            if (k0 < K0) { Ab = A0 + k0; As = K0; } else { Ab = A1 + (k0 - K0); As = K - K0; }
            if (tid < 128) {
                const float* pa = Ab + (size_t)(bm + ar) * As + ac * 8;
                fa0 = ((const float4*)pa)[0]; fa1 = ((const float4*)pa)[1];
            }
#pragma unroll
            for (int i = 0; i < 4; i++) {
                const int ch = i * 256 + tid;
                const float* pw = W + (size_t)(ch >> 2) * K + k0 + (ch & 3) * 8;
                fw[i][0] = ((const float4*)pw)[0]; fw[i][1] = ((const float4*)pw)[1];
            }
        }

#pragma unroll
        for (int ks = 0; ks < 2; ks++) {
            const int kk = ks * 16;
            uint32_t ah[2][4], al[2][4], bh[4][2], bl[4][2];
#pragma unroll
            for (int mt = 0; mt < 2; mt++) {
                const int rb = mt * 16;
                ah[mt][0] = *(const uint32_t*)&Ash[rb + g    ][kk + 2*tg];
                ah[mt][1] = *(const uint32_t*)&Ash[rb + g + 8][kk + 2*tg];
                ah[mt][2] = *(const uint32_t*)&Ash[rb + g    ][kk + 2*tg + 8];
                ah[mt][3] = *(const uint32_t*)&Ash[rb + g + 8][kk + 2*tg + 8];
                al[mt][0] = *(const uint32_t*)&Asl[rb + g    ][kk + 2*tg];
                al[mt][1] = *(const uint32_t*)&Asl[rb + g + 8][kk + 2*tg];
                al[mt][2] = *(const uint32_t*)&Asl[rb + g    ][kk + 2*tg + 8];
                al[mt][3] = *(const uint32_t*)&Asl[rb + g + 8][kk + 2*tg + 8];
            }
#pragma unroll
            for (int nt = 0; nt < 4; nt++) {
                const int nb = wn + nt * 8;
                bh[nt][0] = *(const uint32_t*)&Wsh[nb + g][kk + 2*tg];
                bh[nt][1] = *(const uint32_t*)&Wsh[nb + g][kk + 2*tg + 8];
                bl[nt][0] = *(const uint32_t*)&Wsl[nb + g][kk + 2*tg];
                bl[nt][1] = *(const uint32_t*)&Wsl[nb + g][kk + 2*tg + 8];
            }
#pragma unroll
            for (int mt = 0; mt < 2; mt++)
#pragma unroll
                for (int nt = 0; nt < 4; nt++) {
                    mma_bf16(acc[mt][nt], ah[mt], bh[nt]);
                    mma_bf16(acc[mt][nt], al[mt], bh[nt]);
                    mma_bf16(acc[mt][nt], ah[mt], bl[nt]);
                }
        }
        __syncthreads();
    }

    float rs[2][2] = {{0.f,0.f},{0.f,0.f}};
    float rq[2][2] = {{0.f,0.f},{0.f,0.f}};
#pragma unroll
    for (int mt = 0; mt < 2; mt++)
#pragma unroll
        for (int nt = 0; nt < 4; nt++) {
            const int col = wn + nt * 8 + 2 * tg;
            const float bx = bias[col], by = bias[col + 1];
            float v0 = acc[mt][nt][0] + bx, v1 = acc[mt][nt][1] + by;
            float v2 = acc[mt][nt][2] + bx, v3 = acc[mt][nt][3] + by;
            v0 = 0.5f * v0 * (1.f + erff(v0 * 0.70710678118654752f));
            v1 = 0.5f * v1 * (1.f + erff(v1 * 0.70710678118654752f));
            v2 = 0.5f * v2 * (1.f + erff(v2 * 0.70710678118654752f));
            v3 = 0.5f * v3 * (1.f + erff(v3 * 0.70710678118654752f));
            acc[mt][nt][0] = v0; acc[mt][nt][1] = v1;
            acc[mt][nt][2] = v2; acc[mt][nt][3] = v3;
            rs[mt][0] += v0 + v1; rq[mt][0] += v0 * v0 + v1 * v1;
            rs[mt][1] += v2 + v3; rq[mt][1] += v2 * v2 + v3 * v3;
        }
#pragma unroll
    for (int o = 1; o <= 2; o <<= 1)
#pragma unroll
        for (int mt = 0; mt < 2; mt++)
#pragma unroll
            for (int rh = 0; rh < 2; rh++) {
                rs[mt][rh] += __shfl_xor_sync(0xFFFFFFFFu, rs[mt][rh], o);
                rq[mt][rh] += __shfl_xor_sync(0xFFFFFFFFu, rq[mt][rh], o);
            }
    if (tg == 0) {
#pragma unroll
        for (int mt = 0; mt < 2; mt++) {
            red[warp][mt * 16 + g][0]     = rs[mt][0];
            red[warp][mt * 16 + g][1]     = rq[mt][0];
            red[warp][mt * 16 + 8 + g][0] = rs[mt][1];
            red[warp][mt * 16 + 8 + g][1] = rq[mt][1];
        }
    }
    __syncthreads();
    if (tid < 64) {
        const int r = tid & 31, which = tid >> 5;
        float tsum = 0.f;
#pragma unroll
        for (int w = 0; w < 8; w++) tsum += red[w][r][which];
        fin[r][which] = tsum;
    }
    __syncthreads();
#pragma unroll
    for (int mt = 0; mt < 2; mt++) {
        const int rowL = mt * 16 + g, rowH = rowL + 8;
        const float mL = fin[rowL][0] * (1.f / 256.f);
        const float vL = fin[rowL][1] * (1.f / 256.f) - mL * mL;
        const float rL = rsqrtf(vL + 1e-5f);
        const float mH = fin[rowH][0] * (1.f / 256.f);
        const float vH = fin[rowH][1] * (1.f / 256.f) - mH * mH;
        const float rH = rsqrtf(vH + 1e-5f);
#pragma unroll
        for (int nt = 0; nt < 4; nt++) {
            const int col = wn + nt * 8 + 2 * tg;
            const float gx = g2[col], gy = g2[col + 1];
            const float bx = b2[col], by = b2[col + 1];
            *(float2*)&out[(size_t)(bm + rowL) * DD + col] = make_float2(
                fmaf((acc[mt][nt][0] - mL) * rL, gx, bx),
                fmaf((acc[mt][nt][1] - mL) * rL, gy, by));
            *(float2*)&out[(size_t)(bm + rowH) * DD + col] = make_float2(
                fmaf((acc[mt][nt][2] - mH) * rH, gx, bx),
                fmaf((acc[mt][nt][3] - mH) * rH, gy, by));
        }
    }
}

// warp-per-row stats of virtual z=[y|obs2] (D=512): mean + rstd
__global__ __launch_bounds__(256)
void ln_stats_warp_kernel(const float* __restrict__ y, const float* __restrict__ o2,
                          float2* __restrict__ stats) {
    const int warp = threadIdx.x >> 5, lane = threadIdx.x & 31;
    const int row = blockIdx.x * 8 + warp;
    const int c0 = lane * 8;
    const float* yp = y  + (size_t)row * 256 + c0;
    const float* op = o2 + (size_t)row * 256 + c0;
    float4 a0 = ((const float4*)yp)[0], a1 = ((const float4*)yp)[1];
    float4 b0 = ((const float4*)op)[0], b1 = ((const float4*)op)[1];
    float s  = a0.x + a0.y + a0.z + a0.w + a1.x + a1.y + a1.z + a1.w
             + b0.x + b0.y + b0.z + b0.w + b1.x + b1.y + b1.z + b1.w;
    float s2 = a0.x*a0.x + a0.y*a0.y + a0.z*a0.z + a0.w*a0.w
             + a1.x*a1.x + a1.y*a1.y + a1.z*a1.z + a1.w*a1.w
             + b0.x*b0.x + b0.y*b0.y + b0.z*b0.z + b0.w*b0.w
             + b1.x*b1.x + b1.y*b1.y + b1.z*b1.z + b1.w*b1.w;
#pragma unroll
    for (int o = 16; o > 0; o >>= 1) {
        s  += __shfl_xor_sync(0xFFFFFFFFu, s, o);
        s2 += __shfl_xor_sync(0xFFFFFFFFu, s2, o);
    }
    if (lane == 0) {
        float mean = s * (1.f / 512.f);
        float var  = s2 * (1.f / 512.f) - mean * mean;
        stats[row] = make_float2(mean, rsqrtf(var + 1e-5f));
    }
}

// ---------------- tensor-core attention: cp.async double-buffer + ldmatrix -----
#define KVS 40
__global__ __launch_bounds__(128, 3)
void attn_tc_kernel(const __nv_bfloat16* __restrict__ qh, const __nv_bfloat16* __restrict__ ql,
                    const __nv_bfloat16* __restrict__ kh, const __nv_bfloat16* __restrict__ kl,
                    const __nv_bfloat16* __restrict__ vh, const __nv_bfloat16* __restrict__ vl,
                    const unsigned* __restrict__ mbits, float* __restrict__ y) {
    __shared__ __align__(16) __nv_bfloat16 Ks[2][2][32][KVS];
    __shared__ __align__(16) __nv_bfloat16 Vs[2][2][32][KVS];
    __shared__ unsigned Msk[2][128];

    const int b = blockIdx.z, h = blockIdx.y;
    const int qb = blockIdx.x * 128;
    const int tid = threadIdx.x;
    const int warp = tid >> 5, lane = tid & 31;
    const int g = lane >> 2, tg = lane & 3;

    const uint32_t ksBase = smem_u32(&Ks[0][0][0][0]);
    const uint32_t vsBase = smem_u32(&Vs[0][0][0][0]);
    const uint32_t mkBase = smem_u32(&Msk[0][0]);
    const uint32_t planeB = 32 * KVS * 2;

    const int li = lane >> 3, lr = lane & 7;

    uint32_t aqh[2][2][4], aql[2][2][4];
#pragma unroll
    for (int mt = 0; mt < 2; mt++) {
        const int r0 = qb + warp * 32 + mt * 16 + g;
#pragma unroll
        for (int ks = 0; ks < 2; ks++) {
            const size_t base0 = ((size_t)(b * LL + r0)) * DD + h * HD + ks * 16 + 2 * tg;
            const size_t base8 = base0 + 8ull * DD;
            aqh[mt][ks][0] = *(const uint32_t*)&qh[base0];
            aqh[mt][ks][1] = *(const uint32_t*)&qh[base8];
            aqh[mt][ks][2] = *(const uint32_t*)&qh[base0 + 8];
            aqh[mt][ks][3] = *(const uint32_t*)&qh[base8 + 8];
            aql[mt][ks][0] = *(const uint32_t*)&ql[base0];
            aql[mt][ks][1] = *(const uint32_t*)&ql[base8];
            aql[mt][ks][2] = *(const uint32_t*)&ql[base0 + 8];
            aql[mt][ks][3] = *(const uint32_t*)&ql[base8 + 8];
        }
    }

    float co[2][4][4];
#pragma unroll
    for (int mt = 0; mt < 2; mt++)
#pragma unroll
        for (int n = 0; n < 4; n++)
#pragma unroll
            for (int j = 0; j < 4; j++) co[mt][n][j] = 0.f;
    float dn[2][2] = {{0.f,0.f},{0.f,0.f}};

    const int lrow = tid >> 2, lc = tid & 3;

    {
        const size_t src = ((size_t)(b * LL + 0 + lrow)) * DD + h * HD + lc * 8;
        const uint32_t off = (uint32_t)lrow * (KVS * 2) + lc * 16;
        CP_ASYNC16(ksBase + off,              kh + src);
        CP_ASYNC16(ksBase + planeB + off,     kl + src);
        CP_ASYNC16(vsBase + off,              vh + src);
        CP_ASYNC16(vsBase + planeB + off,     vl + src);
        CP_ASYNC4(mkBase + tid * 4, mbits + ((size_t)(b * LL + qb + tid)) * 32 + 0);
        CP_COMMIT();
    }

    const int NT = LL / 32;
    for (int t = 0; t < NT; t++) {
        const int buf = t & 1;
        if (t + 1 < NT) {
            const int nb = (t + 1) & 1;
            const size_t src = ((size_t)(b * LL + (t + 1) * 32 + lrow)) * DD + h * HD + lc * 8;
            const uint32_t off = (uint32_t)(nb * 2) * planeB
                               + (uint32_t)lrow * (KVS * 2) + lc * 16;
            CP_ASYNC16(ksBase + off,          kh + src);
            CP_ASYNC16(ksBase + planeB + off, kl + src);
            CP_ASYNC16(vsBase + off,          vh + src);
            CP_ASYNC16(vsBase + planeB + off, vl + src);
            CP_ASYNC4(mkBase + (nb * 128 + tid) * 4,
                      mbits + ((size_t)(b * LL + qb + tid)) * 32 + t + 1);
            CP_COMMIT();
            CP_WAIT(1);
        } else {
            CP_WAIT(0);
        }
        __syncthreads();

        const uint32_t kB0 = ksBase + (uint32_t)(buf * 2) * planeB;
        const uint32_t kB1 = kB0 + planeB;
        const uint32_t vB0 = vsBase + (uint32_t)(buf * 2) * planeB;
        const uint32_t vB1 = vB0 + planeB;

        uint32_t bKh[2][4][2], bKl[2][4][2];
#pragma unroll
        for (int ks = 0; ks < 2; ks++)
#pragma unroll
            for (int np = 0; np < 2; np++) {
                const uint32_t off = (uint32_t)(np * 16 + ((li >> 1) << 3) + lr) * (KVS * 2)
                                   + (uint32_t)(ks * 16 + ((li & 1) << 3)) * 2;
                ldsm4(bKh[ks][np*2][0], bKh[ks][np*2][1],
                      bKh[ks][np*2+1][0], bKh[ks][np*2+1][1], kB0 + off);
                ldsm4(bKl[ks][np*2][0], bKl[ks][np*2][1],
                      bKl[ks][np*2+1][0], bKl[ks][np*2+1][1], kB1 + off);
            }

        float cs[2][4][4];
#pragma unroll
        for (int mt = 0; mt < 2; mt++)
#pragma unroll
            for (int n = 0; n < 4; n++)
#pragma unroll
                for (int j = 0; j < 4; j++) cs[mt][n][j] = 0.f;
#pragma unroll
        for (int ks = 0; ks < 2; ks++)
#pragma unroll
            for (int mt = 0; mt < 2; mt++)
#pragma unroll
                for (int n = 0; n < 4; n++) {
                    mma_bf16(cs[mt][n], aqh[mt][ks], bKh[ks][n]);
                    mma_bf16(cs[mt][n], aql[mt][ks], bKh[ks][n]);
                    mma_bf16(cs[mt][n], aqh[mt][ks], bKl[ks][n]);
                }

        uint32_t bVh[2][4][2], bVl[2][4][2];
#pragma unroll
        for (int kp = 0; kp < 2; kp++)
#pragma unroll
            for (int np = 0; np < 2; np++) {
                const uint32_t off = (uint32_t)(kp * 16 + ((li & 1) << 3) + lr) * (KVS * 2)
                                   + (uint32_t)(np * 16 + ((li >> 1) << 3)) * 2;
                ldsm4t(bVh[kp][np*2][0], bVh[kp][np*2][1],
                       bVh[kp][np*2+1][0], bVh[kp][np*2+1][1], vB0 + off);
                ldsm4t(bVl[kp][np*2][0], bVl[kp][np*2][1],
                       bVl[kp][np*2+1][0], bVl[kp][np*2+1][1], vB1 + off);
            }

#pragma unroll
        for (int mt = 0; mt < 2; mt++) {
            const int rbase = warp * 32 + mt * 16;
            const unsigned w0 = Msk[buf][rbase + g];
            const unsigned w8 = Msk[buf][rbase + g + 8];
            float pr[4][4];
#pragma unroll
            for (int n = 0; n < 4; n++) {
                const int c0 = n * 8 + 2 * tg;
                const float m00 = (float)((w0 >> c0) & 1u);
                const float m01 = (float)((w0 >> (c0 + 1)) & 1u);
                const float m10 = (float)((w8 >> c0) & 1u);
                const float m11 = (float)((w8 >> (c0 + 1)) & 1u);
                pr[n][0] = fexp(cs[mt][n][0]) * m00;
                pr[n][1] = fexp(cs[mt][n][1]) * m01;
                pr[n][2] = fexp(cs[mt][n][2]) * m10;
                pr[n][3] = fexp(cs[mt][n][3]) * m11;
                dn[mt][0] += pr[n][0] + pr[n][1];
                dn[mt][1] += pr[n][2] + pr[n][3];
            }
#pragma unroll
            for (int kp = 0; kp < 2; kp++) {
                float e00 = pr[kp*2][0], e01 = pr[kp*2][1], e02 = pr[kp*2][2], e03 = pr[kp*2][3];
                float e10 = pr[kp*2+1][0], e11 = pr[kp*2+1][1], e12 = pr[kp*2+1][2], e13 = pr[kp*2+1][3];
                uint32_t pah[4], pal[4];
                pah[0] = hi_pack(e00, e01); pal[0] = lo_pack(e00, e01);
                pah[1] = hi_pack(e02, e03); pal[1] = lo_pack(e02, e03);
                pah[2] = hi_pack(e10, e11); pal[2] = lo_pack(e10, e11);
                pah[3] = hi_pack(e12, e13); pal[3] = lo_pack(e12, e13);
#pragma unroll
                for (int n = 0; n < 4; n++) {
                    mma_bf16(co[mt][n], pah, bVh[kp][n]);
                    mma_bf16(co[mt][n], pal, bVh[kp][n]);
                    mma_bf16(co[mt][n], pah, bVl[kp][n]);
                }
            }
        }
        __syncthreads();
    }

#pragma unroll
    for (int mt = 0; mt < 2; mt++)
#pragma unroll
        for (int rh = 0; rh < 2; rh++) {
            float d = dn[mt][rh];
            d += __shfl_xor_sync(0xFFFFFFFFu, d, 1);
            d += __shfl_xor_sync(0xFFFFFFFFu, d, 2);
            dn[mt][rh] = (d > 0.f) ? 1.0f / d : 0.f;
        }

#pragma unroll
    for (int mt = 0; mt < 2; mt++) {
        const int r0 = qb + warp * 32 + mt * 16 + g;
#pragma unroll
        for (int n = 0; n < 4; n++) {
            const int col = h * HD + n * 8 + 2 * tg;
            *(float2*)&y[((size_t)(b * LL + r0)) * DD + col] =
                make_float2(co[mt][n][0] * dn[mt][0], co[mt][n][1] * dn[mt][0]);
            *(float2*)&y[((size_t)(b * LL + r0 + 8)) * DD + col] =
                make_float2(co[mt][n][2] * dn[mt][1], co[mt][n][3] * dn[mt][1]);
        }
    }
}

// ---------------- launch ------------------------------------------------------
extern "C" void kernel_launch(void* const* d_in, const int* in_sizes, int n_in,
                              void* d_out, int out_size) {
    const float* obs  = (const float*)d_in[0];
    const float* act  = (const float*)d_in[1];
    const int*   msk  = (const int*)  d_in[2];
    const float* Wq   = (const float*)d_in[3];
    const float* bq   = (const float*)d_in[4];
    const float* Wk   = (const float*)d_in[5];
    const float* bk   = (const float*)d_in[6];
    const float* Wv   = (const float*)d_in[7];
    const float* bv   = (const float*)d_in[8];
    const float* Wobs = (const float*)d_in[9];
    const float* bobs = (const float*)d_in[10];
    const float* gob  = (const float*)d_in[11];
    const float* bob  = (const float*)d_in[12];
    const float* g1   = (const float*)d_in[13];
    const float* b1   = (const float*)d_in[14];
    const float* Wp   = (const float*)d_in[15];
    const float* bp   = (const float*)d_in[16];
    const float* g2   = (const float*)d_in[17];
    const float* b2   = (const float*)d_in[18];

    float *obs2, *yb;
    float2* stats;
    unsigned* mb;
    cudaGetSymbolAddress((void**)&obs2,  g_obs2);
    cudaGetSymbolAddress((void**)&yb,    g_y);
    cudaGetSymbolAddress((void**)&stats, g_stats);
    cudaGetSymbolAddress((void**)&mb,    g_mbits);

    __nv_bfloat16 *qh,*ql,*kh,*kl,*vh,*vl;
    cudaGetSymbolAddress((void**)&qh, g_qh); cudaGetSymbolAddress((void**)&ql, g_ql);
    cudaGetSymbolAddress((void**)&kh, g_kh); cudaGetSymbolAddress((void**)&kl, g_kl);
    cudaGetSymbolAddress((void**)&vh, g_vh); cudaGetSymbolAddress((void**)&vl, g_vl);

    // persistent side stream + events (created once; no device-mem allocation)
    static cudaStream_t s1 = nullptr;
    static cudaEvent_t eFork = nullptr, eMask = nullptr, eObs = nullptr;
    if (!s1) {
        cudaStreamCreateWithFlags(&s1, cudaStreamNonBlocking);
        cudaEventCreateWithFlags(&eFork, cudaEventDisableTiming);
        cudaEventCreateWithFlags(&eMask, cudaEventDisableTiming);
        cudaEventCreateWithFlags(&eObs,  cudaEventDisableTiming);
    }

    // fork side stream off the main (null) stream
    cudaEventRecord(eFork, 0);
    cudaStreamWaitEvent(s1, eFork, 0);

    // ---- side stream: mask pack, then obs-branch fused GEMM ----
    pack_mask_kernel<<<dim3(LL, BB), 128, 0, s1>>>(msk, mb);
    cudaEventRecord(eMask, s1);
    gemm_gelu_ln_kernel<<<MROWS / 32, 256, 0, s1>>>(obs, obs, 256, Wobs, bobs,
                                                    nullptr, nullptr, nullptr,
                                                    gob, bob, obs2, 256);
    cudaEventRecord(eObs, s1);

    // ---- main stream: q / kv projections ----
    gemm2_kernel<<<dim3(4, 128), 256>>>(obs, obs, 256, Wq, Wq, bq, bq,
                                        qh, ql, qh, ql, 256);
    gemm2_kernel<<<dim3(8, 128), 256>>>(obs, act, 256, Wk, Wv, bk, bv,
                                        kh, kl, vh, vl, 512);

    // attention needs q/k/v (same stream) + packed mask (event)
    cudaStreamWaitEvent(0, eMask, 0);
    attn_tc_kernel<<<dim3(LL / 128, HH, BB), 128>>>(qh, ql, kh, kl, vh, vl, mb, yb);

    // join: ln_stats needs y (main) + obs2 (side)
    cudaStreamWaitEvent(0, eObs, 0);
    ln_stats_warp_kernel<<<MROWS / 8, 256>>>(yb, obs2, stats);
    gemm_gelu_ln_kernel<<<MROWS / 32, 256>>>(yb, obs2, 256, Wp, bp,
                                             stats, g1, b1,
                                             g2, b2, (float*)d_out, 512);
}